// round 10
// baseline (speedup 1.0000x reference)
#include <cuda_runtime.h>
#include <cuda_bf16.h>

#define Bn 64
#define Hn 128
#define Cn 1024
#define Qn 128
#define NT 8

typedef unsigned int u32;

// ---------------- scratch ----------------
__device__ float g_S  [Bn * Cn * Qn];
__device__ float g_rowM[Bn * Cn];
__device__ float g_rowZ[Bn * Cn];
__device__ float g_pM [Bn * NT * Qn];
__device__ float g_pZ [Bn * NT * Qn];
__device__ float g_qbp2[Bn * 2 * Hn * Qn];

// ---------------- helpers ----------------
__device__ __forceinline__ u32 smem_u32(const void* p) {
    u32 a;
    asm("{ .reg .u64 t; cvta.to.shared.u64 t, %1; cvt.u32.u64 %0, t; }" : "=r"(a) : "l"(p));
    return a;
}
__device__ __forceinline__ void ldsm4(u32 a, u32* r) {
    asm volatile("ldmatrix.sync.aligned.m8n8.x4.shared.b16 {%0,%1,%2,%3}, [%4];"
        : "=r"(r[0]), "=r"(r[1]), "=r"(r[2]), "=r"(r[3]) : "r"(a));
}
__device__ __forceinline__ void mmabf(float* d, const u32* a, u32 b0, u32 b1) {
    asm volatile("mma.sync.aligned.m16n8k16.row.col.f32.bf16.bf16.f32 "
        "{%0,%1,%2,%3},{%4,%5,%6,%7},{%8,%9},{%0,%1,%2,%3};"
        : "+f"(d[0]), "+f"(d[1]), "+f"(d[2]), "+f"(d[3])
        : "r"(a[0]), "r"(a[1]), "r"(a[2]), "r"(a[3]), "r"(b0), "r"(b1));
}

// 8x8 register transpose across 8 lanes (p = lane & 7); f[j] = M[p][j] -> M[j][p]
__device__ __forceinline__ void xpose8(float* f, int p) {
#pragma unroll
    for (int s = 1; s < 8; s <<= 1) {
        float fn[8];
#pragma unroll
        for (int j = 0; j < 8; j++) {
            float v = __shfl_xor_sync(~0u, f[j ^ s], s);
            fn[j] = ((p ^ j) & s) ? v : f[j];
        }
#pragma unroll
        for (int j = 0; j < 8; j++) f[j] = fn[j];
    }
}

// split 8 fp32 -> bf16 hi/lo, 16B store into 64-col tile (row stride 128B, 8 slots)
__device__ __forceinline__ void split8_64(char* hi, char* lo, int r, int slot,
                                          const float* f)
{
    u32 H[4], L[4];
#pragma unroll
    for (int j = 0; j < 4; j++) {
        float a = f[2 * j], b = f[2 * j + 1];
        __nv_bfloat16 ha = __float2bfloat16(a), hb = __float2bfloat16(b);
        float fa = __bfloat162float(ha), fb = __bfloat162float(hb);
        __nv_bfloat162 hp; hp.x = ha; hp.y = hb;
        H[j] = *(u32*)&hp;
        __nv_bfloat162 lp = __floats2bfloat162_rn(a - fa, b - fb);
        L[j] = *(u32*)&lp;
    }
    u32 off = (u32)r * 128 + (u32)((slot ^ (r & 7)) << 4);
    *(uint4*)(hi + off) = make_uint4(H[0], H[1], H[2], H[3]);
    *(uint4*)(lo + off) = make_uint4(L[0], L[1], L[2], L[3]);
}

// split 8 fp32 -> bf16 hi/lo, 16B store into 128-col tile (row stride 256B, 16 slots)
__device__ __forceinline__ void split8(char* hi, char* lo, int r, int slot,
                                       const float* f)
{
    u32 H[4], L[4];
#pragma unroll
    for (int j = 0; j < 4; j++) {
        float a = f[2 * j], b = f[2 * j + 1];
        __nv_bfloat16 ha = __float2bfloat16(a), hb = __float2bfloat16(b);
        float fa = __bfloat162float(ha), fb = __bfloat162float(hb);
        __nv_bfloat162 hp; hp.x = ha; hp.y = hb;
        H[j] = *(u32*)&hp;
        __nv_bfloat162 lp = __floats2bfloat162_rn(a - fa, b - fb);
        L[j] = *(u32*)&lp;
    }
    u32 off = (u32)r * 256 + (u32)((slot ^ (r & 7)) << 4);
    *(uint4*)(hi + off) = make_uint4(H[0], H[1], H[2], H[3]);
    *(uint4*)(lo + off) = make_uint4(L[0], L[1], L[2], L[3]);
}

// 32x32 warp tile over 128x128xK64 block GEMM (16 warps 4x4). acc += A*B^T
__device__ __forceinline__ void warp_gemm64(u32 ah, u32 al, u32 bh, u32 bl,
                                            int lane, int m0, int n0,
                                            float acc[2][4][4])
{
    int rA = lane & 15, hi16 = lane >> 4;
    int rBl = (lane & 7) + ((lane >> 4) << 3);
    int kh = (lane >> 3) & 1;
    int rowA[2] = {m0 + rA, m0 + 16 + rA};
    int rowB[2] = {n0 + rBl, n0 + 16 + rBl};
#pragma unroll
    for (int ks = 0; ks < 4; ks++) {
        u32 AH[2][4], AL[2][4], BH[2][4], BL[2][4];
#pragma unroll
        for (int f = 0; f < 2; f++) {
            u32 sa = (u32)rowA[f] * 128 + (u32)((((ks << 1) + hi16) ^ (rowA[f] & 7)) << 4);
            ldsm4(ah + sa, AH[f]);
            ldsm4(al + sa, AL[f]);
            u32 sb = (u32)rowB[f] * 128 + (u32)((((ks << 1) + kh) ^ (rowB[f] & 7)) << 4);
            ldsm4(bh + sb, BH[f]);
            ldsm4(bl + sb, BL[f]);
        }
#pragma unroll
        for (int mf = 0; mf < 2; mf++)
#pragma unroll
            for (int nh = 0; nh < 2; nh++)
#pragma unroll
                for (int no = 0; no < 2; no++) {
                    float* d = acc[mf][nh * 2 + no];
                    mmabf(d, AH[mf], BH[nh][2 * no], BH[nh][2 * no + 1]);
                    mmabf(d, AH[mf], BL[nh][2 * no], BL[nh][2 * no + 1]);
                    mmabf(d, AL[mf], BH[nh][2 * no], BH[nh][2 * no + 1]);
                }
    }
}

// ---------------- K1: shfl-transpose fills + S GEMM + fused softmax stats ----
// smem: Ahi 0, Alo 16384, Bhi 32768, Blo 49152,
//       s0s 65536, s1s 66048, qms 66560, cms 67072, red1 67584(2KB), red2 69632(2KB)
#define K1_SMEM 71680

__global__ __launch_bounds__(512, 2) void k1_score(
    const float* __restrict__ c_g, const float* __restrict__ q_g,
    const float* __restrict__ cmask, const float* __restrict__ qmask,
    const float* __restrict__ wc, const float* __restrict__ wq,
    const float* __restrict__ wcq, const float* __restrict__ bias)
{
    extern __shared__ __align__(256) char smem[];
    u32 sb = smem_u32(smem);
    float* s0s  = (float*)(smem + 65536);
    float* s1s  = (float*)(smem + 66048);
    float* qms  = (float*)(smem + 66560);
    float* cms  = (float*)(smem + 67072);
    float* red1 = (float*)(smem + 67584);   // [4][128]
    float* red2 = (float*)(smem + 69632);   // [4][128]
    int tid = threadIdx.x, lane = tid & 31, wid = tid >> 5;
    int b = blockIdx.y, ct = blockIdx.x, c0 = ct * 128;
    float biasv = bias[0];

    if (tid < 128) qms[tid] = qmask[b * Qn + tid];
    else if (tid < 256) cms[tid - 128] = cmask[b * Cn + c0 + tid - 128];

    int p = lane & 7;
    int G = tid >> 3;           // 0..63
    int g4 = G & 3;             // hb sub-block within pass
    int cbB = G >> 2;           // 0..15 (column block)
    int cb = cbB * 8;

    float acc[2][4][4];
#pragma unroll
    for (int i = 0; i < 2; i++)
#pragma unroll
        for (int j = 0; j < 4; j++)
#pragma unroll
            for (int k = 0; k < 4; k++) acc[i][j][k] = 0.f;

    int m0 = (wid >> 2) * 32, n0 = (wid & 3) * 32;
    float sp = 0.f, sq = 0.f;

#pragma unroll
    for (int kc = 0; kc < 2; kc++) {
        int h0g = kc * 64;
        __syncthreads();
#pragma unroll
        for (int pass = 0; pass < 2; pass++) {
            int hb = (g4 + pass * 4) * 8;
            // c side -> A tile [cc][h-minor 64]
            {
                const float* pc = &c_g[((size_t)b * Hn + h0g + hb + p) * Cn + c0 + cb];
                float4 v0 = *(const float4*)pc, v1 = *(const float4*)(pc + 4);
                float f[8] = {v0.x, v0.y, v0.z, v0.w, v1.x, v1.y, v1.z, v1.w};
                xpose8(f, p);
#pragma unroll
                for (int j = 0; j < 8; j++) sp += f[j] * __ldg(&wc[h0g + hb + j]);
                split8_64(smem, smem + 16384, cb + p, hb >> 3, f);
            }
            // q side -> B tile [q][h-minor 64], scaled by wcq
            {
                const float* pq = &q_g[((size_t)b * Hn + h0g + hb + p) * Qn + cb];
                float4 v0 = *(const float4*)pq, v1 = *(const float4*)(pq + 4);
                float f[8] = {v0.x, v0.y, v0.z, v0.w, v1.x, v1.y, v1.z, v1.w};
                xpose8(f, p);
#pragma unroll
                for (int j = 0; j < 8; j++) {
                    sq += f[j] * __ldg(&wq[h0g + hb + j]);
                    f[j] *= __ldg(&wcq[h0g + hb + j]);
                }
                split8_64(smem + 32768, smem + 49152, cb + p, hb >> 3, f);
            }
        }
        __syncthreads();
        warp_gemm64(sb, sb + 16384, sb + 32768, sb + 49152, lane, m0, n0, acc);
    }

    // s0/s1 reduction (4 partials per index)
    red1[g4 * 128 + cb + p] = sp;
    red2[g4 * 128 + cb + p] = sq;
    __syncthreads();
    if (tid < 128) {
        s0s[tid] = red1[tid] + red1[128 + tid] + red1[256 + tid] + red1[384 + tid] + biasv;
        s1s[tid] = red2[tid] + red2[128 + tid] + red2[256 + tid] + red2[384 + tid];
    }
    __syncthreads();

    int lr = lane >> 2, lc2 = (lane & 3) * 2;

    // finalize S: acc += s0[row] + s1[col]
#pragma unroll
    for (int mf = 0; mf < 2; mf++) {
        int r0 = m0 + mf * 16 + lr, r1 = r0 + 8;
        float s0a = s0s[r0], s0b = s0s[r1];
#pragma unroll
        for (int nf = 0; nf < 4; nf++) {
            int col = n0 + nf * 8 + lc2;
            float s1a = s1s[col], s1b = s1s[col + 1];
            acc[mf][nf][0] += s0a + s1a;
            acc[mf][nf][1] += s0a + s1b;
            acc[mf][nf][2] += s0b + s1a;
            acc[mf][nf][3] += s0b + s1b;
        }
    }

    // write S [c][q]
#pragma unroll
    for (int mf = 0; mf < 2; mf++) {
        int r0 = m0 + mf * 16 + lr, r1 = r0 + 8;
#pragma unroll
        for (int nf = 0; nf < 4; nf++) {
            int col = n0 + nf * 8 + lc2;
            *(float2*)&g_S[((size_t)b * Cn + c0 + r0) * Qn + col] =
                make_float2(acc[mf][nf][0], acc[mf][nf][1]);
            *(float2*)&g_S[((size_t)b * Cn + c0 + r1) * Qn + col] =
                make_float2(acc[mf][nf][2], acc[mf][nf][3]);
        }
    }

    // masks
    bool qm0[4], qm1[4];
#pragma unroll
    for (int nf = 0; nf < 4; nf++) {
        qm0[nf] = qms[n0 + nf * 8 + lc2] > 0.f;
        qm1[nf] = qms[n0 + nf * 8 + lc2 + 1] > 0.f;
    }
    bool cmv[2][2];
#pragma unroll
    for (int mf = 0; mf < 2; mf++) {
        cmv[mf][0] = cms[m0 + mf * 16 + lr] > 0.f;
        cmv[mf][1] = cms[m0 + mf * 16 + 8 + lr] > 0.f;
    }

    // ---- row stats ----
    float rmx[2][2];
#pragma unroll
    for (int mf = 0; mf < 2; mf++) { rmx[mf][0] = -1e30f; rmx[mf][1] = -1e30f; }
#pragma unroll
    for (int mf = 0; mf < 2; mf++)
#pragma unroll
        for (int nf = 0; nf < 4; nf++) {
            if (qm0[nf]) {
                rmx[mf][0] = fmaxf(rmx[mf][0], acc[mf][nf][0]);
                rmx[mf][1] = fmaxf(rmx[mf][1], acc[mf][nf][2]);
            }
            if (qm1[nf]) {
                rmx[mf][0] = fmaxf(rmx[mf][0], acc[mf][nf][1]);
                rmx[mf][1] = fmaxf(rmx[mf][1], acc[mf][nf][3]);
            }
        }
#pragma unroll
    for (int mf = 0; mf < 2; mf++)
#pragma unroll
        for (int h = 0; h < 2; h++) {
            rmx[mf][h] = fmaxf(rmx[mf][h], __shfl_xor_sync(~0u, rmx[mf][h], 1));
            rmx[mf][h] = fmaxf(rmx[mf][h], __shfl_xor_sync(~0u, rmx[mf][h], 2));
        }
    if ((lane & 3) == 0)
#pragma unroll
        for (int mf = 0; mf < 2; mf++)
#pragma unroll
            for (int h = 0; h < 2; h++)
                red1[(wid & 3) * 128 + m0 + mf * 16 + h * 8 + lr] = rmx[mf][h];
    __syncthreads();

    float rowMv[2][2];
#pragma unroll
    for (int mf = 0; mf < 2; mf++)
#pragma unroll
        for (int h = 0; h < 2; h++) {
            int r = m0 + mf * 16 + h * 8 + lr;
            float m = red1[r];
#pragma unroll
            for (int g = 1; g < 4; g++) m = fmaxf(m, red1[g * 128 + r]);
            rowMv[mf][h] = m;
        }
    float rzz[2][2] = {{0.f, 0.f}, {0.f, 0.f}};
#pragma unroll
    for (int mf = 0; mf < 2; mf++)
#pragma unroll
        for (int nf = 0; nf < 4; nf++) {
            if (qm0[nf]) {
                rzz[mf][0] += __expf(acc[mf][nf][0] - rowMv[mf][0]);
                rzz[mf][1] += __expf(acc[mf][nf][2] - rowMv[mf][1]);
            }
            if (qm1[nf]) {
                rzz[mf][0] += __expf(acc[mf][nf][1] - rowMv[mf][0]);
                rzz[mf][1] += __expf(acc[mf][nf][3] - rowMv[mf][1]);
            }
        }
#pragma unroll
    for (int mf = 0; mf < 2; mf++)
#pragma unroll
        for (int h = 0; h < 2; h++) {
            rzz[mf][h] += __shfl_xor_sync(~0u, rzz[mf][h], 1);
            rzz[mf][h] += __shfl_xor_sync(~0u, rzz[mf][h], 2);
        }
    if ((lane & 3) == 0)
#pragma unroll
        for (int mf = 0; mf < 2; mf++)
#pragma unroll
            for (int h = 0; h < 2; h++)
                red2[(wid & 3) * 128 + m0 + mf * 16 + h * 8 + lr] = rzz[mf][h];
    __syncthreads();

    if ((wid & 3) == 0 && (lane & 3) == 0) {
#pragma unroll
        for (int mf = 0; mf < 2; mf++)
#pragma unroll
            for (int h = 0; h < 2; h++) {
                int r = m0 + mf * 16 + h * 8 + lr;
                float z = red2[r] + red2[128 + r] + red2[256 + r] + red2[384 + r];
                g_rowM[b * Cn + c0 + r] = rowMv[mf][h];
                g_rowZ[b * Cn + c0 + r] = z;
            }
    }
    __syncthreads();

    // ---- column partial stats ----
    float cmx[4][2];
#pragma unroll
    for (int nf = 0; nf < 4; nf++) { cmx[nf][0] = -1e30f; cmx[nf][1] = -1e30f; }
#pragma unroll
    for (int mf = 0; mf < 2; mf++)
#pragma unroll
        for (int nf = 0; nf < 4; nf++) {
            if (cmv[mf][0]) {
                cmx[nf][0] = fmaxf(cmx[nf][0], acc[mf][nf][0]);
                cmx[nf][1] = fmaxf(cmx[nf][1], acc[mf][nf][1]);
            }
            if (cmv[mf][1]) {
                cmx[nf][0] = fmaxf(cmx[nf][0], acc[mf][nf][2]);
                cmx[nf][1] = fmaxf(cmx[nf][1], acc[mf][nf][3]);
            }
        }
#pragma unroll
    for (int nf = 0; nf < 4; nf++)
#pragma unroll
        for (int v = 0; v < 2; v++) {
            cmx[nf][v] = fmaxf(cmx[nf][v], __shfl_xor_sync(~0u, cmx[nf][v], 4));
            cmx[nf][v] = fmaxf(cmx[nf][v], __shfl_xor_sync(~0u, cmx[nf][v], 8));
            cmx[nf][v] = fmaxf(cmx[nf][v], __shfl_xor_sync(~0u, cmx[nf][v], 16));
        }
    if (lr == 0)
#pragma unroll
        for (int nf = 0; nf < 4; nf++) {
            red1[(wid >> 2) * 128 + n0 + nf * 8 + lc2]     = cmx[nf][0];
            red1[(wid >> 2) * 128 + n0 + nf * 8 + lc2 + 1] = cmx[nf][1];
        }
    __syncthreads();

    float pMv[4][2];
#pragma unroll
    for (int nf = 0; nf < 4; nf++)
#pragma unroll
        for (int v = 0; v < 2; v++) {
            int col = n0 + nf * 8 + lc2 + v;
            float m = red1[col];
#pragma unroll
            for (int g = 1; g < 4; g++) m = fmaxf(m, red1[g * 128 + col]);
            pMv[nf][v] = m;
        }
    float czz[4][2] = {{0,0},{0,0},{0,0},{0,0}};
#pragma unroll
    for (int nf = 0; nf < 4; nf++) {
        if (cmv[0][0]) { czz[nf][0] += __expf(acc[0][nf][0] - pMv[nf][0]); czz[nf][1] += __expf(acc[0][nf][1] - pMv[nf][1]); }
        if (cmv[0][1]) { czz[nf][0] += __expf(acc[0][nf][2] - pMv[nf][0]); czz[nf][1] += __expf(acc[0][nf][3] - pMv[nf][1]); }
        if (cmv[1][0]) { czz[nf][0] += __expf(acc[1][nf][0] - pMv[nf][0]); czz[nf][1] += __expf(acc[1][nf][1] - pMv[nf][1]); }
        if (cmv[1][1]) { czz[nf][0] += __expf(acc[1][nf][2] - pMv[nf][0]); czz[nf][1] += __expf(acc[1][nf][3] - pMv[nf][1]); }
    }
#pragma unroll
    for (int nf = 0; nf < 4; nf++)
#pragma unroll
        for (int v = 0; v < 2; v++) {
            czz[nf][v] += __shfl_xor_sync(~0u, czz[nf][v], 4);
            czz[nf][v] += __shfl_xor_sync(~0u, czz[nf][v], 8);
            czz[nf][v] += __shfl_xor_sync(~0u, czz[nf][v], 16);
        }
    if (lr == 0)
#pragma unroll
        for (int nf = 0; nf < 4; nf++) {
            red2[(wid >> 2) * 128 + n0 + nf * 8 + lc2]     = czz[nf][0];
            red2[(wid >> 2) * 128 + n0 + nf * 8 + lc2 + 1] = czz[nf][1];
        }
    __syncthreads();

    if ((wid >> 2) == 0 && lr == 0) {
#pragma unroll
        for (int nf = 0; nf < 4; nf++)
#pragma unroll
            for (int v = 0; v < 2; v++) {
                int col = n0 + nf * 8 + lc2 + v;
                float z = red2[col] + red2[128 + col] + red2[256 + col] + red2[384 + col];
                g_pM[(b * NT + ct) * Qn + col] = pMv[nf][v];
                g_pZ[(b * NT + ct) * Qn + col] = z;
            }
    }
}

// ---------------- K3: qb^T = c · E2^T, K-split chunks of 64 ----------------
// smem: Ahi 0, Alo 16384, Ehi 32768, Elo 49152, colMs 65536
#define K3_SMEM 66048

__global__ __launch_bounds__(512, 2) void k3_qb(
    const float* __restrict__ c_g, const float* __restrict__ cmask)
{
    extern __shared__ __align__(256) char smem[];
    u32 sb = smem_u32(smem);
    float* colMs = (float*)(smem + 65536);
    int tid = threadIdx.x, lane = tid & 31, wid = tid >> 5;
    int b = blockIdx.y, half = blockIdx.x;

    if (tid < 128) {
        float m = -3.4e38f;
#pragma unroll
        for (int t = 0; t < NT; t++) m = fmaxf(m, g_pM[(b * NT + t) * Qn + tid]);
        colMs[tid] = m;
    }

    float acc[2][4][4];
#pragma unroll
    for (int i = 0; i < 2; i++)
#pragma unroll
        for (int j = 0; j < 4; j++)
#pragma unroll
            for (int k = 0; k < 4; k++) acc[i][j][k] = 0.f;

    int m0 = (wid >> 2) * 32, n0 = (wid & 3) * 32;
    int p = lane & 7;
    int G = tid >> 3;
    int g4 = G & 3;
    int qbB = G >> 2;       // 0..15 over q
    int qcb = qbB * 8;

    for (int it = 0; it < 8; it++) {
        int c0 = (half * 4 + (it >> 1)) * 128 + (it & 1) * 64;
        __syncthreads();
        // A fill: c rows h 0..127, 64 c-cols (natural K-minor)
        for (int i = tid; i < 1024; i += 512) {
            int r = i >> 3, sx = i & 7;
            const float* pa = &c_g[((size_t)b * Hn + r) * Cn + c0 + sx * 8];
            float4 v0 = *(const float4*)pa, v1 = *(const float4*)(pa + 4);
            float f[8] = {v0.x, v0.y, v0.z, v0.w, v1.x, v1.y, v1.z, v1.w};
            split8_64(smem, smem + 16384, r, sx, f);
        }
        // E fill: read S rows (c) x q-cols, exp+mask, shfl-transpose -> E[q][c-local]
#pragma unroll
        for (int pass = 0; pass < 2; pass++) {
            int rb = (g4 + pass * 4) * 8;     // c-local block 0..56
            int row = c0 + rb + p;
            const float* ps = &g_S[((size_t)b * Cn + row) * Qn + qcb];
            float4 s0 = *(const float4*)ps, s1 = *(const float4*)(ps + 4);
            float f[8] = {s0.x, s0.y, s0.z, s0.w, s1.x, s1.y, s1.z, s1.w};
            float cm = __ldg(&cmask[b * Cn + row]);
#pragma unroll
            for (int j = 0; j < 8; j++)
                f[j] = (cm > 0.f) ? __expf(f[j] - colMs[qcb + j]) : 0.f;
            xpose8(f, p);
            split8_64(smem + 32768, smem + 49152, qcb + p, rb >> 3, f);
        }
        __syncthreads();
        warp_gemm64(sb, sb + 16384, sb + 32768, sb + 49152, lane, m0, n0, acc);
    }

    int lr = lane >> 2, lc2 = (lane & 3) * 2;
#pragma unroll
    for (int mf = 0; mf < 2; mf++) {
        int h0 = m0 + mf * 16 + lr, h1 = h0 + 8;
#pragma unroll
        for (int nf = 0; nf < 4; nf++) {
            int col = n0 + nf * 8 + lc2;
            *(float2*)&g_qbp2[((size_t)(b * 2 + half) * Hn + h0) * Qn + col] =
                make_float2(acc[mf][nf][0], acc[mf][nf][1]);
            *(float2*)&g_qbp2[((size_t)(b * 2 + half) * Hn + h1) * Qn + col] =
                make_float2(acc[mf][nf][2], acc[mf][nf][3]);
        }
    }
}

// ---------------- K4: dual GEMM (a, bb) in one pass; assemble output --------
// smem: Ehi 0, Elo 32768, Qhi 65536, Qlo 98304, Phi 131072, Plo 163840,
//       rms 196608, qms 197120, rzs 197632, rcz 198144
#define K4_SMEM 198656

__global__ __launch_bounds__(512) void k4_out(
    const float* __restrict__ c_g, const float* __restrict__ q_g,
    const float* __restrict__ qmask, float* __restrict__ out)
{
    extern __shared__ __align__(256) char smem[];
    u32 sb = smem_u32(smem);
    float* rms = (float*)(smem + 196608);
    float* qms = (float*)(smem + 197120);
    float* rzs = (float*)(smem + 197632);
    float* rcz = (float*)(smem + 198144);
    int tid = threadIdx.x, lane = tid & 31, wid = tid >> 5;
    int b = blockIdx.y, ct = blockIdx.x, c0 = ct * 128;

    if (tid < 128) rms[tid] = g_rowM[b * Cn + c0 + tid];
    else if (tid < 256) qms[tid - 128] = qmask[b * Qn + tid - 128];
    else if (tid < 384) {
        float z = g_rowZ[b * Cn + c0 + tid - 256];
        rzs[tid - 256] = (z > 0.f) ? 1.f / z : 0.f;
    } else {
        int qq = tid - 384;
        float m = -3.4e38f;
#pragma unroll
        for (int t = 0; t < NT; t++) m = fmaxf(m, g_pM[(b * NT + t) * Qn + qq]);
        float z = 0.f;
#pragma unroll
        for (int t = 0; t < NT; t++)
            z += g_pZ[(b * NT + t) * Qn + qq] * __expf(g_pM[(b * NT + t) * Qn + qq] - m);
        rcz[qq] = (z > 0.f) ? 1.f / z : 0.f;
    }
    __syncthreads();

    for (int i = tid; i < 2048; i += 512) {
        int r = i >> 4, sx = i & 15;
        const float* ps = &g_S[((size_t)b * Cn + c0 + r) * Qn + sx * 8];
        float4 s0 = *(const float4*)ps, s1 = *(const float4*)(ps + 4);
        float fe[8] = {s0.x, s0.y, s0.z, s0.w, s1.x, s1.y, s1.z, s1.w};
        float rm = rms[r];
#pragma unroll
        for (int j = 0; j < 8; j++)
            fe[j] = (qms[sx * 8 + j] > 0.f) ? __expf(fe[j] - rm) : 0.f;
        split8(smem, smem + 32768, r, sx, fe);
        const float* pq = &q_g[((size_t)b * Hn + r) * Qn + sx * 8];
        float4 q0 = *(const float4*)pq, q1 = *(const float4*)(pq + 4);
        float fq[8] = {q0.x, q0.y, q0.z, q0.w, q1.x, q1.y, q1.z, q1.w};
        split8(smem + 65536, smem + 98304, r, sx, fq);
        const float* p0 = &g_qbp2[((size_t)(b * 2) * Hn + r) * Qn + sx * 8];
        const float* p1 = p0 + (size_t)Hn * Qn;
        float4 a0 = *(const float4*)p0, a1 = *(const float4*)(p0 + 4);
        float4 b0 = *(const float4*)p1, b1 = *(const float4*)(p1 + 4);
        float fp[8] = {a0.x + b0.x, a0.y + b0.y, a0.z + b0.z, a0.w + b0.w,
                       a1.x + b1.x, a1.y + b1.y, a1.z + b1.z, a1.w + b1.w};
#pragma unroll
        for (int j = 0; j < 8; j++) fp[j] *= rcz[sx * 8 + j];
        split8(smem + 131072, smem + 163840, r, sx, fp);
    }
    __syncthreads();

    int m0 = (wid >> 2) * 32, n0 = (wid & 3) * 32;
    int lr = lane >> 2, lc = (lane & 3) * 2;

    float accA[2][4][4], accB[2][4][4];
#pragma unroll
    for (int i = 0; i < 2; i++)
#pragma unroll
        for (int j = 0; j < 4; j++)
#pragma unroll
            for (int k = 0; k < 4; k++) { accA[i][j][k] = 0.f; accB[i][j][k] = 0.f; }

    {
        u32 eh = sb, el = sb + 32768, qh = sb + 65536, ql = sb + 98304;
        u32 ph = sb + 131072, pl = sb + 163840;
        int rA = lane & 15, hi16 = lane >> 4;
        int rBl = (lane & 7) + ((lane >> 4) << 3);
        int kh = (lane >> 3) & 1;
        int rowA[2] = {m0 + rA, m0 + 16 + rA};
        int rowB[2] = {n0 + rBl, n0 + 16 + rBl};
#pragma unroll
        for (int ks = 0; ks < 8; ks++) {
            u32 AH[2][4], AL[2][4];
#pragma unroll
            for (int f = 0; f < 2; f++) {
                u32 sa = (u32)rowA[f] * 256 + (u32)((((ks << 1) + hi16) ^ (rowA[f] & 7)) << 4);
                ldsm4(eh + sa, AH[f]);
                ldsm4(el + sa, AL[f]);
            }
#pragma unroll
            for (int nh = 0; nh < 2; nh++) {
                u32 QH[4], QL[4], PH[4], PL[4];
                u32 sbo = (u32)rowB[nh] * 256 + (u32)((((ks << 1) + kh) ^ (rowB[nh] & 7)) << 4);
                ldsm4(qh + sbo, QH);
                ldsm4(ql + sbo, QL);
                ldsm4(ph + sbo, PH);
                ldsm4(pl + sbo, PL);
#pragma unroll
                for (int mf = 0; mf < 2; mf++)
#pragma unroll
                    for (int no = 0; no < 2; no++) {
                        float* dA = accA[mf][nh * 2 + no];
                        mmabf(dA, AH[mf], QH[2 * no], QH[2 * no + 1]);
                        mmabf(dA, AH[mf], QL[2 * no], QL[2 * no + 1]);
                        mmabf(dA, AL[mf], QH[2 * no], QH[2 * no + 1]);
                        float* dB = accB[mf][nh * 2 + no];
                        mmabf(dB, AH[mf], PH[2 * no], PH[2 * no + 1]);
                        mmabf(dB, AH[mf], PL[2 * no], PL[2 * no + 1]);
                        mmabf(dB, AL[mf], PH[2 * no], PH[2 * no + 1]);
                    }
            }
        }
    }
    __syncthreads();

    float* StA = (float*)(smem + 65536);
    float* StB = (float*)smem;
#pragma unroll
    for (int mf = 0; mf < 2; mf++) {
        int cl0 = m0 + mf * 16 + lr, cl1 = cl0 + 8;
        float rz0 = rzs[cl0], rz1 = rzs[cl1];
#pragma unroll
        for (int nf = 0; nf < 4; nf++) {
            int h = n0 + nf * 8 + lc;
            StA[(h << 7) + ((cl0 ^ h) & 127)]             = accA[mf][nf][0] * rz0;
            StA[((h + 1) << 7) + ((cl0 ^ (h + 1)) & 127)] = accA[mf][nf][1] * rz0;
            StA[(h << 7) + ((cl1 ^ h) & 127)]             = accA[mf][nf][2] * rz1;
            StA[((h + 1) << 7) + ((cl1 ^ (h + 1)) & 127)] = accA[mf][nf][3] * rz1;
            StB[(h << 7) + ((cl0 ^ h) & 127)]             = accB[mf][nf][0] * rz0;
            StB[((h + 1) << 7) + ((cl0 ^ (h + 1)) & 127)] = accB[mf][nf][1] * rz0;
            StB[(h << 7) + ((cl1 ^ h) & 127)]             = accB[mf][nf][2] * rz1;
            StB[((h + 1) << 7) + ((cl1 ^ (h + 1)) & 127)] = accB[mf][nf][3] * rz1;
        }
    }
    __syncthreads();

    const size_t HC = (size_t)Hn * Cn;
    for (int i = tid; i < 16384; i += 512) {
        int h = i >> 7, cc = i & 127;
        float a  = StA[(h << 7) + ((cc ^ h) & 127)];
        float bb = StB[(h << 7) + ((cc ^ h) & 127)];
        float cv = c_g[((size_t)b * Hn + h) * Cn + c0 + cc];
        size_t o = (size_t)b * 4 * HC + (size_t)h * Cn + c0 + cc;
        out[o]          = cv;
        out[o + HC]     = a;
        out[o + 2 * HC] = cv * a;
        out[o + 3 * HC] = cv * bb;
    }
}

// ---------------- launch ----------------
extern "C" void kernel_launch(void* const* d_in, const int* in_sizes, int n_in,
                              void* d_out, int out_size)
{
    const float* c     = (const float*)d_in[0];
    const float* q     = (const float*)d_in[1];
    const float* cmask = (const float*)d_in[2];
    const float* qmask = (const float*)d_in[3];
    const float* wc    = (const float*)d_in[4];
    const float* wq    = (const float*)d_in[5];
    const float* wcq   = (const float*)d_in[6];
    const float* bias  = (const float*)d_in[7];
    float* out = (float*)d_out;

    cudaFuncSetAttribute(k1_score, cudaFuncAttributeMaxDynamicSharedMemorySize, K1_SMEM);
    cudaFuncSetAttribute(k3_qb,    cudaFuncAttributeMaxDynamicSharedMemorySize, K3_SMEM);
    cudaFuncSetAttribute(k4_out,   cudaFuncAttributeMaxDynamicSharedMemorySize, K4_SMEM);

    k1_score<<<dim3(NT, Bn), 512, K1_SMEM>>>(c, q, cmask, qmask, wc, wq, wcq, bias);
    k3_qb<<<dim3(2, Bn), 512, K3_SMEM>>>(c, cmask);
    k4_out<<<dim3(NT, Bn), 512, K4_SMEM>>>(c, q, qmask, out);
}

// round 11
// speedup vs baseline: 1.1871x; 1.1871x over previous
#include <cuda_runtime.h>
#include <cuda_bf16.h>

#define Bn 64
#define Hn 128
#define Cn 1024
#define Qn 128
#define NT 8

typedef unsigned int u32;

// ---------------- scratch ----------------
__device__ float g_S  [Bn * Cn * Qn];
__device__ float g_rowM[Bn * Cn];
__device__ float g_rowZ[Bn * Cn];
__device__ float g_pM [Bn * NT * Qn];
__device__ float g_pZ [Bn * NT * Qn];
__device__ float g_qbp4[Bn * 4 * Hn * Qn];

// ---------------- helpers ----------------
__device__ __forceinline__ u32 smem_u32(const void* p) {
    u32 a;
    asm("{ .reg .u64 t; cvta.to.shared.u64 t, %1; cvt.u32.u64 %0, t; }" : "=r"(a) : "l"(p));
    return a;
}
__device__ __forceinline__ void ldsm4(u32 a, u32* r) {
    asm volatile("ldmatrix.sync.aligned.m8n8.x4.shared.b16 {%0,%1,%2,%3}, [%4];"
        : "=r"(r[0]), "=r"(r[1]), "=r"(r[2]), "=r"(r[3]) : "r"(a));
}
__device__ __forceinline__ void mmabf(float* d, const u32* a, u32 b0, u32 b1) {
    asm volatile("mma.sync.aligned.m16n8k16.row.col.f32.bf16.bf16.f32 "
        "{%0,%1,%2,%3},{%4,%5,%6,%7},{%8,%9},{%0,%1,%2,%3};"
        : "+f"(d[0]), "+f"(d[1]), "+f"(d[2]), "+f"(d[3])
        : "r"(a[0]), "r"(a[1]), "r"(a[2]), "r"(a[3]), "r"(b0), "r"(b1));
}

// split 8 fp32 -> bf16 hi/lo, 16B store into 64-col tile (row stride 128B, 8 slots)
__device__ __forceinline__ void split8_64(char* hi, char* lo, int r, int slot,
                                          const float* f)
{
    u32 H[4], L[4];
#pragma unroll
    for (int j = 0; j < 4; j++) {
        float a = f[2 * j], b = f[2 * j + 1];
        __nv_bfloat16 ha = __float2bfloat16(a), hb = __float2bfloat16(b);
        float fa = __bfloat162float(ha), fb = __bfloat162float(hb);
        __nv_bfloat162 hp; hp.x = ha; hp.y = hb;
        H[j] = *(u32*)&hp;
        __nv_bfloat162 lp = __floats2bfloat162_rn(a - fa, b - fb);
        L[j] = *(u32*)&lp;
    }
    u32 off = (u32)r * 128 + (u32)((slot ^ (r & 7)) << 4);
    *(uint4*)(hi + off) = make_uint4(H[0], H[1], H[2], H[3]);
    *(uint4*)(lo + off) = make_uint4(L[0], L[1], L[2], L[3]);
}

// split 8 fp32 -> bf16 hi/lo, 16B store into 128-col tile (row stride 256B, 16 slots)
__device__ __forceinline__ void split8(char* hi, char* lo, int r, int slot,
                                       const float* f)
{
    u32 H[4], L[4];
#pragma unroll
    for (int j = 0; j < 4; j++) {
        float a = f[2 * j], b = f[2 * j + 1];
        __nv_bfloat16 ha = __float2bfloat16(a), hb = __float2bfloat16(b);
        float fa = __bfloat162float(ha), fb = __bfloat162float(hb);
        __nv_bfloat162 hp; hp.x = ha; hp.y = hb;
        H[j] = *(u32*)&hp;
        __nv_bfloat162 lp = __floats2bfloat162_rn(a - fa, b - fb);
        L[j] = *(u32*)&lp;
    }
    u32 off = (u32)r * 256 + (u32)((slot ^ (r & 7)) << 4);
    *(uint4*)(hi + off) = make_uint4(H[0], H[1], H[2], H[3]);
    *(uint4*)(lo + off) = make_uint4(L[0], L[1], L[2], L[3]);
}

// 32x32 warp tile over 128x128xK64 block GEMM (16 warps 4x4). acc += A*B^T
__device__ __forceinline__ void warp_gemm64(u32 ah, u32 al, u32 bh, u32 bl,
                                            int lane, int m0, int n0,
                                            float acc[2][4][4])
{
    int rA = lane & 15, hi16 = lane >> 4;
    int rBl = (lane & 7) + ((lane >> 4) << 3);
    int kh = (lane >> 3) & 1;
    int rowA[2] = {m0 + rA, m0 + 16 + rA};
    int rowB[2] = {n0 + rBl, n0 + 16 + rBl};
#pragma unroll
    for (int ks = 0; ks < 4; ks++) {
        u32 AH[2][4], AL[2][4], BH[2][4], BL[2][4];
#pragma unroll
        for (int f = 0; f < 2; f++) {
            u32 sa = (u32)rowA[f] * 128 + (u32)((((ks << 1) + hi16) ^ (rowA[f] & 7)) << 4);
            ldsm4(ah + sa, AH[f]);
            ldsm4(al + sa, AL[f]);
            u32 sb = (u32)rowB[f] * 128 + (u32)((((ks << 1) + kh) ^ (rowB[f] & 7)) << 4);
            ldsm4(bh + sb, BH[f]);
            ldsm4(bl + sb, BL[f]);
        }
#pragma unroll
        for (int mf = 0; mf < 2; mf++)
#pragma unroll
            for (int nh = 0; nh < 2; nh++)
#pragma unroll
                for (int no = 0; no < 2; no++) {
                    float* d = acc[mf][nh * 2 + no];
                    mmabf(d, AH[mf], BH[nh][2 * no], BH[nh][2 * no + 1]);
                    mmabf(d, AH[mf], BL[nh][2 * no], BL[nh][2 * no + 1]);
                    mmabf(d, AL[mf], BH[nh][2 * no], BH[nh][2 * no + 1]);
                }
    }
}

// f32 staging swizzle, 64-col: (row, col<64)
__device__ __forceinline__ int stg64(int row, int col) {
    return row * 64 + ((col ^ row) & 63);
}

// ---------------- K1: K-split (2x64) S GEMM + fused softmax stats ----------
// smem: Ahi 0, Alo 16384, Bhi 32768, Blo 49152, Stg 65536(32KB),
//       s0s 98304, s1s 98816, qms 99328, cms 99840, red1 100352(2KB), red2 102400(2KB)
#define K1_SMEM 104448

__global__ __launch_bounds__(512, 2) void k1_score(
    const float* __restrict__ c_g, const float* __restrict__ q_g,
    const float* __restrict__ cmask, const float* __restrict__ qmask,
    const float* __restrict__ wc, const float* __restrict__ wq,
    const float* __restrict__ wcq, const float* __restrict__ bias)
{
    extern __shared__ __align__(256) char smem[];
    u32 sb = smem_u32(smem);
    float* Stg  = (float*)(smem + 65536);
    float* s0s  = (float*)(smem + 98304);
    float* s1s  = (float*)(smem + 98816);
    float* qms  = (float*)(smem + 99328);
    float* cms  = (float*)(smem + 99840);
    float* red1 = (float*)(smem + 100352);   // [4][128]
    float* red2 = (float*)(smem + 102400);   // [4][128]
    int tid = threadIdx.x, lane = tid & 31, wid = tid >> 5;
    int b = blockIdx.y, ct = blockIdx.x, c0 = ct * 128;
    float biasv = bias[0];

    if (tid < 128) qms[tid] = qmask[b * Qn + tid];
    else if (tid < 256) cms[tid - 128] = cmask[b * Cn + c0 + tid - 128];

    float acc[2][4][4];
#pragma unroll
    for (int i = 0; i < 2; i++)
#pragma unroll
        for (int j = 0; j < 4; j++)
#pragma unroll
            for (int k = 0; k < 4; k++) acc[i][j][k] = 0.f;

    int m0 = (wid >> 2) * 32, n0 = (wid & 3) * 32;

#pragma unroll
    for (int kc = 0; kc < 2; kc++) {
        int h0g = kc * 64;
        __syncthreads();
        // stage c^T chunk: Stg[cc][hl]
        for (int i = tid; i < 1024; i += 512) {
            int hl = i >> 4, sx = i & 15;
            const float* p = &c_g[((size_t)b * Hn + h0g + hl) * Cn + c0 + sx * 8];
            float4 v0 = *(const float4*)p, v1 = *(const float4*)(p + 4);
            float f[8] = {v0.x, v0.y, v0.z, v0.w, v1.x, v1.y, v1.z, v1.w};
#pragma unroll
            for (int j = 0; j < 8; j++) Stg[stg64(sx * 8 + j, hl)] = f[j];
        }
        __syncthreads();
        // split A + s0 partial
        for (int i = tid; i < 1024; i += 512) {
            int cc = i >> 3, hs = i & 7, h0 = hs * 8;
            float f[8];
#pragma unroll
            for (int j = 0; j < 8; j++) f[j] = Stg[stg64(cc, h0 + j)];
            split8_64(smem, smem + 16384, cc, hs, f);
            float p = 0.f;
#pragma unroll
            for (int j = 0; j < 8; j++) p += f[j] * wc[h0g + h0 + j];
            p += __shfl_xor_sync(~0u, p, 1);
            p += __shfl_xor_sync(~0u, p, 2);
            p += __shfl_xor_sync(~0u, p, 4);
            if ((lane & 7) == 0) {
                if (kc == 0) s0s[cc] = p + biasv; else s0s[cc] += p;
            }
        }
        __syncthreads();
        // stage q^T chunk
        for (int i = tid; i < 1024; i += 512) {
            int hl = i >> 4, sx = i & 15;
            const float* p = &q_g[((size_t)b * Hn + h0g + hl) * Qn + sx * 8];
            float4 v0 = *(const float4*)p, v1 = *(const float4*)(p + 4);
            float f[8] = {v0.x, v0.y, v0.z, v0.w, v1.x, v1.y, v1.z, v1.w};
#pragma unroll
            for (int j = 0; j < 8; j++) Stg[stg64(sx * 8 + j, hl)] = f[j];
        }
        __syncthreads();
        // split B (scaled by wcq) + s1 partial
        for (int i = tid; i < 1024; i += 512) {
            int qq = i >> 3, hs = i & 7, h0 = hs * 8;
            float f[8];
#pragma unroll
            for (int j = 0; j < 8; j++) f[j] = Stg[stg64(qq, h0 + j)];
            float p = 0.f;
#pragma unroll
            for (int j = 0; j < 8; j++) p += f[j] * wq[h0g + h0 + j];
            p += __shfl_xor_sync(~0u, p, 1);
            p += __shfl_xor_sync(~0u, p, 2);
            p += __shfl_xor_sync(~0u, p, 4);
            if ((lane & 7) == 0) {
                if (kc == 0) s1s[qq] = p; else s1s[qq] += p;
            }
#pragma unroll
            for (int j = 0; j < 8; j++) f[j] *= wcq[h0g + h0 + j];
            split8_64(smem + 32768, smem + 49152, qq, hs, f);
        }
        __syncthreads();
        warp_gemm64(sb, sb + 16384, sb + 32768, sb + 49152, lane, m0, n0, acc);
    }
    __syncthreads();

    int lr = lane >> 2, lc2 = (lane & 3) * 2;

    // finalize S: acc += s0[row] + s1[col]
#pragma unroll
    for (int mf = 0; mf < 2; mf++) {
        int r0 = m0 + mf * 16 + lr, r1 = r0 + 8;
        float s0a = s0s[r0], s0b = s0s[r1];
#pragma unroll
        for (int nf = 0; nf < 4; nf++) {
            int col = n0 + nf * 8 + lc2;
            float s1a = s1s[col], s1b = s1s[col + 1];
            acc[mf][nf][0] += s0a + s1a;
            acc[mf][nf][1] += s0a + s1b;
            acc[mf][nf][2] += s0b + s1a;
            acc[mf][nf][3] += s0b + s1b;
        }
    }

    // write S [c][q]
#pragma unroll
    for (int mf = 0; mf < 2; mf++) {
        int r0 = m0 + mf * 16 + lr, r1 = r0 + 8;
#pragma unroll
        for (int nf = 0; nf < 4; nf++) {
            int col = n0 + nf * 8 + lc2;
            *(float2*)&g_S[((size_t)b * Cn + c0 + r0) * Qn + col] =
                make_float2(acc[mf][nf][0], acc[mf][nf][1]);
            *(float2*)&g_S[((size_t)b * Cn + c0 + r1) * Qn + col] =
                make_float2(acc[mf][nf][2], acc[mf][nf][3]);
        }
    }

    // masks
    bool qm0[4], qm1[4];
#pragma unroll
    for (int nf = 0; nf < 4; nf++) {
        qm0[nf] = qms[n0 + nf * 8 + lc2] > 0.f;
        qm1[nf] = qms[n0 + nf * 8 + lc2 + 1] > 0.f;
    }
    bool cmv[2][2];
#pragma unroll
    for (int mf = 0; mf < 2; mf++) {
        cmv[mf][0] = cms[m0 + mf * 16 + lr] > 0.f;
        cmv[mf][1] = cms[m0 + mf * 16 + 8 + lr] > 0.f;
    }

    // ---- row stats ----
    float rmx[2][2];
#pragma unroll
    for (int mf = 0; mf < 2; mf++) { rmx[mf][0] = -1e30f; rmx[mf][1] = -1e30f; }
#pragma unroll
    for (int mf = 0; mf < 2; mf++)
#pragma unroll
        for (int nf = 0; nf < 4; nf++) {
            if (qm0[nf]) {
                rmx[mf][0] = fmaxf(rmx[mf][0], acc[mf][nf][0]);
                rmx[mf][1] = fmaxf(rmx[mf][1], acc[mf][nf][2]);
            }
            if (qm1[nf]) {
                rmx[mf][0] = fmaxf(rmx[mf][0], acc[mf][nf][1]);
                rmx[mf][1] = fmaxf(rmx[mf][1], acc[mf][nf][3]);
            }
        }
#pragma unroll
    for (int mf = 0; mf < 2; mf++)
#pragma unroll
        for (int h = 0; h < 2; h++) {
            rmx[mf][h] = fmaxf(rmx[mf][h], __shfl_xor_sync(~0u, rmx[mf][h], 1));
            rmx[mf][h] = fmaxf(rmx[mf][h], __shfl_xor_sync(~0u, rmx[mf][h], 2));
        }
    if ((lane & 3) == 0)
#pragma unroll
        for (int mf = 0; mf < 2; mf++)
#pragma unroll
            for (int h = 0; h < 2; h++)
                red1[(wid & 3) * 128 + m0 + mf * 16 + h * 8 + lr] = rmx[mf][h];
    __syncthreads();

    float rowMv[2][2];
#pragma unroll
    for (int mf = 0; mf < 2; mf++)
#pragma unroll
        for (int h = 0; h < 2; h++) {
            int r = m0 + mf * 16 + h * 8 + lr;
            float m = red1[r];
#pragma unroll
            for (int g = 1; g < 4; g++) m = fmaxf(m, red1[g * 128 + r]);
            rowMv[mf][h] = m;
        }
    float rzz[2][2] = {{0.f, 0.f}, {0.f, 0.f}};
#pragma unroll
    for (int mf = 0; mf < 2; mf++)
#pragma unroll
        for (int nf = 0; nf < 4; nf++) {
            if (qm0[nf]) {
                rzz[mf][0] += __expf(acc[mf][nf][0] - rowMv[mf][0]);
                rzz[mf][1] += __expf(acc[mf][nf][2] - rowMv[mf][1]);
            }
            if (qm1[nf]) {
                rzz[mf][0] += __expf(acc[mf][nf][1] - rowMv[mf][0]);
                rzz[mf][1] += __expf(acc[mf][nf][3] - rowMv[mf][1]);
            }
        }
#pragma unroll
    for (int mf = 0; mf < 2; mf++)
#pragma unroll
        for (int h = 0; h < 2; h++) {
            rzz[mf][h] += __shfl_xor_sync(~0u, rzz[mf][h], 1);
            rzz[mf][h] += __shfl_xor_sync(~0u, rzz[mf][h], 2);
        }
    if ((lane & 3) == 0)
#pragma unroll
        for (int mf = 0; mf < 2; mf++)
#pragma unroll
            for (int h = 0; h < 2; h++)
                red2[(wid & 3) * 128 + m0 + mf * 16 + h * 8 + lr] = rzz[mf][h];
    __syncthreads();

    if ((wid & 3) == 0 && (lane & 3) == 0) {
#pragma unroll
        for (int mf = 0; mf < 2; mf++)
#pragma unroll
            for (int h = 0; h < 2; h++) {
                int r = m0 + mf * 16 + h * 8 + lr;
                float z = red2[r] + red2[128 + r] + red2[256 + r] + red2[384 + r];
                g_rowM[b * Cn + c0 + r] = rowMv[mf][h];
                g_rowZ[b * Cn + c0 + r] = z;
            }
    }
    __syncthreads();

    // ---- column partial stats ----
    float cmx[4][2];
#pragma unroll
    for (int nf = 0; nf < 4; nf++) { cmx[nf][0] = -1e30f; cmx[nf][1] = -1e30f; }
#pragma unroll
    for (int mf = 0; mf < 2; mf++)
#pragma unroll
        for (int nf = 0; nf < 4; nf++) {
            if (cmv[mf][0]) {
                cmx[nf][0] = fmaxf(cmx[nf][0], acc[mf][nf][0]);
                cmx[nf][1] = fmaxf(cmx[nf][1], acc[mf][nf][1]);
            }
            if (cmv[mf][1]) {
                cmx[nf][0] = fmaxf(cmx[nf][0], acc[mf][nf][2]);
                cmx[nf][1] = fmaxf(cmx[nf][1], acc[mf][nf][3]);
            }
        }
#pragma unroll
    for (int nf = 0; nf < 4; nf++)
#pragma unroll
        for (int v = 0; v < 2; v++) {
            cmx[nf][v] = fmaxf(cmx[nf][v], __shfl_xor_sync(~0u, cmx[nf][v], 4));
            cmx[nf][v] = fmaxf(cmx[nf][v], __shfl_xor_sync(~0u, cmx[nf][v], 8));
            cmx[nf][v] = fmaxf(cmx[nf][v], __shfl_xor_sync(~0u, cmx[nf][v], 16));
        }
    if (lr == 0)
#pragma unroll
        for (int nf = 0; nf < 4; nf++) {
            red1[(wid >> 2) * 128 + n0 + nf * 8 + lc2]     = cmx[nf][0];
            red1[(wid >> 2) * 128 + n0 + nf * 8 + lc2 + 1] = cmx[nf][1];
        }
    __syncthreads();

    float pMv[4][2];
#pragma unroll
    for (int nf = 0; nf < 4; nf++)
#pragma unroll
        for (int v = 0; v < 2; v++) {
            int col = n0 + nf * 8 + lc2 + v;
            float m = red1[col];
#pragma unroll
            for (int g = 1; g < 4; g++) m = fmaxf(m, red1[g * 128 + col]);
            pMv[nf][v] = m;
        }
    float czz[4][2] = {{0,0},{0,0},{0,0},{0,0}};
#pragma unroll
    for (int nf = 0; nf < 4; nf++) {
        if (cmv[0][0]) { czz[nf][0] += __expf(acc[0][nf][0] - pMv[nf][0]); czz[nf][1] += __expf(acc[0][nf][1] - pMv[nf][1]); }
        if (cmv[0][1]) { czz[nf][0] += __expf(acc[0][nf][2] - pMv[nf][0]); czz[nf][1] += __expf(acc[0][nf][3] - pMv[nf][1]); }
        if (cmv[1][0]) { czz[nf][0] += __expf(acc[1][nf][0] - pMv[nf][0]); czz[nf][1] += __expf(acc[1][nf][1] - pMv[nf][1]); }
        if (cmv[1][1]) { czz[nf][0] += __expf(acc[1][nf][2] - pMv[nf][0]); czz[nf][1] += __expf(acc[1][nf][3] - pMv[nf][1]); }
    }
#pragma unroll
    for (int nf = 0; nf < 4; nf++)
#pragma unroll
        for (int v = 0; v < 2; v++) {
            czz[nf][v] += __shfl_xor_sync(~0u, czz[nf][v], 4);
            czz[nf][v] += __shfl_xor_sync(~0u, czz[nf][v], 8);
            czz[nf][v] += __shfl_xor_sync(~0u, czz[nf][v], 16);
        }
    if (lr == 0)
#pragma unroll
        for (int nf = 0; nf < 4; nf++) {
            red2[(wid >> 2) * 128 + n0 + nf * 8 + lc2]     = czz[nf][0];
            red2[(wid >> 2) * 128 + n0 + nf * 8 + lc2 + 1] = czz[nf][1];
        }
    __syncthreads();

    if ((wid >> 2) == 0 && lr == 0) {
#pragma unroll
        for (int nf = 0; nf < 4; nf++)
#pragma unroll
            for (int v = 0; v < 2; v++) {
                int col = n0 + nf * 8 + lc2 + v;
                float z = red2[col] + red2[128 + col] + red2[256 + col] + red2[384 + col];
                g_pM[(b * NT + ct) * Qn + col] = pMv[nf][v];
                g_pZ[(b * NT + ct) * Qn + col] = z;
            }
    }
}

// ---------------- K3: qb^T = c · E2^T, split-K over 4 quarters --------------
// smem: Ahi 0, Alo 16384, Ehi 32768, Elo 49152, Stg 65536(32KB), colMs 98304
#define K3_SMEM 98816

__global__ __launch_bounds__(512, 2) void k3_qb(
    const float* __restrict__ c_g, const float* __restrict__ cmask)
{
    extern __shared__ __align__(256) char smem[];
    u32 sb = smem_u32(smem);
    float* Stg   = (float*)(smem + 65536);
    float* colMs = (float*)(smem + 98304);
    int tid = threadIdx.x, lane = tid & 31, wid = tid >> 5;
    int b = blockIdx.y, quarter = blockIdx.x;

    if (tid < 128) {
        float m = -3.4e38f;
#pragma unroll
        for (int t = 0; t < NT; t++) m = fmaxf(m, g_pM[(b * NT + t) * Qn + tid]);
        colMs[tid] = m;
    }

    float acc[2][4][4];
#pragma unroll
    for (int i = 0; i < 2; i++)
#pragma unroll
        for (int j = 0; j < 4; j++)
#pragma unroll
            for (int k = 0; k < 4; k++) acc[i][j][k] = 0.f;

    int m0 = (wid >> 2) * 32, n0 = (wid & 3) * 32;

    for (int it = 0; it < 4; it++) {
        int c0 = quarter * 256 + it * 64;
        __syncthreads();
        // A fill: c rows h 0..127, 64 c-cols (K-minor natural)
        for (int i = tid; i < 1024; i += 512) {
            int r = i >> 3, sx = i & 7;
            const float* pa = &c_g[((size_t)b * Hn + r) * Cn + c0 + sx * 8];
            float4 v0 = *(const float4*)pa, v1 = *(const float4*)(pa + 4);
            float f[8] = {v0.x, v0.y, v0.z, v0.w, v1.x, v1.y, v1.z, v1.w};
            split8_64(smem, smem + 16384, r, sx, f);
        }
        // stage E^T: Stg[q][c_local], exp+mask applied
        for (int i = tid; i < 1024; i += 512) {
            int rl = i >> 4, sx = i & 15;
            const float* ps = &g_S[((size_t)b * Cn + c0 + rl) * Qn + sx * 8];
            float4 s0 = *(const float4*)ps, s1 = *(const float4*)(ps + 4);
            float f[8] = {s0.x, s0.y, s0.z, s0.w, s1.x, s1.y, s1.z, s1.w};
            bool cmv = cmask[b * Cn + c0 + rl] > 0.f;
#pragma unroll
            for (int j = 0; j < 8; j++) {
                int q = sx * 8 + j;
                Stg[stg64(q, rl)] = cmv ? __expf(f[j] - colMs[q]) : 0.f;
            }
        }
        __syncthreads();
        // split E: rows q 0..127, 64 c-cols
        for (int i = tid; i < 1024; i += 512) {
            int qq = i >> 3, cs = i & 7;
            float f[8];
#pragma unroll
            for (int j = 0; j < 8; j++) f[j] = Stg[stg64(qq, cs * 8 + j)];
            split8_64(smem + 32768, smem + 49152, qq, cs, f);
        }
        __syncthreads();
        warp_gemm64(sb, sb + 16384, sb + 32768, sb + 49152, lane, m0, n0, acc);
    }

    int lr = lane >> 2, lc2 = (lane & 3) * 2;
#pragma unroll
    for (int mf = 0; mf < 2; mf++) {
        int h0 = m0 + mf * 16 + lr, h1 = h0 + 8;
#pragma unroll
        for (int nf = 0; nf < 4; nf++) {
            int col = n0 + nf * 8 + lc2;
            *(float2*)&g_qbp4[((size_t)(b * 4 + quarter) * Hn + h0) * Qn + col] =
                make_float2(acc[mf][nf][0], acc[mf][nf][1]);
            *(float2*)&g_qbp4[((size_t)(b * 4 + quarter) * Hn + h1) * Qn + col] =
                make_float2(acc[mf][nf][2], acc[mf][nf][3]);
        }
    }
}

// ---------------- K4: dual GEMM (a, bb) in one pass; assemble output --------
// smem: Ehi 0, Elo 32768, Qhi 65536, Qlo 98304, Phi 131072, Plo 163840,
//       rms 196608, qms 197120, rzs 197632, rcz 198144
#define K4_SMEM 198656

__global__ __launch_bounds__(512) void k4_out(
    const float* __restrict__ c_g, const float* __restrict__ q_g,
    const float* __restrict__ qmask, float* __restrict__ out)
{
    extern __shared__ __align__(256) char smem[];
    u32 sb = smem_u32(smem);
    float* rms = (float*)(smem + 196608);
    float* qms = (float*)(smem + 197120);
    float* rzs = (float*)(smem + 197632);
    float* rcz = (float*)(smem + 198144);
    int tid = threadIdx.x, lane = tid & 31, wid = tid >> 5;
    int b = blockIdx.y, ct = blockIdx.x, c0 = ct * 128;

    if (tid < 128) rms[tid] = g_rowM[b * Cn + c0 + tid];
    else if (tid < 256) qms[tid - 128] = qmask[b * Qn + tid - 128];
    else if (tid < 384) {
        float z = g_rowZ[b * Cn + c0 + tid - 256];
        rzs[tid - 256] = (z > 0.f) ? 1.f / z : 0.f;
    } else {
        int qq = tid - 384;
        float m = -3.4e38f;
#pragma unroll
        for (int t = 0; t < NT; t++) m = fmaxf(m, g_pM[(b * NT + t) * Qn + qq]);
        float z = 0.f;
#pragma unroll
        for (int t = 0; t < NT; t++)
            z += g_pZ[(b * NT + t) * Qn + qq] * __expf(g_pM[(b * NT + t) * Qn + qq] - m);
        rcz[qq] = (z > 0.f) ? 1.f / z : 0.f;
    }
    __syncthreads();

    for (int i = tid; i < 2048; i += 512) {
        int r = i >> 4, sx = i & 15;
        const float* ps = &g_S[((size_t)b * Cn + c0 + r) * Qn + sx * 8];
        float4 s0 = *(const float4*)ps, s1 = *(const float4*)(ps + 4);
        float fe[8] = {s0.x, s0.y, s0.z, s0.w, s1.x, s1.y, s1.z, s1.w};
        float rm = rms[r];
#pragma unroll
        for (int j = 0; j < 8; j++)
            fe[j] = (qms[sx * 8 + j] > 0.f) ? __expf(fe[j] - rm) : 0.f;
        split8(smem, smem + 32768, r, sx, fe);
        const float* pq = &q_g[((size_t)b * Hn + r) * Qn + sx * 8];
        float4 q0 = *(const float4*)pq, q1 = *(const float4*)(pq + 4);
        float fq[8] = {q0.x, q0.y, q0.z, q0.w, q1.x, q1.y, q1.z, q1.w};
        split8(smem + 65536, smem + 98304, r, sx, fq);
        const float* p0 = &g_qbp4[((size_t)(b * 4) * Hn + r) * Qn + sx * 8];
        const size_t PS = (size_t)Hn * Qn;
        float fp[8] = {0, 0, 0, 0, 0, 0, 0, 0};
#pragma unroll
        for (int t = 0; t < 4; t++) {
            float4 a0 = *(const float4*)(p0 + t * PS);
            float4 a1 = *(const float4*)(p0 + t * PS + 4);
            fp[0] += a0.x; fp[1] += a0.y; fp[2] += a0.z; fp[3] += a0.w;
            fp[4] += a1.x; fp[5] += a1.y; fp[6] += a1.z; fp[7] += a1.w;
        }
#pragma unroll
        for (int j = 0; j < 8; j++) fp[j] *= rcz[sx * 8 + j];
        split8(smem + 131072, smem + 163840, r, sx, fp);
    }
    __syncthreads();

    int m0 = (wid >> 2) * 32, n0 = (wid & 3) * 32;
    int lr = lane >> 2, lc = (lane & 3) * 2;

    float accA[2][4][4], accB[2][4][4];
#pragma unroll
    for (int i = 0; i < 2; i++)
#pragma unroll
        for (int j = 0; j < 4; j++)
#pragma unroll
            for (int k = 0; k < 4; k++) { accA[i][j][k] = 0.f; accB[i][j][k] = 0.f; }

    {
        u32 eh = sb, el = sb + 32768, qh = sb + 65536, ql = sb + 98304;
        u32 ph = sb + 131072, pl = sb + 163840;
        int rA = lane & 15, hi16 = lane >> 4;
        int rBl = (lane & 7) + ((lane >> 4) << 3);
        int kh = (lane >> 3) & 1;
        int rowA[2] = {m0 + rA, m0 + 16 + rA};
        int rowB[2] = {n0 + rBl, n0 + 16 + rBl};
#pragma unroll
        for (int ks = 0; ks < 8; ks++) {
            u32 AH[2][4], AL[2][4];
#pragma unroll
            for (int f = 0; f < 2; f++) {
                u32 sa = (u32)rowA[f] * 256 + (u32)((((ks << 1) + hi16) ^ (rowA[f] & 7)) << 4);
                ldsm4(eh + sa, AH[f]);
                ldsm4(el + sa, AL[f]);
            }
#pragma unroll
            for (int nh = 0; nh < 2; nh++) {
                u32 QH[4], QL[4], PH[4], PL[4];
                u32 sbo = (u32)rowB[nh] * 256 + (u32)((((ks << 1) + kh) ^ (rowB[nh] & 7)) << 4);
                ldsm4(qh + sbo, QH);
                ldsm4(ql + sbo, QL);
                ldsm4(ph + sbo, PH);
                ldsm4(pl + sbo, PL);
#pragma unroll
                for (int mf = 0; mf < 2; mf++)
#pragma unroll
                    for (int no = 0; no < 2; no++) {
                        float* dA = accA[mf][nh * 2 + no];
                        mmabf(dA, AH[mf], QH[2 * no], QH[2 * no + 1]);
                        mmabf(dA, AH[mf], QL[2 * no], QL[2 * no + 1]);
                        mmabf(dA, AL[mf], QH[2 * no], QH[2 * no + 1]);
                        float* dB = accB[mf][nh * 2 + no];
                        mmabf(dB, AH[mf], PH[2 * no], PH[2 * no + 1]);
                        mmabf(dB, AH[mf], PL[2 * no], PL[2 * no + 1]);
                        mmabf(dB, AL[mf], PH[2 * no], PH[2 * no + 1]);
                    }
            }
        }
    }
    __syncthreads();

    float* StA = (float*)(smem + 65536);
    float* StB = (float*)smem;
#pragma unroll
    for (int mf = 0; mf < 2; mf++) {
        int cl0 = m0 + mf * 16 + lr, cl1 = cl0 + 8;
        float rz0 = rzs[cl0], rz1 = rzs[cl1];
#pragma unroll
        for (int nf = 0; nf < 4; nf++) {
            int h = n0 + nf * 8 + lc;
            StA[(h << 7) + ((cl0 ^ h) & 127)]             = accA[mf][nf][0] * rz0;
            StA[((h + 1) << 7) + ((cl0 ^ (h + 1)) & 127)] = accA[mf][nf][1] * rz0;
            StA[(h << 7) + ((cl1 ^ h) & 127)]             = accA[mf][nf][2] * rz1;
            StA[((h + 1) << 7) + ((cl1 ^ (h + 1)) & 127)] = accA[mf][nf][3] * rz1;
            StB[(h << 7) + ((cl0 ^ h) & 127)]             = accB[mf][nf][0] * rz0;
            StB[((h + 1) << 7) + ((cl0 ^ (h + 1)) & 127)] = accB[mf][nf][1] * rz0;
            StB[(h << 7) + ((cl1 ^ h) & 127)]             = accB[mf][nf][2] * rz1;
            StB[((h + 1) << 7) + ((cl1 ^ (h + 1)) & 127)] = accB[mf][nf][3] * rz1;
        }
    }
    __syncthreads();

    const size_t HC = (size_t)Hn * Cn;
    for (int i = tid; i < 16384; i += 512) {
        int h = i >> 7, cc = i & 127;
        float a  = StA[(h << 7) + ((cc ^ h) & 127)];
        float bb = StB[(h << 7) + ((cc ^ h) & 127)];
        float cv = c_g[((size_t)b * Hn + h) * Cn + c0 + cc];
        size_t o = (size_t)b * 4 * HC + (size_t)h * Cn + c0 + cc;
        out[o]          = cv;
        out[o + HC]     = a;
        out[o + 2 * HC] = cv * a;
        out[o + 3 * HC] = cv * bb;
    }
}

// ---------------- launch ----------------
extern "C" void kernel_launch(void* const* d_in, const int* in_sizes, int n_in,
                              void* d_out, int out_size)
{
    const float* c     = (const float*)d_in[0];
    const float* q     = (const float*)d_in[1];
    const float* cmask = (const float*)d_in[2];
    const float* qmask = (const float*)d_in[3];
    const float* wc    = (const float*)d_in[4];
    const float* wq    = (const float*)d_in[5];
    const float* wcq   = (const float*)d_in[6];
    const float* bias  = (const float*)d_in[7];
    float* out = (float*)d_out;

    cudaFuncSetAttribute(k1_score, cudaFuncAttributeMaxDynamicSharedMemorySize, K1_SMEM);
    cudaFuncSetAttribute(k3_qb,    cudaFuncAttributeMaxDynamicSharedMemorySize, K3_SMEM);
    cudaFuncSetAttribute(k4_out,   cudaFuncAttributeMaxDynamicSharedMemorySize, K4_SMEM);

    k1_score<<<dim3(NT, Bn), 512, K1_SMEM>>>(c, q, cmask, qmask, wc, wq, wcq, bias);
    k3_qb<<<dim3(4, Bn), 512, K3_SMEM>>>(c, cmask);
    k4_out<<<dim3(NT, Bn), 512, K4_SMEM>>>(c, q, qmask, out);
}

// round 12
// speedup vs baseline: 1.2724x; 1.0719x over previous
#include <cuda_runtime.h>
#include <cuda_bf16.h>

#define Bn 64
#define Hn 128
#define Cn 1024
#define Qn 128
#define NT 8

typedef unsigned int u32;

// ---------------- scratch ----------------
__device__ float g_S  [Bn * Cn * Qn];
__device__ float g_rowM[Bn * Cn];
__device__ float g_rowZ[Bn * Cn];
__device__ float g_pM [Bn * NT * Qn];
__device__ float g_pZ [Bn * NT * Qn];
__device__ float g_qbp4[Bn * 4 * Hn * Qn];

// ---------------- helpers ----------------
__device__ __forceinline__ u32 smem_u32(const void* p) {
    u32 a;
    asm("{ .reg .u64 t; cvta.to.shared.u64 t, %1; cvt.u32.u64 %0, t; }" : "=r"(a) : "l"(p));
    return a;
}
__device__ __forceinline__ void ldsm4(u32 a, u32* r) {
    asm volatile("ldmatrix.sync.aligned.m8n8.x4.shared.b16 {%0,%1,%2,%3}, [%4];"
        : "=r"(r[0]), "=r"(r[1]), "=r"(r[2]), "=r"(r[3]) : "r"(a));
}
__device__ __forceinline__ void ldsm4t(u32 a, u32* r) {
    asm volatile("ldmatrix.sync.aligned.m8n8.x4.trans.shared.b16 {%0,%1,%2,%3}, [%4];"
        : "=r"(r[0]), "=r"(r[1]), "=r"(r[2]), "=r"(r[3]) : "r"(a));
}
__device__ __forceinline__ void mmabf(float* d, const u32* a, u32 b0, u32 b1) {
    asm volatile("mma.sync.aligned.m16n8k16.row.col.f32.bf16.bf16.f32 "
        "{%0,%1,%2,%3},{%4,%5,%6,%7},{%8,%9},{%0,%1,%2,%3};"
        : "+f"(d[0]), "+f"(d[1]), "+f"(d[2]), "+f"(d[3])
        : "r"(a[0]), "r"(a[1]), "r"(a[2]), "r"(a[3]), "r"(b0), "r"(b1));
}

// split 8 fp32 -> bf16 hi/lo, 16B store into 64-col tile (row stride 128B, 8 slots)
__device__ __forceinline__ void split8_64(char* hi, char* lo, int r, int slot,
                                          const float* f)
{
    u32 H[4], L[4];
#pragma unroll
    for (int j = 0; j < 4; j++) {
        float a = f[2 * j], b = f[2 * j + 1];
        __nv_bfloat16 ha = __float2bfloat16(a), hb = __float2bfloat16(b);
        float fa = __bfloat162float(ha), fb = __bfloat162float(hb);
        __nv_bfloat162 hp; hp.x = ha; hp.y = hb;
        H[j] = *(u32*)&hp;
        __nv_bfloat162 lp = __floats2bfloat162_rn(a - fa, b - fb);
        L[j] = *(u32*)&lp;
    }
    u32 off = (u32)r * 128 + (u32)((slot ^ (r & 7)) << 4);
    *(uint4*)(hi + off) = make_uint4(H[0], H[1], H[2], H[3]);
    *(uint4*)(lo + off) = make_uint4(L[0], L[1], L[2], L[3]);
}

// split 8 fp32 -> bf16 hi/lo, 16B store into 128-col tile (row stride 256B, 16 slots)
__device__ __forceinline__ void split8(char* hi, char* lo, int r, int slot,
                                       const float* f)
{
    u32 H[4], L[4];
#pragma unroll
    for (int j = 0; j < 4; j++) {
        float a = f[2 * j], b = f[2 * j + 1];
        __nv_bfloat16 ha = __float2bfloat16(a), hb = __float2bfloat16(b);
        float fa = __bfloat162float(ha), fb = __bfloat162float(hb);
        __nv_bfloat162 hp; hp.x = ha; hp.y = hb;
        H[j] = *(u32*)&hp;
        __nv_bfloat162 lp = __floats2bfloat162_rn(a - fa, b - fb);
        L[j] = *(u32*)&lp;
    }
    u32 off = (u32)r * 256 + (u32)((slot ^ (r & 7)) << 4);
    *(uint4*)(hi + off) = make_uint4(H[0], H[1], H[2], H[3]);
    *(uint4*)(lo + off) = make_uint4(L[0], L[1], L[2], L[3]);
}

// GEMM over K=64 where BOTH operands are stored [k:64 rows][mn:128 cols], trans-ldsm.
__device__ __forceinline__ void warp_gemm_tt(u32 ah, u32 al, u32 bh, u32 bl,
                                             int lane, int m0, int n0,
                                             float acc[2][4][4])
{
    int rkA = (lane & 7) + ((lane >> 4) << 3);      // A: k-half by bit4
    int slA = (lane >> 3) & 1;                      // A: m-half by bit3
    int rkB = (lane & 7) + (((lane >> 3) & 1) << 3);// B: k-half by bit3
    int slB = lane >> 4;                            // B: n-half by bit4
#pragma unroll
    for (int ks = 0; ks < 4; ks++) {
        u32 AH[2][4], AL[2][4], BH[2][4], BL[2][4];
#pragma unroll
        for (int mf = 0; mf < 2; mf++) {
            int row = ks * 16 + rkA;
            int slot = (m0 >> 3) + 2 * mf + slA;
            u32 ad = (u32)row * 256 + (u32)((slot ^ (row & 7)) << 4);
            ldsm4t(ah + ad, AH[mf]);
            ldsm4t(al + ad, AL[mf]);
        }
#pragma unroll
        for (int nb = 0; nb < 2; nb++) {
            int row = ks * 16 + rkB;
            int slot = (n0 >> 3) + 2 * nb + slB;
            u32 ad = (u32)row * 256 + (u32)((slot ^ (row & 7)) << 4);
            ldsm4t(bh + ad, BH[nb]);
            ldsm4t(bl + ad, BL[nb]);
        }
#pragma unroll
        for (int mf = 0; mf < 2; mf++)
#pragma unroll
            for (int nh = 0; nh < 2; nh++)
#pragma unroll
                for (int no = 0; no < 2; no++) {
                    float* d = acc[mf][nh * 2 + no];
                    mmabf(d, AH[mf], BH[nh][2 * no], BH[nh][2 * no + 1]);
                    mmabf(d, AH[mf], BL[nh][2 * no], BL[nh][2 * no + 1]);
                    mmabf(d, AL[mf], BH[nh][2 * no], BH[nh][2 * no + 1]);
                }
    }
}

// GEMM over K=64: A non-trans [m:128][k:64], B trans [k:64][n:128].
__device__ __forceinline__ void warp_gemm_nt(u32 ah, u32 al, u32 bh, u32 bl,
                                             int lane, int m0, int n0,
                                             float acc[2][4][4])
{
    int rA = lane & 15, hi16 = lane >> 4;
    int rowA[2] = {m0 + rA, m0 + 16 + rA};
    int rkB = (lane & 7) + (((lane >> 3) & 1) << 3);
    int slB = lane >> 4;
#pragma unroll
    for (int ks = 0; ks < 4; ks++) {
        u32 AH[2][4], AL[2][4], BH[2][4], BL[2][4];
#pragma unroll
        for (int f = 0; f < 2; f++) {
            u32 sa = (u32)rowA[f] * 128 + (u32)((((ks << 1) + hi16) ^ (rowA[f] & 7)) << 4);
            ldsm4(ah + sa, AH[f]);
            ldsm4(al + sa, AL[f]);
        }
#pragma unroll
        for (int nb = 0; nb < 2; nb++) {
            int row = ks * 16 + rkB;
            int slot = (n0 >> 3) + 2 * nb + slB;
            u32 ad = (u32)row * 256 + (u32)((slot ^ (row & 7)) << 4);
            ldsm4t(bh + ad, BH[nb]);
            ldsm4t(bl + ad, BL[nb]);
        }
#pragma unroll
        for (int mf = 0; mf < 2; mf++)
#pragma unroll
            for (int nh = 0; nh < 2; nh++)
#pragma unroll
                for (int no = 0; no < 2; no++) {
                    float* d = acc[mf][nh * 2 + no];
                    mmabf(d, AH[mf], BH[nh][2 * no], BH[nh][2 * no + 1]);
                    mmabf(d, AH[mf], BL[nh][2 * no], BL[nh][2 * no + 1]);
                    mmabf(d, AL[mf], BH[nh][2 * no], BH[nh][2 * no + 1]);
                }
    }
}

// ---------------- K1: natural-orientation fills (trans-ldsm GEMM) ----------
// smem: Ahi 0, Alo 16384, Bhi 32768, Blo 49152 (tiles [64h][128] bf16),
//       s0s 65536, s1s 66048, qms 66560, cms 67072, red1 67584(8KB), red2 75776(8KB)
#define K1_SMEM 83968

__global__ __launch_bounds__(512, 2) void k1_score(
    const float* __restrict__ c_g, const float* __restrict__ q_g,
    const float* __restrict__ cmask, const float* __restrict__ qmask,
    const float* __restrict__ wc, const float* __restrict__ wq,
    const float* __restrict__ wcq, const float* __restrict__ bias)
{
    extern __shared__ __align__(256) char smem[];
    u32 sb = smem_u32(smem);
    float* s0s  = (float*)(smem + 65536);
    float* s1s  = (float*)(smem + 66048);
    float* qms  = (float*)(smem + 66560);
    float* cms  = (float*)(smem + 67072);
    float* red1 = (float*)(smem + 67584);   // [16][128]
    float* red2 = (float*)(smem + 75776);   // [16][128]
    int tid = threadIdx.x, lane = tid & 31, wid = tid >> 5;
    int b = blockIdx.y, ct = blockIdx.x, c0 = ct * 128;
    float biasv = bias[0];

    for (int i = tid; i < 2048; i += 512) { red1[i] = 0.f; red2[i] = 0.f; }
    if (tid < 128) qms[tid] = qmask[b * Qn + tid];
    else if (tid < 256) cms[tid - 128] = cmask[b * Cn + c0 + tid - 128];

    float acc[2][4][4];
#pragma unroll
    for (int i = 0; i < 2; i++)
#pragma unroll
        for (int j = 0; j < 4; j++)
#pragma unroll
            for (int k = 0; k < 4; k++) acc[i][j][k] = 0.f;

    int m0 = (wid >> 2) * 32, n0 = (wid & 3) * 32;
    int sx0 = tid & 15;

#pragma unroll
    for (int kc = 0; kc < 2; kc++) {
        __syncthreads();
        float s0p[8] = {0, 0, 0, 0, 0, 0, 0, 0};
        float s1p[8] = {0, 0, 0, 0, 0, 0, 0, 0};
#pragma unroll
        for (int it = 0; it < 2; it++) {
            int i = tid + it * 512;
            int hl = i >> 4, sx = i & 15;
            int h = kc * 64 + hl;
            const float* pc = &c_g[((size_t)b * Hn + h) * Cn + c0 + sx * 8];
            float4 v0 = *(const float4*)pc, v1 = *(const float4*)(pc + 4);
            float f[8] = {v0.x, v0.y, v0.z, v0.w, v1.x, v1.y, v1.z, v1.w};
            float wcv = __ldg(&wc[h]);
#pragma unroll
            for (int j = 0; j < 8; j++) s0p[j] += f[j] * wcv;
            split8(smem, smem + 16384, hl, sx, f);
            const float* pq = &q_g[((size_t)b * Hn + h) * Qn + sx * 8];
            float4 u0 = *(const float4*)pq, u1 = *(const float4*)(pq + 4);
            float g[8] = {u0.x, u0.y, u0.z, u0.w, u1.x, u1.y, u1.z, u1.w};
            float wqv = __ldg(&wq[h]), wcqv = __ldg(&wcq[h]);
#pragma unroll
            for (int j = 0; j < 8; j++) { s1p[j] += g[j] * wqv; g[j] *= wcqv; }
            split8(smem + 32768, smem + 49152, hl, sx, g);
        }
#pragma unroll
        for (int j = 0; j < 8; j++) {
            s0p[j] += __shfl_xor_sync(~0u, s0p[j], 16);
            s1p[j] += __shfl_xor_sync(~0u, s1p[j], 16);
        }
        if (lane < 16) {
#pragma unroll
            for (int j = 0; j < 8; j++) {
                red1[wid * 128 + sx0 * 8 + j] += s0p[j];
                red2[wid * 128 + sx0 * 8 + j] += s1p[j];
            }
        }
        __syncthreads();
        warp_gemm_tt(sb, sb + 16384, sb + 32768, sb + 49152, lane, m0, n0, acc);
    }
    __syncthreads();
    if (tid < 128) {
        float a = 0.f, bqv = 0.f;
#pragma unroll
        for (int w = 0; w < 16; w++) { a += red1[w * 128 + tid]; bqv += red2[w * 128 + tid]; }
        s0s[tid] = a + biasv;
        s1s[tid] = bqv;
    }
    __syncthreads();

    int lr = lane >> 2, lc2 = (lane & 3) * 2;

    // finalize S: acc += s0[row] + s1[col]
#pragma unroll
    for (int mf = 0; mf < 2; mf++) {
        int r0 = m0 + mf * 16 + lr, r1 = r0 + 8;
        float s0a = s0s[r0], s0b = s0s[r1];
#pragma unroll
        for (int nf = 0; nf < 4; nf++) {
            int col = n0 + nf * 8 + lc2;
            float s1a = s1s[col], s1b = s1s[col + 1];
            acc[mf][nf][0] += s0a + s1a;
            acc[mf][nf][1] += s0a + s1b;
            acc[mf][nf][2] += s0b + s1a;
            acc[mf][nf][3] += s0b + s1b;
        }
    }

    // write S [c][q]
#pragma unroll
    for (int mf = 0; mf < 2; mf++) {
        int r0 = m0 + mf * 16 + lr, r1 = r0 + 8;
#pragma unroll
        for (int nf = 0; nf < 4; nf++) {
            int col = n0 + nf * 8 + lc2;
            *(float2*)&g_S[((size_t)b * Cn + c0 + r0) * Qn + col] =
                make_float2(acc[mf][nf][0], acc[mf][nf][1]);
            *(float2*)&g_S[((size_t)b * Cn + c0 + r1) * Qn + col] =
                make_float2(acc[mf][nf][2], acc[mf][nf][3]);
        }
    }

    // masks
    bool qm0[4], qm1[4];
#pragma unroll
    for (int nf = 0; nf < 4; nf++) {
        qm0[nf] = qms[n0 + nf * 8 + lc2] > 0.f;
        qm1[nf] = qms[n0 + nf * 8 + lc2 + 1] > 0.f;
    }
    bool cmv[2][2];
#pragma unroll
    for (int mf = 0; mf < 2; mf++) {
        cmv[mf][0] = cms[m0 + mf * 16 + lr] > 0.f;
        cmv[mf][1] = cms[m0 + mf * 16 + 8 + lr] > 0.f;
    }

    // ---- row stats ----
    float rmx[2][2];
#pragma unroll
    for (int mf = 0; mf < 2; mf++) { rmx[mf][0] = -1e30f; rmx[mf][1] = -1e30f; }
#pragma unroll
    for (int mf = 0; mf < 2; mf++)
#pragma unroll
        for (int nf = 0; nf < 4; nf++) {
            if (qm0[nf]) {
                rmx[mf][0] = fmaxf(rmx[mf][0], acc[mf][nf][0]);
                rmx[mf][1] = fmaxf(rmx[mf][1], acc[mf][nf][2]);
            }
            if (qm1[nf]) {
                rmx[mf][0] = fmaxf(rmx[mf][0], acc[mf][nf][1]);
                rmx[mf][1] = fmaxf(rmx[mf][1], acc[mf][nf][3]);
            }
        }
#pragma unroll
    for (int mf = 0; mf < 2; mf++)
#pragma unroll
        for (int h = 0; h < 2; h++) {
            rmx[mf][h] = fmaxf(rmx[mf][h], __shfl_xor_sync(~0u, rmx[mf][h], 1));
            rmx[mf][h] = fmaxf(rmx[mf][h], __shfl_xor_sync(~0u, rmx[mf][h], 2));
        }
    if ((lane & 3) == 0)
#pragma unroll
        for (int mf = 0; mf < 2; mf++)
#pragma unroll
            for (int h = 0; h < 2; h++)
                red1[(wid & 3) * 128 + m0 + mf * 16 + h * 8 + lr] = rmx[mf][h];
    __syncthreads();

    float rowMv[2][2];
#pragma unroll
    for (int mf = 0; mf < 2; mf++)
#pragma unroll
        for (int h = 0; h < 2; h++) {
            int r = m0 + mf * 16 + h * 8 + lr;
            float m = red1[r];
#pragma unroll
            for (int g = 1; g < 4; g++) m = fmaxf(m, red1[g * 128 + r]);
            rowMv[mf][h] = m;
        }
    float rzz[2][2] = {{0.f, 0.f}, {0.f, 0.f}};
#pragma unroll
    for (int mf = 0; mf < 2; mf++)
#pragma unroll
        for (int nf = 0; nf < 4; nf++) {
            if (qm0[nf]) {
                rzz[mf][0] += __expf(acc[mf][nf][0] - rowMv[mf][0]);
                rzz[mf][1] += __expf(acc[mf][nf][2] - rowMv[mf][1]);
            }
            if (qm1[nf]) {
                rzz[mf][0] += __expf(acc[mf][nf][1] - rowMv[mf][0]);
                rzz[mf][1] += __expf(acc[mf][nf][3] - rowMv[mf][1]);
            }
        }
#pragma unroll
    for (int mf = 0; mf < 2; mf++)
#pragma unroll
        for (int h = 0; h < 2; h++) {
            rzz[mf][h] += __shfl_xor_sync(~0u, rzz[mf][h], 1);
            rzz[mf][h] += __shfl_xor_sync(~0u, rzz[mf][h], 2);
        }
    if ((lane & 3) == 0)
#pragma unroll
        for (int mf = 0; mf < 2; mf++)
#pragma unroll
            for (int h = 0; h < 2; h++)
                red2[(wid & 3) * 128 + m0 + mf * 16 + h * 8 + lr] = rzz[mf][h];
    __syncthreads();

    if ((wid & 3) == 0 && (lane & 3) == 0) {
#pragma unroll
        for (int mf = 0; mf < 2; mf++)
#pragma unroll
            for (int h = 0; h < 2; h++) {
                int r = m0 + mf * 16 + h * 8 + lr;
                float z = red2[r] + red2[128 + r] + red2[256 + r] + red2[384 + r];
                g_rowM[b * Cn + c0 + r] = rowMv[mf][h];
                g_rowZ[b * Cn + c0 + r] = z;
            }
    }
    __syncthreads();

    // ---- column partial stats ----
    float cmx[4][2];
#pragma unroll
    for (int nf = 0; nf < 4; nf++) { cmx[nf][0] = -1e30f; cmx[nf][1] = -1e30f; }
#pragma unroll
    for (int mf = 0; mf < 2; mf++)
#pragma unroll
        for (int nf = 0; nf < 4; nf++) {
            if (cmv[mf][0]) {
                cmx[nf][0] = fmaxf(cmx[nf][0], acc[mf][nf][0]);
                cmx[nf][1] = fmaxf(cmx[nf][1], acc[mf][nf][1]);
            }
            if (cmv[mf][1]) {
                cmx[nf][0] = fmaxf(cmx[nf][0], acc[mf][nf][2]);
                cmx[nf][1] = fmaxf(cmx[nf][1], acc[mf][nf][3]);
            }
        }
#pragma unroll
    for (int nf = 0; nf < 4; nf++)
#pragma unroll
        for (int v = 0; v < 2; v++) {
            cmx[nf][v] = fmaxf(cmx[nf][v], __shfl_xor_sync(~0u, cmx[nf][v], 4));
            cmx[nf][v] = fmaxf(cmx[nf][v], __shfl_xor_sync(~0u, cmx[nf][v], 8));
            cmx[nf][v] = fmaxf(cmx[nf][v], __shfl_xor_sync(~0u, cmx[nf][v], 16));
        }
    if (lr == 0)
#pragma unroll
        for (int nf = 0; nf < 4; nf++) {
            red1[(wid >> 2) * 128 + n0 + nf * 8 + lc2]     = cmx[nf][0];
            red1[(wid >> 2) * 128 + n0 + nf * 8 + lc2 + 1] = cmx[nf][1];
        }
    __syncthreads();

    float pMv[4][2];
#pragma unroll
    for (int nf = 0; nf < 4; nf++)
#pragma unroll
        for (int v = 0; v < 2; v++) {
            int col = n0 + nf * 8 + lc2 + v;
            float m = red1[col];
#pragma unroll
            for (int g = 1; g < 4; g++) m = fmaxf(m, red1[g * 128 + col]);
            pMv[nf][v] = m;
        }
    float czz[4][2] = {{0,0},{0,0},{0,0},{0,0}};
#pragma unroll
    for (int nf = 0; nf < 4; nf++) {
        if (cmv[0][0]) { czz[nf][0] += __expf(acc[0][nf][0] - pMv[nf][0]); czz[nf][1] += __expf(acc[0][nf][1] - pMv[nf][1]); }
        if (cmv[0][1]) { czz[nf][0] += __expf(acc[0][nf][2] - pMv[nf][0]); czz[nf][1] += __expf(acc[0][nf][3] - pMv[nf][1]); }
        if (cmv[1][0]) { czz[nf][0] += __expf(acc[1][nf][0] - pMv[nf][0]); czz[nf][1] += __expf(acc[1][nf][1] - pMv[nf][1]); }
        if (cmv[1][1]) { czz[nf][0] += __expf(acc[1][nf][2] - pMv[nf][0]); czz[nf][1] += __expf(acc[1][nf][3] - pMv[nf][1]); }
    }
#pragma unroll
    for (int nf = 0; nf < 4; nf++)
#pragma unroll
        for (int v = 0; v < 2; v++) {
            czz[nf][v] += __shfl_xor_sync(~0u, czz[nf][v], 4);
            czz[nf][v] += __shfl_xor_sync(~0u, czz[nf][v], 8);
            czz[nf][v] += __shfl_xor_sync(~0u, czz[nf][v], 16);
        }
    if (lr == 0)
#pragma unroll
        for (int nf = 0; nf < 4; nf++) {
            red2[(wid >> 2) * 128 + n0 + nf * 8 + lc2]     = czz[nf][0];
            red2[(wid >> 2) * 128 + n0 + nf * 8 + lc2 + 1] = czz[nf][1];
        }
    __syncthreads();

    if ((wid >> 2) == 0 && lr == 0) {
#pragma unroll
        for (int nf = 0; nf < 4; nf++)
#pragma unroll
            for (int v = 0; v < 2; v++) {
                int col = n0 + nf * 8 + lc2 + v;
                float z = red2[col] + red2[128 + col] + red2[256 + col] + red2[384 + col];
                g_pM[(b * NT + ct) * Qn + col] = pMv[nf][v];
                g_pZ[(b * NT + ct) * Qn + col] = z;
            }
    }
}

// ---------------- K3: qb^T = c · E2^T, split-K over 4 quarters --------------
// smem: Ahi 0 ([128h][64c]), Alo 16384, Ehi 32768 ([64c][128q]), Elo 49152, colMs 65536
#define K3_SMEM 66048

__global__ __launch_bounds__(512, 2) void k3_qb(
    const float* __restrict__ c_g, const float* __restrict__ cmask)
{
    extern __shared__ __align__(256) char smem[];
    u32 sb = smem_u32(smem);
    float* colMs = (float*)(smem + 65536);
    int tid = threadIdx.x, lane = tid & 31, wid = tid >> 5;
    int b = blockIdx.y, quarter = blockIdx.x;

    if (tid < 128) {
        float m = -3.4e38f;
#pragma unroll
        for (int t = 0; t < NT; t++) m = fmaxf(m, g_pM[(b * NT + t) * Qn + tid]);
        colMs[tid] = m;
    }

    float acc[2][4][4];
#pragma unroll
    for (int i = 0; i < 2; i++)
#pragma unroll
        for (int j = 0; j < 4; j++)
#pragma unroll
            for (int k = 0; k < 4; k++) acc[i][j][k] = 0.f;

    int m0 = (wid >> 2) * 32, n0 = (wid & 3) * 32;

    for (int it = 0; it < 4; it++) {
        int c0 = quarter * 256 + it * 64;
        __syncthreads();
        // A fill: c rows h 0..127, 64 c-cols (K-minor natural)
        for (int i = tid; i < 1024; i += 512) {
            int r = i >> 3, sx = i & 7;
            const float* pa = &c_g[((size_t)b * Hn + r) * Cn + c0 + sx * 8];
            float4 v0 = *(const float4*)pa, v1 = *(const float4*)(pa + 4);
            float f[8] = {v0.x, v0.y, v0.z, v0.w, v1.x, v1.y, v1.z, v1.w};
            split8_64(smem, smem + 16384, r, sx, f);
        }
        // E fill: natural orientation [c-local 64][q 128], exp+mask at fill
        for (int i = tid; i < 1024; i += 512) {
            int cl = i >> 4, sx = i & 15;
            const float* ps = &g_S[((size_t)b * Cn + c0 + cl) * Qn + sx * 8];
            float4 s0 = *(const float4*)ps, s1 = *(const float4*)(ps + 4);
            float f[8] = {s0.x, s0.y, s0.z, s0.w, s1.x, s1.y, s1.z, s1.w};
            bool cmv = __ldg(&cmask[b * Cn + c0 + cl]) > 0.f;
#pragma unroll
            for (int j = 0; j < 8; j++)
                f[j] = cmv ? __expf(f[j] - colMs[sx * 8 + j]) : 0.f;
            split8(smem + 32768, smem + 49152, cl, sx, f);
        }
        __syncthreads();
        warp_gemm_nt(sb, sb + 16384, sb + 32768, sb + 49152, lane, m0, n0, acc);
    }

    int lr = lane >> 2, lc2 = (lane & 3) * 2;
#pragma unroll
    for (int mf = 0; mf < 2; mf++) {
        int h0 = m0 + mf * 16 + lr, h1 = h0 + 8;
#pragma unroll
        for (int nf = 0; nf < 4; nf++) {
            int col = n0 + nf * 8 + lc2;
            *(float2*)&g_qbp4[((size_t)(b * 4 + quarter) * Hn + h0) * Qn + col] =
                make_float2(acc[mf][nf][0], acc[mf][nf][1]);
            *(float2*)&g_qbp4[((size_t)(b * 4 + quarter) * Hn + h1) * Qn + col] =
                make_float2(acc[mf][nf][2], acc[mf][nf][3]);
        }
    }
}

// ---------------- K4: dual GEMM (a, bb) in one pass; assemble output --------
#define K4_SMEM 198656

__global__ __launch_bounds__(512) void k4_out(
    const float* __restrict__ c_g, const float* __restrict__ q_g,
    const float* __restrict__ qmask, float* __restrict__ out)
{
    extern __shared__ __align__(256) char smem[];
    u32 sb = smem_u32(smem);
    float* rms = (float*)(smem + 196608);
    float* qms = (float*)(smem + 197120);
    float* rzs = (float*)(smem + 197632);
    float* rcz = (float*)(smem + 198144);
    int tid = threadIdx.x, lane = tid & 31, wid = tid >> 5;
    int b = blockIdx.y, ct = blockIdx.x, c0 = ct * 128;

    if (tid < 128) rms[tid] = g_rowM[b * Cn + c0 + tid];
    else if (tid < 256) qms[tid - 128] = qmask[b * Qn + tid - 128];
    else if (tid < 384) {
        float z = g_rowZ[b * Cn + c0 + tid - 256];
        rzs[tid - 256] = (z > 0.f) ? 1.f / z : 0.f;
    } else {
        int qq = tid - 384;
        float m = -3.4e38f;
#pragma unroll
        for (int t = 0; t < NT; t++) m = fmaxf(m, g_pM[(b * NT + t) * Qn + qq]);
        float z = 0.f;
#pragma unroll
        for (int t = 0; t < NT; t++)
            z += g_pZ[(b * NT + t) * Qn + qq] * __expf(g_pM[(b * NT + t) * Qn + qq] - m);
        rcz[qq] = (z > 0.f) ? 1.f / z : 0.f;
    }
    __syncthreads();

    for (int i = tid; i < 2048; i += 512) {
        int r = i >> 4, sx = i & 15;
        const float* ps = &g_S[((size_t)b * Cn + c0 + r) * Qn + sx * 8];
        float4 s0 = *(const float4*)ps, s1 = *(const float4*)(ps + 4);
        float fe[8] = {s0.x, s0.y, s0.z, s0.w, s1.x, s1.y, s1.z, s1.w};
        float rm = rms[r];
#pragma unroll
        for (int j = 0; j < 8; j++)
            fe[j] = (qms[sx * 8 + j] > 0.f) ? __expf(fe[j] - rm) : 0.f;
        split8(smem, smem + 32768, r, sx, fe);
        const float* pq = &q_g[((size_t)b * Hn + r) * Qn + sx * 8];
        float4 q0 = *(const float4*)pq, q1 = *(const float4*)(pq + 4);
        float fq[8] = {q0.x, q0.y, q0.z, q0.w, q1.x, q1.y, q1.z, q1.w};
        split8(smem + 65536, smem + 98304, r, sx, fq);
        const float* p0 = &g_qbp4[((size_t)(b * 4) * Hn + r) * Qn + sx * 8];
        const size_t PS = (size_t)Hn * Qn;
        float fp[8] = {0, 0, 0, 0, 0, 0, 0, 0};
#pragma unroll
        for (int t = 0; t < 4; t++) {
            float4 a0 = *(const float4*)(p0 + t * PS);
            float4 a1 = *(const float4*)(p0 + t * PS + 4);
            fp[0] += a0.x; fp[1] += a0.y; fp[2] += a0.z; fp[3] += a0.w;
            fp[4] += a1.x; fp[5] += a1.y; fp[6] += a1.z; fp[7] += a1.w;
        }
#pragma unroll
        for (int j = 0; j < 8; j++) fp[j] *= rcz[sx * 8 + j];
        split8(smem + 131072, smem + 163840, r, sx, fp);
    }
    __syncthreads();

    int m0 = (wid >> 2) * 32, n0 = (wid & 3) * 32;
    int lr = lane >> 2, lc = (lane & 3) * 2;

    float accA[2][4][4], accB[2][4][4];
#pragma unroll
    for (int i = 0; i < 2; i++)
#pragma unroll
        for (int j = 0; j < 4; j++)
#pragma unroll
            for (int k = 0; k < 4; k++) { accA[i][j][k] = 0.f; accB[i][j][k] = 0.f; }

    {
        u32 eh = sb, el = sb + 32768, qh = sb + 65536, ql = sb + 98304;
        u32 ph = sb + 131072, pl = sb + 163840;
        int rA = lane & 15, hi16 = lane >> 4;
        int rBl = (lane & 7) + ((lane >> 4) << 3);
        int kh = (lane >> 3) & 1;
        int rowA[2] = {m0 + rA, m0 + 16 + rA};
        int rowB[2] = {n0 + rBl, n0 + 16 + rBl};
#pragma unroll
        for (int ks = 0; ks < 8; ks++) {
            u32 AH[2][4], AL[2][4];
#pragma unroll
            for (int f = 0; f < 2; f++) {
                u32 sa = (u32)rowA[f] * 256 + (u32)((((ks << 1) + hi16) ^ (rowA[f] & 7)) << 4);
                ldsm4(eh + sa, AH[f]);
                ldsm4(el + sa, AL[f]);
            }
#pragma unroll
            for (int nh = 0; nh < 2; nh++) {
                u32 QH[4], QL[4], PH[4], PL[4];
                u32 sbo = (u32)rowB[nh] * 256 + (u32)((((ks << 1) + kh) ^ (rowB[nh] & 7)) << 4);
                ldsm4(qh + sbo, QH);
                ldsm4(ql + sbo, QL);
                ldsm4(ph + sbo, PH);
                ldsm4(pl + sbo, PL);
#pragma unroll
                for (int mf = 0; mf < 2; mf++)
#pragma unroll
                    for (int no = 0; no < 2; no++) {
                        float* dA = accA[mf][nh * 2 + no];
                        mmabf(dA, AH[mf], QH[2 * no], QH[2 * no + 1]);
                        mmabf(dA, AH[mf], QL[2 * no], QL[2 * no + 1]);
                        mmabf(dA, AL[mf], QH[2 * no], QH[2 * no + 1]);
                        float* dB = accB[mf][nh * 2 + no];
                        mmabf(dB, AH[mf], PH[2 * no], PH[2 * no + 1]);
                        mmabf(dB, AH[mf], PL[2 * no], PL[2 * no + 1]);
                        mmabf(dB, AL[mf], PH[2 * no], PH[2 * no + 1]);
                    }
            }
        }
    }
    __syncthreads();

    float* StA = (float*)(smem + 65536);
    float* StB = (float*)smem;
#pragma unroll
    for (int mf = 0; mf < 2; mf++) {
        int cl0 = m0 + mf * 16 + lr, cl1 = cl0 + 8;
        float rz0 = rzs[cl0], rz1 = rzs[cl1];
#pragma unroll
        for (int nf = 0; nf < 4; nf++) {
            int h = n0 + nf * 8 + lc;
            StA[(h << 7) + ((cl0 ^ h) & 127)]             = accA[mf][nf][0] * rz0;
            StA[((h + 1) << 7) + ((cl0 ^ (h + 1)) & 127)] = accA[mf][nf][1] * rz0;
            StA[(h << 7) + ((cl1 ^ h) & 127)]             = accA[mf][nf][2] * rz1;
            StA[((h + 1) << 7) + ((cl1 ^ (h + 1)) & 127)] = accA[mf][nf][3] * rz1;
            StB[(h << 7) + ((cl0 ^ h) & 127)]             = accB[mf][nf][0] * rz0;
            StB[((h + 1) << 7) + ((cl0 ^ (h + 1)) & 127)] = accB[mf][nf][1] * rz0;
            StB[(h << 7) + ((cl1 ^ h) & 127)]             = accB[mf][nf][2] * rz1;
            StB[((h + 1) << 7) + ((cl1 ^ (h + 1)) & 127)] = accB[mf][nf][3] * rz1;
        }
    }
    __syncthreads();

    const size_t HC = (size_t)Hn * Cn;
    for (int i = tid; i < 16384; i += 512) {
        int h = i >> 7, cc = i & 127;
        float a  = StA[(h << 7) + ((cc ^ h) & 127)];
        float bb = StB[(h << 7) + ((cc ^ h) & 127)];
        float cv = c_g[((size_t)b * Hn + h) * Cn + c0 + cc];
        size_t o = (size_t)b * 4 * HC + (size_t)h * Cn + c0 + cc;
        out[o]          = cv;
        out[o + HC]     = a;
        out[o + 2 * HC] = cv * a;
        out[o + 3 * HC] = cv * bb;
    }
}

// ---------------- launch ----------------
extern "C" void kernel_launch(void* const* d_in, const int* in_sizes, int n_in,
                              void* d_out, int out_size)
{
    const float* c     = (const float*)d_in[0];
    const float* q     = (const float*)d_in[1];
    const float* cmask = (const float*)d_in[2];
    const float* qmask = (const float*)d_in[3];
    const float* wc    = (const float*)d_in[4];
    const float* wq    = (const float*)d_in[5];
    const float* wcq   = (const float*)d_in[6];
    const float* bias  = (const float*)d_in[7];
    float* out = (float*)d_out;

    cudaFuncSetAttribute(k1_score, cudaFuncAttributeMaxDynamicSharedMemorySize, K1_SMEM);
    cudaFuncSetAttribute(k3_qb,    cudaFuncAttributeMaxDynamicSharedMemorySize, K3_SMEM);
    cudaFuncSetAttribute(k4_out,   cudaFuncAttributeMaxDynamicSharedMemorySize, K4_SMEM);

    k1_score<<<dim3(NT, Bn), 512, K1_SMEM>>>(c, q, cmask, qmask, wc, wq, wcq, bias);
    k3_qb<<<dim3(4, Bn), 512, K3_SMEM>>>(c, cmask);
    k4_out<<<dim3(NT, Bn), 512, K4_SMEM>>>(c, q, qmask, out);
}

// round 13
// speedup vs baseline: 1.3027x; 1.0238x over previous
#include <cuda_runtime.h>
#include <cuda_bf16.h>

#define Bn 64
#define Hn 128
#define Cn 1024
#define Qn 128
#define NT 8

typedef unsigned int u32;

// ---------------- scratch ----------------
__device__ float g_S  [Bn * Cn * Qn];
__device__ float g_rowM[Bn * Cn];
__device__ float g_rowZ[Bn * Cn];
__device__ float g_pM [Bn * NT * Qn];
__device__ float g_pZ [Bn * NT * Qn];
__device__ float g_qbp4[Bn * 4 * Hn * Qn];
__device__ char  g_qhi[Bn * 32768];   // q bf16-hi tiles, smem byte-layout
__device__ char  g_qlo[Bn * 32768];   // q bf16-lo tiles
__device__ float g_s1 [Bn * Qn];      // q . wq

// ---------------- helpers ----------------
__device__ __forceinline__ u32 smem_u32(const void* p) {
    u32 a;
    asm("{ .reg .u64 t; cvta.to.shared.u64 t, %1; cvt.u32.u64 %0, t; }" : "=r"(a) : "l"(p));
    return a;
}
__device__ __forceinline__ void ldsm4(u32 a, u32* r) {
    asm volatile("ldmatrix.sync.aligned.m8n8.x4.shared.b16 {%0,%1,%2,%3}, [%4];"
        : "=r"(r[0]), "=r"(r[1]), "=r"(r[2]), "=r"(r[3]) : "r"(a));
}
__device__ __forceinline__ void ldsm4t(u32 a, u32* r) {
    asm volatile("ldmatrix.sync.aligned.m8n8.x4.trans.shared.b16 {%0,%1,%2,%3}, [%4];"
        : "=r"(r[0]), "=r"(r[1]), "=r"(r[2]), "=r"(r[3]) : "r"(a));
}
__device__ __forceinline__ void mmabf(float* d, const u32* a, u32 b0, u32 b1) {
    asm volatile("mma.sync.aligned.m16n8k16.row.col.f32.bf16.bf16.f32 "
        "{%0,%1,%2,%3},{%4,%5,%6,%7},{%8,%9},{%0,%1,%2,%3};"
        : "+f"(d[0]), "+f"(d[1]), "+f"(d[2]), "+f"(d[3])
        : "r"(a[0]), "r"(a[1]), "r"(a[2]), "r"(a[3]), "r"(b0), "r"(b1));
}

// split 8 fp32 -> bf16 hi/lo, 16B store into 64-col tile (row stride 128B, 8 slots)
__device__ __forceinline__ void split8_64(char* hi, char* lo, int r, int slot,
                                          const float* f)
{
    u32 H[4], L[4];
#pragma unroll
    for (int j = 0; j < 4; j++) {
        float a = f[2 * j], b = f[2 * j + 1];
        __nv_bfloat16 ha = __float2bfloat16(a), hb = __float2bfloat16(b);
        float fa = __bfloat162float(ha), fb = __bfloat162float(hb);
        __nv_bfloat162 hp; hp.x = ha; hp.y = hb;
        H[j] = *(u32*)&hp;
        __nv_bfloat162 lp = __floats2bfloat162_rn(a - fa, b - fb);
        L[j] = *(u32*)&lp;
    }
    u32 off = (u32)r * 128 + (u32)((slot ^ (r & 7)) << 4);
    *(uint4*)(hi + off) = make_uint4(H[0], H[1], H[2], H[3]);
    *(uint4*)(lo + off) = make_uint4(L[0], L[1], L[2], L[3]);
}

// split 8 fp32 -> bf16 hi/lo, 16B store into 128-col tile (row stride 256B, 16 slots)
__device__ __forceinline__ void split8(char* hi, char* lo, int r, int slot,
                                       const float* f)
{
    u32 H[4], L[4];
#pragma unroll
    for (int j = 0; j < 4; j++) {
        float a = f[2 * j], b = f[2 * j + 1];
        __nv_bfloat16 ha = __float2bfloat16(a), hb = __float2bfloat16(b);
        float fa = __bfloat162float(ha), fb = __bfloat162float(hb);
        __nv_bfloat162 hp; hp.x = ha; hp.y = hb;
        H[j] = *(u32*)&hp;
        __nv_bfloat162 lp = __floats2bfloat162_rn(a - fa, b - fb);
        L[j] = *(u32*)&lp;
    }
    u32 off = (u32)r * 256 + (u32)((slot ^ (r & 7)) << 4);
    *(uint4*)(hi + off) = make_uint4(H[0], H[1], H[2], H[3]);
    *(uint4*)(lo + off) = make_uint4(L[0], L[1], L[2], L[3]);
}

// GEMM over K=64 where BOTH operands are stored [k:64 rows][mn:128 cols], trans-ldsm.
__device__ __forceinline__ void warp_gemm_tt(u32 ah, u32 al, u32 bh, u32 bl,
                                             int lane, int m0, int n0,
                                             float acc[2][4][4])
{
    int rkA = (lane & 7) + ((lane >> 4) << 3);
    int slA = (lane >> 3) & 1;
    int rkB = (lane & 7) + (((lane >> 3) & 1) << 3);
    int slB = lane >> 4;
#pragma unroll
    for (int ks = 0; ks < 4; ks++) {
        u32 AH[2][4], AL[2][4], BH[2][4], BL[2][4];
#pragma unroll
        for (int mf = 0; mf < 2; mf++) {
            int row = ks * 16 + rkA;
            int slot = (m0 >> 3) + 2 * mf + slA;
            u32 ad = (u32)row * 256 + (u32)((slot ^ (row & 7)) << 4);
            ldsm4t(ah + ad, AH[mf]);
            ldsm4t(al + ad, AL[mf]);
        }
#pragma unroll
        for (int nb = 0; nb < 2; nb++) {
            int row = ks * 16 + rkB;
            int slot = (n0 >> 3) + 2 * nb + slB;
            u32 ad = (u32)row * 256 + (u32)((slot ^ (row & 7)) << 4);
            ldsm4t(bh + ad, BH[nb]);
            ldsm4t(bl + ad, BL[nb]);
        }
#pragma unroll
        for (int mf = 0; mf < 2; mf++)
#pragma unroll
            for (int nh = 0; nh < 2; nh++)
#pragma unroll
                for (int no = 0; no < 2; no++) {
                    float* d = acc[mf][nh * 2 + no];
                    mmabf(d, AH[mf], BH[nh][2 * no], BH[nh][2 * no + 1]);
                    mmabf(d, AH[mf], BL[nh][2 * no], BL[nh][2 * no + 1]);
                    mmabf(d, AL[mf], BH[nh][2 * no], BH[nh][2 * no + 1]);
                }
    }
}

// GEMM over K=64: A non-trans [m:128][k:64], B trans [k:64][n:128].
__device__ __forceinline__ void warp_gemm_nt(u32 ah, u32 al, u32 bh, u32 bl,
                                             int lane, int m0, int n0,
                                             float acc[2][4][4])
{
    int rA = lane & 15, hi16 = lane >> 4;
    int rowA[2] = {m0 + rA, m0 + 16 + rA};
    int rkB = (lane & 7) + (((lane >> 3) & 1) << 3);
    int slB = lane >> 4;
#pragma unroll
    for (int ks = 0; ks < 4; ks++) {
        u32 AH[2][4], AL[2][4], BH[2][4], BL[2][4];
#pragma unroll
        for (int f = 0; f < 2; f++) {
            u32 sa = (u32)rowA[f] * 128 + (u32)((((ks << 1) + hi16) ^ (rowA[f] & 7)) << 4);
            ldsm4(ah + sa, AH[f]);
            ldsm4(al + sa, AL[f]);
        }
#pragma unroll
        for (int nb = 0; nb < 2; nb++) {
            int row = ks * 16 + rkB;
            int slot = (n0 >> 3) + 2 * nb + slB;
            u32 ad = (u32)row * 256 + (u32)((slot ^ (row & 7)) << 4);
            ldsm4t(bh + ad, BH[nb]);
            ldsm4t(bl + ad, BL[nb]);
        }
#pragma unroll
        for (int mf = 0; mf < 2; mf++)
#pragma unroll
            for (int nh = 0; nh < 2; nh++)
#pragma unroll
                for (int no = 0; no < 2; no++) {
                    float* d = acc[mf][nh * 2 + no];
                    mmabf(d, AH[mf], BH[nh][2 * no], BH[nh][2 * no + 1]);
                    mmabf(d, AH[mf], BL[nh][2 * no], BL[nh][2 * no + 1]);
                    mmabf(d, AL[mf], BH[nh][2 * no], BH[nh][2 * no + 1]);
                }
    }
}

// ---------------- K0: per-batch q split + s1 ----------------
__global__ __launch_bounds__(512) void k0_prep(
    const float* __restrict__ q_g, const float* __restrict__ wq)
{
    __shared__ float red[32 * 128];
    int tid = threadIdx.x, b = blockIdx.x;
    int sx = tid & 15;
    float s1p[8] = {0, 0, 0, 0, 0, 0, 0, 0};
    char* dhB = g_qhi + b * 32768;
    char* dlB = g_qlo + b * 32768;
#pragma unroll
    for (int it = 0; it < 4; it++) {
        int i = tid + it * 512;
        int h = i >> 4;
        const float* pq = &q_g[((size_t)b * Hn + h) * Qn + sx * 8];
        float4 v0 = *(const float4*)pq, v1 = *(const float4*)(pq + 4);
        float f[8] = {v0.x, v0.y, v0.z, v0.w, v1.x, v1.y, v1.z, v1.w};
        float wqv = __ldg(&wq[h]);
#pragma unroll
        for (int j = 0; j < 8; j++) s1p[j] += f[j] * wqv;
        split8(dhB + (h >> 6) * 16384, dlB + (h >> 6) * 16384, h & 63, sx, f);
    }
    int k = tid >> 4;
#pragma unroll
    for (int j = 0; j < 8; j++) red[k * 128 + sx * 8 + j] = s1p[j];
    __syncthreads();
    if (tid < 128) {
        float s = 0.f;
#pragma unroll
        for (int w = 0; w < 32; w++) s += red[w * 128 + tid];
        g_s1[b * Qn + tid] = s;
    }
}

// ---------------- K1: A = c*wcq (fresh), B = precomputed q tiles ------------
// smem: Ahi 0, Alo 16384, Bhi 32768, Blo 49152 (tiles [64h][128] bf16),
//       s0s 65536, s1s 66048, qms 66560, cms 67072, red1 67584(8KB), red2 75776(8KB)
#define K1_SMEM 83968

__global__ __launch_bounds__(512, 2) void k1_score(
    const float* __restrict__ c_g,
    const float* __restrict__ cmask, const float* __restrict__ qmask,
    const float* __restrict__ wc, const float* __restrict__ wcq,
    const float* __restrict__ bias)
{
    extern __shared__ __align__(256) char smem[];
    u32 sb = smem_u32(smem);
    float* s0s  = (float*)(smem + 65536);
    float* s1s  = (float*)(smem + 66048);
    float* qms  = (float*)(smem + 66560);
    float* cms  = (float*)(smem + 67072);
    float* red1 = (float*)(smem + 67584);   // [16][128]
    float* red2 = (float*)(smem + 75776);   // [16][128]
    int tid = threadIdx.x, lane = tid & 31, wid = tid >> 5;
    int b = blockIdx.y, ct = blockIdx.x, c0 = ct * 128;
    float biasv = bias[0];

    for (int i = tid; i < 2048; i += 512) red1[i] = 0.f;
    if (tid < 128) qms[tid] = qmask[b * Qn + tid];
    else if (tid < 256) cms[tid - 128] = cmask[b * Cn + c0 + tid - 128];
    else if (tid < 384) s1s[tid - 256] = g_s1[b * Qn + tid - 256];

    float acc[2][4][4];
#pragma unroll
    for (int i = 0; i < 2; i++)
#pragma unroll
        for (int j = 0; j < 4; j++)
#pragma unroll
            for (int k = 0; k < 4; k++) acc[i][j][k] = 0.f;

    int m0 = (wid >> 2) * 32, n0 = (wid & 3) * 32;
    int sx0 = tid & 15;

#pragma unroll
    for (int kc = 0; kc < 2; kc++) {
        __syncthreads();
        // B fill: straight copy of precomputed bf16 q tiles (16KB hi + 16KB lo)
        const uint4* srcH = (const uint4*)(g_qhi + b * 32768 + kc * 16384);
        const uint4* srcL = (const uint4*)(g_qlo + b * 32768 + kc * 16384);
#pragma unroll
        for (int it = 0; it < 2; it++) {
            int i = tid + it * 512;
            ((uint4*)(smem + 32768))[i] = srcH[i];
            ((uint4*)(smem + 49152))[i] = srcL[i];
        }
        // A fill: read c, s0 partial from raw, scale by wcq, split
        float s0p[8] = {0, 0, 0, 0, 0, 0, 0, 0};
#pragma unroll
        for (int it = 0; it < 2; it++) {
            int i = tid + it * 512;
            int hl = i >> 4, sx = i & 15;
            int h = kc * 64 + hl;
            const float* pc = &c_g[((size_t)b * Hn + h) * Cn + c0 + sx * 8];
            float4 v0 = *(const float4*)pc, v1 = *(const float4*)(pc + 4);
            float f[8] = {v0.x, v0.y, v0.z, v0.w, v1.x, v1.y, v1.z, v1.w};
            float wcv = __ldg(&wc[h]), wcqv = __ldg(&wcq[h]);
#pragma unroll
            for (int j = 0; j < 8; j++) { s0p[j] += f[j] * wcv; f[j] *= wcqv; }
            split8(smem, smem + 16384, hl, sx, f);
        }
#pragma unroll
        for (int j = 0; j < 8; j++)
            s0p[j] += __shfl_xor_sync(~0u, s0p[j], 16);
        if (lane < 16) {
#pragma unroll
            for (int j = 0; j < 8; j++)
                red1[wid * 128 + sx0 * 8 + j] += s0p[j];
        }
        __syncthreads();
        warp_gemm_tt(sb, sb + 16384, sb + 32768, sb + 49152, lane, m0, n0, acc);
    }
    __syncthreads();
    if (tid < 128) {
        float a = 0.f;
#pragma unroll
        for (int w = 0; w < 16; w++) a += red1[w * 128 + tid];
        s0s[tid] = a + biasv;
    }
    __syncthreads();

    int lr = lane >> 2, lc2 = (lane & 3) * 2;

    // finalize S: acc += s0[row] + s1[col]
#pragma unroll
    for (int mf = 0; mf < 2; mf++) {
        int r0 = m0 + mf * 16 + lr, r1 = r0 + 8;
        float s0a = s0s[r0], s0b = s0s[r1];
#pragma unroll
        for (int nf = 0; nf < 4; nf++) {
            int col = n0 + nf * 8 + lc2;
            float s1a = s1s[col], s1b = s1s[col + 1];
            acc[mf][nf][0] += s0a + s1a;
            acc[mf][nf][1] += s0a + s1b;
            acc[mf][nf][2] += s0b + s1a;
            acc[mf][nf][3] += s0b + s1b;
        }
    }

    // write S [c][q]
#pragma unroll
    for (int mf = 0; mf < 2; mf++) {
        int r0 = m0 + mf * 16 + lr, r1 = r0 + 8;
#pragma unroll
        for (int nf = 0; nf < 4; nf++) {
            int col = n0 + nf * 8 + lc2;
            *(float2*)&g_S[((size_t)b * Cn + c0 + r0) * Qn + col] =
                make_float2(acc[mf][nf][0], acc[mf][nf][1]);
            *(float2*)&g_S[((size_t)b * Cn + c0 + r1) * Qn + col] =
                make_float2(acc[mf][nf][2], acc[mf][nf][3]);
        }
    }

    // masks
    bool qm0[4], qm1[4];
#pragma unroll
    for (int nf = 0; nf < 4; nf++) {
        qm0[nf] = qms[n0 + nf * 8 + lc2] > 0.f;
        qm1[nf] = qms[n0 + nf * 8 + lc2 + 1] > 0.f;
    }
    bool cmv[2][2];
#pragma unroll
    for (int mf = 0; mf < 2; mf++) {
        cmv[mf][0] = cms[m0 + mf * 16 + lr] > 0.f;
        cmv[mf][1] = cms[m0 + mf * 16 + 8 + lr] > 0.f;
    }

    // ---- row stats ----
    float rmx[2][2];
#pragma unroll
    for (int mf = 0; mf < 2; mf++) { rmx[mf][0] = -1e30f; rmx[mf][1] = -1e30f; }
#pragma unroll
    for (int mf = 0; mf < 2; mf++)
#pragma unroll
        for (int nf = 0; nf < 4; nf++) {
            if (qm0[nf]) {
                rmx[mf][0] = fmaxf(rmx[mf][0], acc[mf][nf][0]);
                rmx[mf][1] = fmaxf(rmx[mf][1], acc[mf][nf][2]);
            }
            if (qm1[nf]) {
                rmx[mf][0] = fmaxf(rmx[mf][0], acc[mf][nf][1]);
                rmx[mf][1] = fmaxf(rmx[mf][1], acc[mf][nf][3]);
            }
        }
#pragma unroll
    for (int mf = 0; mf < 2; mf++)
#pragma unroll
        for (int h = 0; h < 2; h++) {
            rmx[mf][h] = fmaxf(rmx[mf][h], __shfl_xor_sync(~0u, rmx[mf][h], 1));
            rmx[mf][h] = fmaxf(rmx[mf][h], __shfl_xor_sync(~0u, rmx[mf][h], 2));
        }
    if ((lane & 3) == 0)
#pragma unroll
        for (int mf = 0; mf < 2; mf++)
#pragma unroll
            for (int h = 0; h < 2; h++)
                red1[(wid & 3) * 128 + m0 + mf * 16 + h * 8 + lr] = rmx[mf][h];
    __syncthreads();

    float rowMv[2][2];
#pragma unroll
    for (int mf = 0; mf < 2; mf++)
#pragma unroll
        for (int h = 0; h < 2; h++) {
            int r = m0 + mf * 16 + h * 8 + lr;
            float m = red1[r];
#pragma unroll
            for (int g = 1; g < 4; g++) m = fmaxf(m, red1[g * 128 + r]);
            rowMv[mf][h] = m;
        }
    float rzz[2][2] = {{0.f, 0.f}, {0.f, 0.f}};
#pragma unroll
    for (int mf = 0; mf < 2; mf++)
#pragma unroll
        for (int nf = 0; nf < 4; nf++) {
            if (qm0[nf]) {
                rzz[mf][0] += __expf(acc[mf][nf][0] - rowMv[mf][0]);
                rzz[mf][1] += __expf(acc[mf][nf][2] - rowMv[mf][1]);
            }
            if (qm1[nf]) {
                rzz[mf][0] += __expf(acc[mf][nf][1] - rowMv[mf][0]);
                rzz[mf][1] += __expf(acc[mf][nf][3] - rowMv[mf][1]);
            }
        }
#pragma unroll
    for (int mf = 0; mf < 2; mf++)
#pragma unroll
        for (int h = 0; h < 2; h++) {
            rzz[mf][h] += __shfl_xor_sync(~0u, rzz[mf][h], 1);
            rzz[mf][h] += __shfl_xor_sync(~0u, rzz[mf][h], 2);
        }
    if ((lane & 3) == 0)
#pragma unroll
        for (int mf = 0; mf < 2; mf++)
#pragma unroll
            for (int h = 0; h < 2; h++)
                red2[(wid & 3) * 128 + m0 + mf * 16 + h * 8 + lr] = rzz[mf][h];
    __syncthreads();

    if ((wid & 3) == 0 && (lane & 3) == 0) {
#pragma unroll
        for (int mf = 0; mf < 2; mf++)
#pragma unroll
            for (int h = 0; h < 2; h++) {
                int r = m0 + mf * 16 + h * 8 + lr;
                float z = red2[r] + red2[128 + r] + red2[256 + r] + red2[384 + r];
                g_rowM[b * Cn + c0 + r] = rowMv[mf][h];
                g_rowZ[b * Cn + c0 + r] = z;
            }
    }
    __syncthreads();

    // ---- column partial stats ----
    float cmx[4][2];
#pragma unroll
    for (int nf = 0; nf < 4; nf++) { cmx[nf][0] = -1e30f; cmx[nf][1] = -1e30f; }
#pragma unroll
    for (int mf = 0; mf < 2; mf++)
#pragma unroll
        for (int nf = 0; nf < 4; nf++) {
            if (cmv[mf][0]) {
                cmx[nf][0] = fmaxf(cmx[nf][0], acc[mf][nf][0]);
                cmx[nf][1] = fmaxf(cmx[nf][1], acc[mf][nf][1]);
            }
            if (cmv[mf][1]) {
                cmx[nf][0] = fmaxf(cmx[nf][0], acc[mf][nf][2]);
                cmx[nf][1] = fmaxf(cmx[nf][1], acc[mf][nf][3]);
            }
        }
#pragma unroll
    for (int nf = 0; nf < 4; nf++)
#pragma unroll
        for (int v = 0; v < 2; v++) {
            cmx[nf][v] = fmaxf(cmx[nf][v], __shfl_xor_sync(~0u, cmx[nf][v], 4));
            cmx[nf][v] = fmaxf(cmx[nf][v], __shfl_xor_sync(~0u, cmx[nf][v], 8));
            cmx[nf][v] = fmaxf(cmx[nf][v], __shfl_xor_sync(~0u, cmx[nf][v], 16));
        }
    if (lr == 0)
#pragma unroll
        for (int nf = 0; nf < 4; nf++) {
            red1[(wid >> 2) * 128 + n0 + nf * 8 + lc2]     = cmx[nf][0];
            red1[(wid >> 2) * 128 + n0 + nf * 8 + lc2 + 1] = cmx[nf][1];
        }
    __syncthreads();

    float pMv[4][2];
#pragma unroll
    for (int nf = 0; nf < 4; nf++)
#pragma unroll
        for (int v = 0; v < 2; v++) {
            int col = n0 + nf * 8 + lc2 + v;
            float m = red1[col];
#pragma unroll
            for (int g = 1; g < 4; g++) m = fmaxf(m, red1[g * 128 + col]);
            pMv[nf][v] = m;
        }
    float czz[4][2] = {{0,0},{0,0},{0,0},{0,0}};
#pragma unroll
    for (int nf = 0; nf < 4; nf++) {
        if (cmv[0][0]) { czz[nf][0] += __expf(acc[0][nf][0] - pMv[nf][0]); czz[nf][1] += __expf(acc[0][nf][1] - pMv[nf][1]); }
        if (cmv[0][1]) { czz[nf][0] += __expf(acc[0][nf][2] - pMv[nf][0]); czz[nf][1] += __expf(acc[0][nf][3] - pMv[nf][1]); }
        if (cmv[1][0]) { czz[nf][0] += __expf(acc[1][nf][0] - pMv[nf][0]); czz[nf][1] += __expf(acc[1][nf][1] - pMv[nf][1]); }
        if (cmv[1][1]) { czz[nf][0] += __expf(acc[1][nf][2] - pMv[nf][0]); czz[nf][1] += __expf(acc[1][nf][3] - pMv[nf][1]); }
    }
#pragma unroll
    for (int nf = 0; nf < 4; nf++)
#pragma unroll
        for (int v = 0; v < 2; v++) {
            czz[nf][v] += __shfl_xor_sync(~0u, czz[nf][v], 4);
            czz[nf][v] += __shfl_xor_sync(~0u, czz[nf][v], 8);
            czz[nf][v] += __shfl_xor_sync(~0u, czz[nf][v], 16);
        }
    if (lr == 0)
#pragma unroll
        for (int nf = 0; nf < 4; nf++) {
            red2[(wid >> 2) * 128 + n0 + nf * 8 + lc2]     = czz[nf][0];
            red2[(wid >> 2) * 128 + n0 + nf * 8 + lc2 + 1] = czz[nf][1];
        }
    __syncthreads();

    if ((wid >> 2) == 0 && lr == 0) {
#pragma unroll
        for (int nf = 0; nf < 4; nf++)
#pragma unroll
            for (int v = 0; v < 2; v++) {
                int col = n0 + nf * 8 + lc2 + v;
                float z = red2[col] + red2[128 + col] + red2[256 + col] + red2[384 + col];
                g_pM[(b * NT + ct) * Qn + col] = pMv[nf][v];
                g_pZ[(b * NT + ct) * Qn + col] = z;
            }
    }
}

// ---------------- K3: qb^T = c · E2^T, split-K over 4 quarters --------------
// smem: Ahi 0 ([128h][64c]), Alo 16384, Ehi 32768 ([64c][128q]), Elo 49152, colMs 65536
#define K3_SMEM 66048

__global__ __launch_bounds__(512, 2) void k3_qb(
    const float* __restrict__ c_g, const float* __restrict__ cmask)
{
    extern __shared__ __align__(256) char smem[];
    u32 sb = smem_u32(smem);
    float* colMs = (float*)(smem + 65536);
    int tid = threadIdx.x, lane = tid & 31, wid = tid >> 5;
    int b = blockIdx.y, quarter = blockIdx.x;

    if (tid < 128) {
        float m = -3.4e38f;
#pragma unroll
        for (int t = 0; t < NT; t++) m = fmaxf(m, g_pM[(b * NT + t) * Qn + tid]);
        colMs[tid] = m;
    }

    float acc[2][4][4];
#pragma unroll
    for (int i = 0; i < 2; i++)
#pragma unroll
        for (int j = 0; j < 4; j++)
#pragma unroll
            for (int k = 0; k < 4; k++) acc[i][j][k] = 0.f;

    int m0 = (wid >> 2) * 32, n0 = (wid & 3) * 32;

    for (int it = 0; it < 4; it++) {
        int c0 = quarter * 256 + it * 64;
        __syncthreads();
        for (int i = tid; i < 1024; i += 512) {
            int r = i >> 3, sx = i & 7;
            const float* pa = &c_g[((size_t)b * Hn + r) * Cn + c0 + sx * 8];
            float4 v0 = *(const float4*)pa, v1 = *(const float4*)(pa + 4);
            float f[8] = {v0.x, v0.y, v0.z, v0.w, v1.x, v1.y, v1.z, v1.w};
            split8_64(smem, smem + 16384, r, sx, f);
        }
        for (int i = tid; i < 1024; i += 512) {
            int cl = i >> 4, sx = i & 15;
            const float* ps = &g_S[((size_t)b * Cn + c0 + cl) * Qn + sx * 8];
            float4 s0 = *(const float4*)ps, s1 = *(const float4*)(ps + 4);
            float f[8] = {s0.x, s0.y, s0.z, s0.w, s1.x, s1.y, s1.z, s1.w};
            bool cmv = __ldg(&cmask[b * Cn + c0 + cl]) > 0.f;
#pragma unroll
            for (int j = 0; j < 8; j++)
                f[j] = cmv ? __expf(f[j] - colMs[sx * 8 + j]) : 0.f;
            split8(smem + 32768, smem + 49152, cl, sx, f);
        }
        __syncthreads();
        warp_gemm_nt(sb, sb + 16384, sb + 32768, sb + 49152, lane, m0, n0, acc);
    }

    int lr = lane >> 2, lc2 = (lane & 3) * 2;
#pragma unroll
    for (int mf = 0; mf < 2; mf++) {
        int h0 = m0 + mf * 16 + lr, h1 = h0 + 8;
#pragma unroll
        for (int nf = 0; nf < 4; nf++) {
            int col = n0 + nf * 8 + lc2;
            *(float2*)&g_qbp4[((size_t)(b * 4 + quarter) * Hn + h0) * Qn + col] =
                make_float2(acc[mf][nf][0], acc[mf][nf][1]);
            *(float2*)&g_qbp4[((size_t)(b * 4 + quarter) * Hn + h1) * Qn + col] =
                make_float2(acc[mf][nf][2], acc[mf][nf][3]);
        }
    }
}

// ---------------- K4: dual GEMM (a, bb) in one pass; assemble output --------
#define K4_SMEM 198656

__global__ __launch_bounds__(512) void k4_out(
    const float* __restrict__ c_g,
    const float* __restrict__ qmask, float* __restrict__ out)
{
    extern __shared__ __align__(256) char smem[];
    u32 sb = smem_u32(smem);
    float* rms = (float*)(smem + 196608);
    float* qms = (float*)(smem + 197120);
    float* rzs = (float*)(smem + 197632);
    float* rcz = (float*)(smem + 198144);
    int tid = threadIdx.x, lane = tid & 31, wid = tid >> 5;
    int b = blockIdx.y, ct = blockIdx.x, c0 = ct * 128;

    if (tid < 128) rms[tid] = g_rowM[b * Cn + c0 + tid];
    else if (tid < 256) qms[tid - 128] = qmask[b * Qn + tid - 128];
    else if (tid < 384) {
        float z = g_rowZ[b * Cn + c0 + tid - 256];
        rzs[tid - 256] = (z > 0.f) ? 1.f / z : 0.f;
    } else {
        int qq = tid - 384;
        float m = -3.4e38f;
#pragma unroll
        for (int t = 0; t < NT; t++) m = fmaxf(m, g_pM[(b * NT + t) * Qn + qq]);
        float z = 0.f;
#pragma unroll
        for (int t = 0; t < NT; t++)
            z += g_pZ[(b * NT + t) * Qn + qq] * __expf(g_pM[(b * NT + t) * Qn + qq] - m);
        rcz[qq] = (z > 0.f) ? 1.f / z : 0.f;
    }

    // Q fill: straight copy of precomputed bf16 q tiles (32KB hi + 32KB lo)
    {
        const uint4* srcH = (const uint4*)(g_qhi + b * 32768);
        const uint4* srcL = (const uint4*)(g_qlo + b * 32768);
#pragma unroll
        for (int it = 0; it < 4; it++) {
            int i = tid + it * 512;
            ((uint4*)(smem + 65536))[i] = srcH[i];
            ((uint4*)(smem + 98304))[i] = srcL[i];
        }
    }
    __syncthreads();

    for (int i = tid; i < 2048; i += 512) {
        int r = i >> 4, sx = i & 15;
        const float* ps = &g_S[((size_t)b * Cn + c0 + r) * Qn + sx * 8];
        float4 s0 = *(const float4*)ps, s1 = *(const float4*)(ps + 4);
        float fe[8] = {s0.x, s0.y, s0.z, s0.w, s1.x, s1.y, s1.z, s1.w};
        float rm = rms[r];
#pragma unroll
        for (int j = 0; j < 8; j++)
            fe[j] = (qms[sx * 8 + j] > 0.f) ? __expf(fe[j] - rm) : 0.f;
        split8(smem, smem + 32768, r, sx, fe);
        const float* p0 = &g_qbp4[((size_t)(b * 4) * Hn + r) * Qn + sx * 8];
        const size_t PS = (size_t)Hn * Qn;
        float fp[8] = {0, 0, 0, 0, 0, 0, 0, 0};
#pragma unroll
        for (int t = 0; t < 4; t++) {
            float4 a0 = *(const float4*)(p0 + t * PS);
            float4 a1 = *(const float4*)(p0 + t * PS + 4);
            fp[0] += a0.x; fp[1] += a0.y; fp[2] += a0.z; fp[3] += a0.w;
            fp[4] += a1.x; fp[5] += a1.y; fp[6] += a1.z; fp[7] += a1.w;
        }
#pragma unroll
        for (int j = 0; j < 8; j++) fp[j] *= rcz[sx * 8 + j];
        split8(smem + 131072, smem + 163840, r, sx, fp);
    }
    __syncthreads();

    int m0 = (wid >> 2) * 32, n0 = (wid & 3) * 32;
    int lr = lane >> 2, lc = (lane & 3) * 2;

    float accA[2][4][4], accB[2][4][4];
#pragma unroll
    for (int i = 0; i < 2; i++)
#pragma unroll
        for (int j = 0; j < 4; j++)
#pragma unroll
            for (int k = 0; k < 4; k++) { accA[i][j][k] = 0.f; accB[i][j][k] = 0.f; }

    {
        u32 eh = sb, el = sb + 32768, qh = sb + 65536, ql = sb + 98304;
        u32 ph = sb + 131072, pl = sb + 163840;
        int rA = lane & 15, hi16 = lane >> 4;
        int rBl = (lane & 7) + ((lane >> 4) << 3);
        int kh = (lane >> 3) & 1;
        int rowA[2] = {m0 + rA, m0 + 16 + rA};
        int rowB[2] = {n0 + rBl, n0 + 16 + rBl};
#pragma unroll
        for (int ks = 0; ks < 8; ks++) {
            u32 AH[2][4], AL[2][4];
#pragma unroll
            for (int f = 0; f < 2; f++) {
                u32 sa = (u32)rowA[f] * 256 + (u32)((((ks << 1) + hi16) ^ (rowA[f] & 7)) << 4);
                ldsm4(eh + sa, AH[f]);
                ldsm4(el + sa, AL[f]);
            }
#pragma unroll
            for (int nh = 0; nh < 2; nh++) {
                u32 QH[4], QL[4], PH[4], PL[4];
                u32 sbo = (u32)rowB[nh] * 256 + (u32)((((ks << 1) + kh) ^ (rowB[nh] & 7)) << 4);
                ldsm4(qh + sbo, QH);
                ldsm4(ql + sbo, QL);
                ldsm4(ph + sbo, PH);
                ldsm4(pl + sbo, PL);
#pragma unroll
                for (int mf = 0; mf < 2; mf++)
#pragma unroll
                    for (int no = 0; no < 2; no++) {
                        float* dA = accA[mf][nh * 2 + no];
                        mmabf(dA, AH[mf], QH[2 * no], QH[2 * no + 1]);
                        mmabf(dA, AH[mf], QL[2 * no], QL[2 * no + 1]);
                        mmabf(dA, AL[mf], QH[2 * no], QH[2 * no + 1]);
                        float* dB = accB[mf][nh * 2 + no];
                        mmabf(dB, AH[mf], PH[2 * no], PH[2 * no + 1]);
                        mmabf(dB, AH[mf], PL[2 * no], PL[2 * no + 1]);
                        mmabf(dB, AL[mf], PH[2 * no], PH[2 * no + 1]);
                    }
            }
        }
    }
    __syncthreads();

    float* StA = (float*)(smem + 65536);
    float* StB = (float*)smem;
#pragma unroll
    for (int mf = 0; mf < 2; mf++) {
        int cl0 = m0 + mf * 16 + lr, cl1 = cl0 + 8;
        float rz0 = rzs[cl0], rz1 = rzs[cl1];
#pragma unroll
        for (int nf = 0; nf < 4; nf++) {
            int h = n0 + nf * 8 + lc;
            StA[(h << 7) + ((cl0 ^ h) & 127)]             = accA[mf][nf][0] * rz0;
            StA[((h + 1) << 7) + ((cl0 ^ (h + 1)) & 127)] = accA[mf][nf][1] * rz0;
            StA[(h << 7) + ((cl1 ^ h) & 127)]             = accA[mf][nf][2] * rz1;
            StA[((h + 1) << 7) + ((cl1 ^ (h + 1)) & 127)] = accA[mf][nf][3] * rz1;
            StB[(h << 7) + ((cl0 ^ h) & 127)]             = accB[mf][nf][0] * rz0;
            StB[((h + 1) << 7) + ((cl0 ^ (h + 1)) & 127)] = accB[mf][nf][1] * rz0;
            StB[(h << 7) + ((cl1 ^ h) & 127)]             = accB[mf][nf][2] * rz1;
            StB[((h + 1) << 7) + ((cl1 ^ (h + 1)) & 127)] = accB[mf][nf][3] * rz1;
        }
    }
    __syncthreads();

    const size_t HC = (size_t)Hn * Cn;
    for (int i = tid; i < 16384; i += 512) {
        int h = i >> 7, cc = i & 127;
        float a  = StA[(h << 7) + ((cc ^ h) & 127)];
        float bb = StB[(h << 7) + ((cc ^ h) & 127)];
        float cv = c_g[((size_t)b * Hn + h) * Cn + c0 + cc];
        size_t o = (size_t)b * 4 * HC + (size_t)h * Cn + c0 + cc;
        out[o]          = cv;
        out[o + HC]     = a;
        out[o + 2 * HC] = cv * a;
        out[o + 3 * HC] = cv * bb;
    }
}

// ---------------- launch ----------------
extern "C" void kernel_launch(void* const* d_in, const int* in_sizes, int n_in,
                              void* d_out, int out_size)
{
    const float* c     = (const float*)d_in[0];
    const float* q     = (const float*)d_in[1];
    const float* cmask = (const float*)d_in[2];
    const float* qmask = (const float*)d_in[3];
    const float* wc    = (const float*)d_in[4];
    const float* wq    = (const float*)d_in[5];
    const float* wcq   = (const float*)d_in[6];
    const float* bias  = (const float*)d_in[7];
    float* out = (float*)d_out;

    cudaFuncSetAttribute(k1_score, cudaFuncAttributeMaxDynamicSharedMemorySize, K1_SMEM);
    cudaFuncSetAttribute(k3_qb,    cudaFuncAttributeMaxDynamicSharedMemorySize, K3_SMEM);
    cudaFuncSetAttribute(k4_out,   cudaFuncAttributeMaxDynamicSharedMemorySize, K4_SMEM);

    k0_prep<<<Bn, 512>>>(q, wq);
    k1_score<<<dim3(NT, Bn), 512, K1_SMEM>>>(c, cmask, qmask, wc, wcq, bias);
    k3_qb<<<dim3(4, Bn), 512, K3_SMEM>>>(c, cmask);
    k4_out<<<dim3(NT, Bn), 512, K4_SMEM>>>(c, qmask, out);
}

// round 14
// speedup vs baseline: 1.3170x; 1.0110x over previous
#include <cuda_runtime.h>
#include <cuda_bf16.h>

#define Bn 64
#define Hn 128
#define Cn 1024
#define Qn 128
#define NT 8

typedef unsigned int u32;

// ---------------- scratch ----------------
__device__ float g_S  [Bn * Cn * Qn];
__device__ float g_rowM[Bn * Cn];
__device__ float g_rowZ[Bn * Cn];
__device__ float g_pM [Bn * NT * Qn];
__device__ float g_pZ [Bn * NT * Qn];
__device__ float g_qbp4[Bn * 4 * Hn * Qn];
__device__ char  g_qhi[Bn * 32768];   // q bf16-hi tiles, smem byte-layout [h][q]
__device__ char  g_qlo[Bn * 32768];
__device__ char  g_phi[Bn * 32768];   // qb^T bf16-hi tiles (normalized)
__device__ char  g_plo[Bn * 32768];
__device__ float g_s1 [Bn * Qn];

// ---------------- helpers ----------------
__device__ __forceinline__ u32 smem_u32(const void* p) {
    u32 a;
    asm("{ .reg .u64 t; cvta.to.shared.u64 t, %1; cvt.u32.u64 %0, t; }" : "=r"(a) : "l"(p));
    return a;
}
__device__ __forceinline__ void ldsm4(u32 a, u32* r) {
    asm volatile("ldmatrix.sync.aligned.m8n8.x4.shared.b16 {%0,%1,%2,%3}, [%4];"
        : "=r"(r[0]), "=r"(r[1]), "=r"(r[2]), "=r"(r[3]) : "r"(a));
}
__device__ __forceinline__ void ldsm4t(u32 a, u32* r) {
    asm volatile("ldmatrix.sync.aligned.m8n8.x4.trans.shared.b16 {%0,%1,%2,%3}, [%4];"
        : "=r"(r[0]), "=r"(r[1]), "=r"(r[2]), "=r"(r[3]) : "r"(a));
}
__device__ __forceinline__ void mmabf(float* d, const u32* a, u32 b0, u32 b1) {
    asm volatile("mma.sync.aligned.m16n8k16.row.col.f32.bf16.bf16.f32 "
        "{%0,%1,%2,%3},{%4,%5,%6,%7},{%8,%9},{%0,%1,%2,%3};"
        : "+f"(d[0]), "+f"(d[1]), "+f"(d[2]), "+f"(d[3])
        : "r"(a[0]), "r"(a[1]), "r"(a[2]), "r"(a[3]), "r"(b0), "r"(b1));
}

// split 8 fp32 -> bf16 hi/lo, 16B store into 64-col tile (row stride 128B)
__device__ __forceinline__ void split8_64(char* hi, char* lo, int r, int slot,
                                          const float* f)
{
    u32 H[4], L[4];
#pragma unroll
    for (int j = 0; j < 4; j++) {
        float a = f[2 * j], b = f[2 * j + 1];
        __nv_bfloat16 ha = __float2bfloat16(a), hb = __float2bfloat16(b);
        float fa = __bfloat162float(ha), fb = __bfloat162float(hb);
        __nv_bfloat162 hp; hp.x = ha; hp.y = hb;
        H[j] = *(u32*)&hp;
        __nv_bfloat162 lp = __floats2bfloat162_rn(a - fa, b - fb);
        L[j] = *(u32*)&lp;
    }
    u32 off = (u32)r * 128 + (u32)((slot ^ (r & 7)) << 4);
    *(uint4*)(hi + off) = make_uint4(H[0], H[1], H[2], H[3]);
    *(uint4*)(lo + off) = make_uint4(L[0], L[1], L[2], L[3]);
}

// split 8 fp32 -> bf16 hi/lo, 16B store into 128-col tile (row stride 256B)
__device__ __forceinline__ void split8(char* hi, char* lo, int r, int slot,
                                       const float* f)
{
    u32 H[4], L[4];
#pragma unroll
    for (int j = 0; j < 4; j++) {
        float a = f[2 * j], b = f[2 * j + 1];
        __nv_bfloat16 ha = __float2bfloat16(a), hb = __float2bfloat16(b);
        float fa = __bfloat162float(ha), fb = __bfloat162float(hb);
        __nv_bfloat162 hp; hp.x = ha; hp.y = hb;
        H[j] = *(u32*)&hp;
        __nv_bfloat162 lp = __floats2bfloat162_rn(a - fa, b - fb);
        L[j] = *(u32*)&lp;
    }
    u32 off = (u32)r * 256 + (u32)((slot ^ (r & 7)) << 4);
    *(uint4*)(hi + off) = make_uint4(H[0], H[1], H[2], H[3]);
    *(uint4*)(lo + off) = make_uint4(L[0], L[1], L[2], L[3]);
}

// GEMM over K=64 where BOTH operands are stored [k:64 rows][mn:128 cols], trans-ldsm.
__device__ __forceinline__ void warp_gemm_tt(u32 ah, u32 al, u32 bh, u32 bl,
                                             int lane, int m0, int n0,
                                             float acc[2][4][4])
{
    int rkA = (lane & 7) + ((lane >> 4) << 3);
    int slA = (lane >> 3) & 1;
    int rkB = (lane & 7) + (((lane >> 3) & 1) << 3);
    int slB = lane >> 4;
#pragma unroll
    for (int ks = 0; ks < 4; ks++) {
        u32 AH[2][4], AL[2][4], BH[2][4], BL[2][4];
#pragma unroll
        for (int mf = 0; mf < 2; mf++) {
            int row = ks * 16 + rkA;
            int slot = (m0 >> 3) + 2 * mf + slA;
            u32 ad = (u32)row * 256 + (u32)((slot ^ (row & 7)) << 4);
            ldsm4t(ah + ad, AH[mf]);
            ldsm4t(al + ad, AL[mf]);
        }
#pragma unroll
        for (int nb = 0; nb < 2; nb++) {
            int row = ks * 16 + rkB;
            int slot = (n0 >> 3) + 2 * nb + slB;
            u32 ad = (u32)row * 256 + (u32)((slot ^ (row & 7)) << 4);
            ldsm4t(bh + ad, BH[nb]);
            ldsm4t(bl + ad, BL[nb]);
        }
#pragma unroll
        for (int mf = 0; mf < 2; mf++)
#pragma unroll
            for (int nh = 0; nh < 2; nh++)
#pragma unroll
                for (int no = 0; no < 2; no++) {
                    float* d = acc[mf][nh * 2 + no];
                    mmabf(d, AH[mf], BH[nh][2 * no], BH[nh][2 * no + 1]);
                    mmabf(d, AH[mf], BL[nh][2 * no], BL[nh][2 * no + 1]);
                    mmabf(d, AL[mf], BH[nh][2 * no], BH[nh][2 * no + 1]);
                }
    }
}

// GEMM over K=64: A non-trans [m:128][k:64], B trans [k:64][n:128].
__device__ __forceinline__ void warp_gemm_nt(u32 ah, u32 al, u32 bh, u32 bl,
                                             int lane, int m0, int n0,
                                             float acc[2][4][4])
{
    int rA = lane & 15, hi16 = lane >> 4;
    int rowA[2] = {m0 + rA, m0 + 16 + rA};
    int rkB = (lane & 7) + (((lane >> 3) & 1) << 3);
    int slB = lane >> 4;
#pragma unroll
    for (int ks = 0; ks < 4; ks++) {
        u32 AH[2][4], AL[2][4], BH[2][4], BL[2][4];
#pragma unroll
        for (int f = 0; f < 2; f++) {
            u32 sa = (u32)rowA[f] * 128 + (u32)((((ks << 1) + hi16) ^ (rowA[f] & 7)) << 4);
            ldsm4(ah + sa, AH[f]);
            ldsm4(al + sa, AL[f]);
        }
#pragma unroll
        for (int nb = 0; nb < 2; nb++) {
            int row = ks * 16 + rkB;
            int slot = (n0 >> 3) + 2 * nb + slB;
            u32 ad = (u32)row * 256 + (u32)((slot ^ (row & 7)) << 4);
            ldsm4t(bh + ad, BH[nb]);
            ldsm4t(bl + ad, BL[nb]);
        }
#pragma unroll
        for (int mf = 0; mf < 2; mf++)
#pragma unroll
            for (int nh = 0; nh < 2; nh++)
#pragma unroll
                for (int no = 0; no < 2; no++) {
                    float* d = acc[mf][nh * 2 + no];
                    mmabf(d, AH[mf], BH[nh][2 * no], BH[nh][2 * no + 1]);
                    mmabf(d, AH[mf], BL[nh][2 * no], BL[nh][2 * no + 1]);
                    mmabf(d, AL[mf], BH[nh][2 * no], BH[nh][2 * no + 1]);
                }
    }
}

// ---------------- K0: per-batch q split + s1 ----------------
__global__ __launch_bounds__(512) void k0_prep(
    const float* __restrict__ q_g, const float* __restrict__ wq)
{
    __shared__ float red[32 * 128];
    int tid = threadIdx.x, b = blockIdx.x;
    int sx = tid & 15;
    float s1p[8] = {0, 0, 0, 0, 0, 0, 0, 0};
    char* dhB = g_qhi + b * 32768;
    char* dlB = g_qlo + b * 32768;
#pragma unroll
    for (int it = 0; it < 4; it++) {
        int i = tid + it * 512;
        int h = i >> 4;
        const float* pq = &q_g[((size_t)b * Hn + h) * Qn + sx * 8];
        float4 v0 = *(const float4*)pq, v1 = *(const float4*)(pq + 4);
        float f[8] = {v0.x, v0.y, v0.z, v0.w, v1.x, v1.y, v1.z, v1.w};
        float wqv = __ldg(&wq[h]);
#pragma unroll
        for (int j = 0; j < 8; j++) s1p[j] += f[j] * wqv;
        split8(dhB + (h >> 6) * 16384, dlB + (h >> 6) * 16384, h & 63, sx, f);
    }
    int k = tid >> 4;
#pragma unroll
    for (int j = 0; j < 8; j++) red[k * 128 + sx * 8 + j] = s1p[j];
    __syncthreads();
    if (tid < 128) {
        float s = 0.f;
#pragma unroll
        for (int w = 0; w < 32; w++) s += red[w * 128 + tid];
        g_s1[b * Qn + tid] = s;
    }
}

// ---------------- K1 ----------------
#define K1_SMEM 83968

__global__ __launch_bounds__(512, 2) void k1_score(
    const float* __restrict__ c_g,
    const float* __restrict__ cmask, const float* __restrict__ qmask,
    const float* __restrict__ wc, const float* __restrict__ wcq,
    const float* __restrict__ bias)
{
    extern __shared__ __align__(256) char smem[];
    u32 sb = smem_u32(smem);
    float* s0s  = (float*)(smem + 65536);
    float* s1s  = (float*)(smem + 66048);
    float* qms  = (float*)(smem + 66560);
    float* cms  = (float*)(smem + 67072);
    float* red1 = (float*)(smem + 67584);
    float* red2 = (float*)(smem + 75776);
    int tid = threadIdx.x, lane = tid & 31, wid = tid >> 5;
    int b = blockIdx.y, ct = blockIdx.x, c0 = ct * 128;
    float biasv = bias[0];

    for (int i = tid; i < 2048; i += 512) red1[i] = 0.f;
    if (tid < 128) qms[tid] = qmask[b * Qn + tid];
    else if (tid < 256) cms[tid - 128] = cmask[b * Cn + c0 + tid - 128];
    else if (tid < 384) s1s[tid - 256] = g_s1[b * Qn + tid - 256];

    float acc[2][4][4];
#pragma unroll
    for (int i = 0; i < 2; i++)
#pragma unroll
        for (int j = 0; j < 4; j++)
#pragma unroll
            for (int k = 0; k < 4; k++) acc[i][j][k] = 0.f;

    int m0 = (wid >> 2) * 32, n0 = (wid & 3) * 32;
    int sx0 = tid & 15;

#pragma unroll
    for (int kc = 0; kc < 2; kc++) {
        __syncthreads();
        const uint4* srcH = (const uint4*)(g_qhi + b * 32768 + kc * 16384);
        const uint4* srcL = (const uint4*)(g_qlo + b * 32768 + kc * 16384);
#pragma unroll
        for (int it = 0; it < 2; it++) {
            int i = tid + it * 512;
            ((uint4*)(smem + 32768))[i] = srcH[i];
            ((uint4*)(smem + 49152))[i] = srcL[i];
        }
        float s0p[8] = {0, 0, 0, 0, 0, 0, 0, 0};
#pragma unroll
        for (int it = 0; it < 2; it++) {
            int i = tid + it * 512;
            int hl = i >> 4, sx = i & 15;
            int h = kc * 64 + hl;
            const float* pc = &c_g[((size_t)b * Hn + h) * Cn + c0 + sx * 8];
            float4 v0 = *(const float4*)pc, v1 = *(const float4*)(pc + 4);
            float f[8] = {v0.x, v0.y, v0.z, v0.w, v1.x, v1.y, v1.z, v1.w};
            float wcv = __ldg(&wc[h]), wcqv = __ldg(&wcq[h]);
#pragma unroll
            for (int j = 0; j < 8; j++) { s0p[j] += f[j] * wcv; f[j] *= wcqv; }
            split8(smem, smem + 16384, hl, sx, f);
        }
#pragma unroll
        for (int j = 0; j < 8; j++)
            s0p[j] += __shfl_xor_sync(~0u, s0p[j], 16);
        if (lane < 16) {
#pragma unroll
            for (int j = 0; j < 8; j++)
                red1[wid * 128 + sx0 * 8 + j] += s0p[j];
        }
        __syncthreads();
        warp_gemm_tt(sb, sb + 16384, sb + 32768, sb + 49152, lane, m0, n0, acc);
    }
    __syncthreads();
    if (tid < 128) {
        float a = 0.f;
#pragma unroll
        for (int w = 0; w < 16; w++) a += red1[w * 128 + tid];
        s0s[tid] = a + biasv;
    }
    __syncthreads();

    int lr = lane >> 2, lc2 = (lane & 3) * 2;

#pragma unroll
    for (int mf = 0; mf < 2; mf++) {
        int r0 = m0 + mf * 16 + lr, r1 = r0 + 8;
        float s0a = s0s[r0], s0b = s0s[r1];
#pragma unroll
        for (int nf = 0; nf < 4; nf++) {
            int col = n0 + nf * 8 + lc2;
            float s1a = s1s[col], s1b = s1s[col + 1];
            acc[mf][nf][0] += s0a + s1a;
            acc[mf][nf][1] += s0a + s1b;
            acc[mf][nf][2] += s0b + s1a;
            acc[mf][nf][3] += s0b + s1b;
        }
    }

#pragma unroll
    for (int mf = 0; mf < 2; mf++) {
        int r0 = m0 + mf * 16 + lr, r1 = r0 + 8;
#pragma unroll
        for (int nf = 0; nf < 4; nf++) {
            int col = n0 + nf * 8 + lc2;
            *(float2*)&g_S[((size_t)b * Cn + c0 + r0) * Qn + col] =
                make_float2(acc[mf][nf][0], acc[mf][nf][1]);
            *(float2*)&g_S[((size_t)b * Cn + c0 + r1) * Qn + col] =
                make_float2(acc[mf][nf][2], acc[mf][nf][3]);
        }
    }

    bool qm0[4], qm1[4];
#pragma unroll
    for (int nf = 0; nf < 4; nf++) {
        qm0[nf] = qms[n0 + nf * 8 + lc2] > 0.f;
        qm1[nf] = qms[n0 + nf * 8 + lc2 + 1] > 0.f;
    }
    bool cmv[2][2];
#pragma unroll
    for (int mf = 0; mf < 2; mf++) {
        cmv[mf][0] = cms[m0 + mf * 16 + lr] > 0.f;
        cmv[mf][1] = cms[m0 + mf * 16 + 8 + lr] > 0.f;
    }

    float rmx[2][2];
#pragma unroll
    for (int mf = 0; mf < 2; mf++) { rmx[mf][0] = -1e30f; rmx[mf][1] = -1e30f; }
#pragma unroll
    for (int mf = 0; mf < 2; mf++)
#pragma unroll
        for (int nf = 0; nf < 4; nf++) {
            if (qm0[nf]) {
                rmx[mf][0] = fmaxf(rmx[mf][0], acc[mf][nf][0]);
                rmx[mf][1] = fmaxf(rmx[mf][1], acc[mf][nf][2]);
            }
            if (qm1[nf]) {
                rmx[mf][0] = fmaxf(rmx[mf][0], acc[mf][nf][1]);
                rmx[mf][1] = fmaxf(rmx[mf][1], acc[mf][nf][3]);
            }
        }
#pragma unroll
    for (int mf = 0; mf < 2; mf++)
#pragma unroll
        for (int h = 0; h < 2; h++) {
            rmx[mf][h] = fmaxf(rmx[mf][h], __shfl_xor_sync(~0u, rmx[mf][h], 1));
            rmx[mf][h] = fmaxf(rmx[mf][h], __shfl_xor_sync(~0u, rmx[mf][h], 2));
        }
    if ((lane & 3) == 0)
#pragma unroll
        for (int mf = 0; mf < 2; mf++)
#pragma unroll
            for (int h = 0; h < 2; h++)
                red1[(wid & 3) * 128 + m0 + mf * 16 + h * 8 + lr] = rmx[mf][h];
    __syncthreads();

    float rowMv[2][2];
#pragma unroll
    for (int mf = 0; mf < 2; mf++)
#pragma unroll
        for (int h = 0; h < 2; h++) {
            int r = m0 + mf * 16 + h * 8 + lr;
            float m = red1[r];
#pragma unroll
            for (int g = 1; g < 4; g++) m = fmaxf(m, red1[g * 128 + r]);
            rowMv[mf][h] = m;
        }
    float rzz[2][2] = {{0.f, 0.f}, {0.f, 0.f}};
#pragma unroll
    for (int mf = 0; mf < 2; mf++)
#pragma unroll
        for (int nf = 0; nf < 4; nf++) {
            if (qm0[nf]) {
                rzz[mf][0] += __expf(acc[mf][nf][0] - rowMv[mf][0]);
                rzz[mf][1] += __expf(acc[mf][nf][2] - rowMv[mf][1]);
            }
            if (qm1[nf]) {
                rzz[mf][0] += __expf(acc[mf][nf][1] - rowMv[mf][0]);
                rzz[mf][1] += __expf(acc[mf][nf][3] - rowMv[mf][1]);
            }
        }
#pragma unroll
    for (int mf = 0; mf < 2; mf++)
#pragma unroll
        for (int h = 0; h < 2; h++) {
            rzz[mf][h] += __shfl_xor_sync(~0u, rzz[mf][h], 1);
            rzz[mf][h] += __shfl_xor_sync(~0u, rzz[mf][h], 2);
        }
    if ((lane & 3) == 0)
#pragma unroll
        for (int mf = 0; mf < 2; mf++)
#pragma unroll
            for (int h = 0; h < 2; h++)
                red2[(wid & 3) * 128 + m0 + mf * 16 + h * 8 + lr] = rzz[mf][h];
    __syncthreads();

    if ((wid & 3) == 0 && (lane & 3) == 0) {
#pragma unroll
        for (int mf = 0; mf < 2; mf++)
#pragma unroll
            for (int h = 0; h < 2; h++) {
                int r = m0 + mf * 16 + h * 8 + lr;
                float z = red2[r] + red2[128 + r] + red2[256 + r] + red2[384 + r];
                g_rowM[b * Cn + c0 + r] = rowMv[mf][h];
                g_rowZ[b * Cn + c0 + r] = z;
            }
    }
    __syncthreads();

    float cmx[4][2];
#pragma unroll
    for (int nf = 0; nf < 4; nf++) { cmx[nf][0] = -1e30f; cmx[nf][1] = -1e30f; }
#pragma unroll
    for (int mf = 0; mf < 2; mf++)
#pragma unroll
        for (int nf = 0; nf < 4; nf++) {
            if (cmv[mf][0]) {
                cmx[nf][0] = fmaxf(cmx[nf][0], acc[mf][nf][0]);
                cmx[nf][1] = fmaxf(cmx[nf][1], acc[mf][nf][1]);
            }
            if (cmv[mf][1]) {
                cmx[nf][0] = fmaxf(cmx[nf][0], acc[mf][nf][2]);
                cmx[nf][1] = fmaxf(cmx[nf][1], acc[mf][nf][3]);
            }
        }
#pragma unroll
    for (int nf = 0; nf < 4; nf++)
#pragma unroll
        for (int v = 0; v < 2; v++) {
            cmx[nf][v] = fmaxf(cmx[nf][v], __shfl_xor_sync(~0u, cmx[nf][v], 4));
            cmx[nf][v] = fmaxf(cmx[nf][v], __shfl_xor_sync(~0u, cmx[nf][v], 8));
            cmx[nf][v] = fmaxf(cmx[nf][v], __shfl_xor_sync(~0u, cmx[nf][v], 16));
        }
    if (lr == 0)
#pragma unroll
        for (int nf = 0; nf < 4; nf++) {
            red1[(wid >> 2) * 128 + n0 + nf * 8 + lc2]     = cmx[nf][0];
            red1[(wid >> 2) * 128 + n0 + nf * 8 + lc2 + 1] = cmx[nf][1];
        }
    __syncthreads();

    float pMv[4][2];
#pragma unroll
    for (int nf = 0; nf < 4; nf++)
#pragma unroll
        for (int v = 0; v < 2; v++) {
            int col = n0 + nf * 8 + lc2 + v;
            float m = red1[col];
#pragma unroll
            for (int g = 1; g < 4; g++) m = fmaxf(m, red1[g * 128 + col]);
            pMv[nf][v] = m;
        }
    float czz[4][2] = {{0,0},{0,0},{0,0},{0,0}};
#pragma unroll
    for (int nf = 0; nf < 4; nf++) {
        if (cmv[0][0]) { czz[nf][0] += __expf(acc[0][nf][0] - pMv[nf][0]); czz[nf][1] += __expf(acc[0][nf][1] - pMv[nf][1]); }
        if (cmv[0][1]) { czz[nf][0] += __expf(acc[0][nf][2] - pMv[nf][0]); czz[nf][1] += __expf(acc[0][nf][3] - pMv[nf][1]); }
        if (cmv[1][0]) { czz[nf][0] += __expf(acc[1][nf][0] - pMv[nf][0]); czz[nf][1] += __expf(acc[1][nf][1] - pMv[nf][1]); }
        if (cmv[1][1]) { czz[nf][0] += __expf(acc[1][nf][2] - pMv[nf][0]); czz[nf][1] += __expf(acc[1][nf][3] - pMv[nf][1]); }
    }
#pragma unroll
    for (int nf = 0; nf < 4; nf++)
#pragma unroll
        for (int v = 0; v < 2; v++) {
            czz[nf][v] += __shfl_xor_sync(~0u, czz[nf][v], 4);
            czz[nf][v] += __shfl_xor_sync(~0u, czz[nf][v], 8);
            czz[nf][v] += __shfl_xor_sync(~0u, czz[nf][v], 16);
        }
    if (lr == 0)
#pragma unroll
        for (int nf = 0; nf < 4; nf++) {
            red2[(wid >> 2) * 128 + n0 + nf * 8 + lc2]     = czz[nf][0];
            red2[(wid >> 2) * 128 + n0 + nf * 8 + lc2 + 1] = czz[nf][1];
        }
    __syncthreads();

    if ((wid >> 2) == 0 && lr == 0) {
#pragma unroll
        for (int nf = 0; nf < 4; nf++)
#pragma unroll
            for (int v = 0; v < 2; v++) {
                int col = n0 + nf * 8 + lc2 + v;
                float z = red2[col] + red2[128 + col] + red2[256 + col] + red2[384 + col];
                g_pM[(b * NT + ct) * Qn + col] = pMv[nf][v];
                g_pZ[(b * NT + ct) * Qn + col] = z;
            }
    }
}

// ---------------- K3: qb^T partials ----------------
#define K3_SMEM 66048

__global__ __launch_bounds__(512, 2) void k3_qb(
    const float* __restrict__ c_g, const float* __restrict__ cmask)
{
    extern __shared__ __align__(256) char smem[];
    u32 sb = smem_u32(smem);
    float* colMs = (float*)(smem + 65536);
    int tid = threadIdx.x, lane = tid & 31, wid = tid >> 5;
    int b = blockIdx.y, quarter = blockIdx.x;

    if (tid < 128) {
        float m = -3.4e38f;
#pragma unroll
        for (int t = 0; t < NT; t++) m = fmaxf(m, g_pM[(b * NT + t) * Qn + tid]);
        colMs[tid] = m;
    }

    float acc[2][4][4];
#pragma unroll
    for (int i = 0; i < 2; i++)
#pragma unroll
        for (int j = 0; j < 4; j++)
#pragma unroll
            for (int k = 0; k < 4; k++) acc[i][j][k] = 0.f;

    int m0 = (wid >> 2) * 32, n0 = (wid & 3) * 32;

    for (int it = 0; it < 4; it++) {
        int c0 = quarter * 256 + it * 64;
        __syncthreads();
        for (int i = tid; i < 1024; i += 512) {
            int r = i >> 3, sx = i & 7;
            const float* pa = &c_g[((size_t)b * Hn + r) * Cn + c0 + sx * 8];
            float4 v0 = *(const float4*)pa, v1 = *(const float4*)(pa + 4);
            float f[8] = {v0.x, v0.y, v0.z, v0.w, v1.x, v1.y, v1.z, v1.w};
            split8_64(smem, smem + 16384, r, sx, f);
        }
        for (int i = tid; i < 1024; i += 512) {
            int cl = i >> 4, sx = i & 15;
            const float* ps = &g_S[((size_t)b * Cn + c0 + cl) * Qn + sx * 8];
            float4 s0 = *(const float4*)ps, s1 = *(const float4*)(ps + 4);
            float f[8] = {s0.x, s0.y, s0.z, s0.w, s1.x, s1.y, s1.z, s1.w};
            bool cmv = __ldg(&cmask[b * Cn + c0 + cl]) > 0.f;
#pragma unroll
            for (int j = 0; j < 8; j++)
                f[j] = cmv ? __expf(f[j] - colMs[sx * 8 + j]) : 0.f;
            split8(smem + 32768, smem + 49152, cl, sx, f);
        }
        __syncthreads();
        warp_gemm_nt(sb, sb + 16384, sb + 32768, sb + 49152, lane, m0, n0, acc);
    }

    int lr = lane >> 2, lc2 = (lane & 3) * 2;
#pragma unroll
    for (int mf = 0; mf < 2; mf++) {
        int h0 = m0 + mf * 16 + lr, h1 = h0 + 8;
#pragma unroll
        for (int nf = 0; nf < 4; nf++) {
            int col = n0 + nf * 8 + lc2;
            *(float2*)&g_qbp4[((size_t)(b * 4 + quarter) * Hn + h0) * Qn + col] =
                make_float2(acc[mf][nf][0], acc[mf][nf][1]);
            *(float2*)&g_qbp4[((size_t)(b * 4 + quarter) * Hn + h1) * Qn + col] =
                make_float2(acc[mf][nf][2], acc[mf][nf][3]);
        }
    }
}

// ---------------- K3b: combine partials, normalize, split to bf16 tiles -----
__global__ __launch_bounds__(512) void k3b_comb() {
    __shared__ float rcz[128];
    int tid = threadIdx.x, b = blockIdx.x;
    if (tid < 128) {
        float m = -3.4e38f;
#pragma unroll
        for (int t = 0; t < NT; t++) m = fmaxf(m, g_pM[(b * NT + t) * Qn + tid]);
        float z = 0.f;
#pragma unroll
        for (int t = 0; t < NT; t++)
            z += g_pZ[(b * NT + t) * Qn + tid] * __expf(g_pM[(b * NT + t) * Qn + tid] - m);
        rcz[tid] = (z > 0.f) ? 1.f / z : 0.f;
    }
    __syncthreads();
    char* dhB = g_phi + b * 32768;
    char* dlB = g_plo + b * 32768;
    const size_t PS = (size_t)Hn * Qn;
    int sx = tid & 15;
#pragma unroll
    for (int it = 0; it < 4; it++) {
        int i = tid + it * 512;
        int h = i >> 4;
        const float* p0 = &g_qbp4[((size_t)(b * 4) * Hn + h) * Qn + sx * 8];
        float fp[8] = {0, 0, 0, 0, 0, 0, 0, 0};
#pragma unroll
        for (int t = 0; t < 4; t++) {
            float4 a0 = *(const float4*)(p0 + t * PS);
            float4 a1 = *(const float4*)(p0 + t * PS + 4);
            fp[0] += a0.x; fp[1] += a0.y; fp[2] += a0.z; fp[3] += a0.w;
            fp[4] += a1.x; fp[5] += a1.y; fp[6] += a1.z; fp[7] += a1.w;
        }
#pragma unroll
        for (int j = 0; j < 8; j++) fp[j] *= rcz[sx * 8 + j];
        split8(dhB + (h >> 6) * 16384, dlB + (h >> 6) * 16384, h & 63, sx, fp);
    }
}

// ---------------- K4: dual GEMM; Q and P fills are straight copies ----------
#define K4_SMEM 198656

__global__ __launch_bounds__(512) void k4_out(
    const float* __restrict__ c_g,
    const float* __restrict__ qmask, float* __restrict__ out)
{
    extern __shared__ __align__(256) char smem[];
    u32 sb = smem_u32(smem);
    float* rms = (float*)(smem + 196608);
    float* qms = (float*)(smem + 197120);
    float* rzs = (float*)(smem + 197632);
    int tid = threadIdx.x, lane = tid & 31, wid = tid >> 5;
    int b = blockIdx.y, ct = blockIdx.x, c0 = ct * 128;

    if (tid < 128) rms[tid] = g_rowM[b * Cn + c0 + tid];
    else if (tid < 256) qms[tid - 128] = qmask[b * Qn + tid - 128];
    else if (tid < 384) {
        float z = g_rowZ[b * Cn + c0 + tid - 256];
        rzs[tid - 256] = (z > 0.f) ? 1.f / z : 0.f;
    }

    // Q + P fills: straight copies of precomputed bf16 tiles
    {
        const uint4* qH = (const uint4*)(g_qhi + b * 32768);
        const uint4* qL = (const uint4*)(g_qlo + b * 32768);
        const uint4* pH = (const uint4*)(g_phi + b * 32768);
        const uint4* pL = (const uint4*)(g_plo + b * 32768);
#pragma unroll
        for (int it = 0; it < 4; it++) {
            int i = tid + it * 512;
            ((uint4*)(smem + 65536))[i]  = qH[i];
            ((uint4*)(smem + 98304))[i]  = qL[i];
            ((uint4*)(smem + 131072))[i] = pH[i];
            ((uint4*)(smem + 163840))[i] = pL[i];
        }
    }
    __syncthreads();

    for (int i = tid; i < 2048; i += 512) {
        int r = i >> 4, sx = i & 15;
        const float* ps = &g_S[((size_t)b * Cn + c0 + r) * Qn + sx * 8];
        float4 s0 = *(const float4*)ps, s1 = *(const float4*)(ps + 4);
        float fe[8] = {s0.x, s0.y, s0.z, s0.w, s1.x, s1.y, s1.z, s1.w};
        float rm = rms[r];
#pragma unroll
        for (int j = 0; j < 8; j++)
            fe[j] = (qms[sx * 8 + j] > 0.f) ? __expf(fe[j] - rm) : 0.f;
        split8(smem, smem + 32768, r, sx, fe);
    }
    __syncthreads();

    int m0 = (wid >> 2) * 32, n0 = (wid & 3) * 32;
    int lr = lane >> 2, lc = (lane & 3) * 2;

    float accA[2][4][4], accB[2][4][4];
#pragma unroll
    for (int i = 0; i < 2; i++)
#pragma unroll
        for (int j = 0; j < 4; j++)
#pragma unroll
            for (int k = 0; k < 4; k++) { accA[i][j][k] = 0.f; accB[i][j][k] = 0.f; }

    {
        u32 eh = sb, el = sb + 32768, qh = sb + 65536, ql = sb + 98304;
        u32 ph = sb + 131072, pl = sb + 163840;
        int rA = lane & 15, hi16 = lane >> 4;
        int rBl = (lane & 7) + ((lane >> 4) << 3);
        int kh = (lane >> 3) & 1;
        int rowA[2] = {m0 + rA, m0 + 16 + rA};
        int rowB[2] = {n0 + rBl, n0 + 16 + rBl};
#pragma unroll
        for (int ks = 0; ks < 8; ks++) {
            u32 AH[2][4], AL[2][4];
#pragma unroll
            for (int f = 0; f < 2; f++) {
                u32 sa = (u32)rowA[f] * 256 + (u32)((((ks << 1) + hi16) ^ (rowA[f] & 7)) << 4);
                ldsm4(eh + sa, AH[f]);
                ldsm4(el + sa, AL[f]);
            }
#pragma unroll
            for (int nh = 0; nh < 2; nh++) {
                u32 QH[4], QL[4], PH[4], PL[4];
                u32 sbo = (u32)rowB[nh] * 256 + (u32)((((ks << 1) + kh) ^ (rowB[nh] & 7)) << 4);
                ldsm4(qh + sbo, QH);
                ldsm4(ql + sbo, QL);
                ldsm4(ph + sbo, PH);
                ldsm4(pl + sbo, PL);
#pragma unroll
                for (int mf = 0; mf < 2; mf++)
#pragma unroll
                    for (int no = 0; no < 2; no++) {
                        float* dA = accA[mf][nh * 2 + no];
                        mmabf(dA, AH[mf], QH[2 * no], QH[2 * no + 1]);
                        mmabf(dA, AH[mf], QL[2 * no], QL[2 * no + 1]);
                        mmabf(dA, AL[mf], QH[2 * no], QH[2 * no + 1]);
                        float* dB = accB[mf][nh * 2 + no];
                        mmabf(dB, AH[mf], PH[2 * no], PH[2 * no + 1]);
                        mmabf(dB, AH[mf], PL[2 * no], PL[2 * no + 1]);
                        mmabf(dB, AL[mf], PH[2 * no], PH[2 * no + 1]);
                    }
            }
        }
    }
    __syncthreads();

    float* StA = (float*)(smem + 65536);
    float* StB = (float*)smem;
#pragma unroll
    for (int mf = 0; mf < 2; mf++) {
        int cl0 = m0 + mf * 16 + lr, cl1 = cl0 + 8;
        float rz0 = rzs[cl0], rz1 = rzs[cl1];
#pragma unroll
        for (int nf = 0; nf < 4; nf++) {
            int h = n0 + nf * 8 + lc;
            StA[(h << 7) + ((cl0 ^ h) & 127)]             = accA[mf][nf][0] * rz0;
            StA[((h + 1) << 7) + ((cl0 ^ (h + 1)) & 127)] = accA[mf][nf][1] * rz0;
            StA[(h << 7) + ((cl1 ^ h) & 127)]             = accA[mf][nf][2] * rz1;
            StA[((h + 1) << 7) + ((cl1 ^ (h + 1)) & 127)] = accA[mf][nf][3] * rz1;
            StB[(h << 7) + ((cl0 ^ h) & 127)]             = accB[mf][nf][0] * rz0;
            StB[((h + 1) << 7) + ((cl0 ^ (h + 1)) & 127)] = accB[mf][nf][1] * rz0;
            StB[(h << 7) + ((cl1 ^ h) & 127)]             = accB[mf][nf][2] * rz1;
            StB[((h + 1) << 7) + ((cl1 ^ (h + 1)) & 127)] = accB[mf][nf][3] * rz1;
        }
    }
    __syncthreads();

    const size_t HC = (size_t)Hn * Cn;
    for (int i = tid; i < 16384; i += 512) {
        int h = i >> 7, cc = i & 127;
        float a  = StA[(h << 7) + ((cc ^ h) & 127)];
        float bb = StB[(h << 7) + ((cc ^ h) & 127)];
        float cv = c_g[((size_t)b * Hn + h) * Cn + c0 + cc];
        size_t o = (size_t)b * 4 * HC + (size_t)h * Cn + c0 + cc;
        out[o]          = cv;
        out[o + HC]     = a;
        out[o + 2 * HC] = cv * a;
        out[o + 3 * HC] = cv * bb;
    }
}

// ---------------- launch ----------------
extern "C" void kernel_launch(void* const* d_in, const int* in_sizes, int n_in,
                              void* d_out, int out_size)
{
    const float* c     = (const float*)d_in[0];
    const float* q     = (const float*)d_in[1];
    const float* cmask = (const float*)d_in[2];
    const float* qmask = (const float*)d_in[3];
    const float* wc    = (const float*)d_in[4];
    const float* wq    = (const float*)d_in[5];
    const float* wcq   = (const float*)d_in[6];
    const float* bias  = (const float*)d_in[7];
    float* out = (float*)d_out;

    cudaFuncSetAttribute(k1_score, cudaFuncAttributeMaxDynamicSharedMemorySize, K1_SMEM);
    cudaFuncSetAttribute(k3_qb,    cudaFuncAttributeMaxDynamicSharedMemorySize, K3_SMEM);
    cudaFuncSetAttribute(k4_out,   cudaFuncAttributeMaxDynamicSharedMemorySize, K4_SMEM);

    k0_prep<<<Bn, 512>>>(q, wq);
    k1_score<<<dim3(NT, Bn), 512, K1_SMEM>>>(c, cmask, qmask, wc, wcq, bias);
    k3_qb<<<dim3(4, Bn), 512, K3_SMEM>>>(c, cmask);
    k3b_comb<<<Bn, 512>>>();
    k4_out<<<dim3(NT, Bn), 512, K4_SMEM>>>(c, qmask, out);
}

// round 16
// speedup vs baseline: 1.4114x; 1.0717x over previous
#include <cuda_runtime.h>
#include <cuda_bf16.h>

#define Bn 64
#define Hn 128
#define Cn 1024
#define Qn 128
#define NT 8

typedef unsigned int u32;

// ---------------- scratch ----------------
__device__ float g_S  [Bn * Cn * Qn];
__device__ float g_rowM[Bn * Cn];
__device__ float g_rowZ[Bn * Cn];
__device__ float g_pM [Bn * NT * Qn];
__device__ float g_pZ [Bn * NT * Qn];
__device__ float g_qbp4[Bn * 4 * Hn * Qn];
__device__ char  g_qhi[Bn * 32768];   // q bf16-hi tiles, smem byte-layout [h][q]
__device__ char  g_qlo[Bn * 32768];
__device__ char  g_phi[Bn * 32768];   // qb^T bf16-hi tiles (normalized)
__device__ char  g_plo[Bn * 32768];
__device__ float g_s1 [Bn * Qn];

// ---------------- helpers ----------------
__device__ __forceinline__ u32 smem_u32(const void* p) {
    u32 a;
    asm("{ .reg .u64 t; cvta.to.shared.u64 t, %1; cvt.u32.u64 %0, t; }" : "=r"(a) : "l"(p));
    return a;
}
__device__ __forceinline__ void ldsm4(u32 a, u32* r) {
    asm volatile("ldmatrix.sync.aligned.m8n8.x4.shared.b16 {%0,%1,%2,%3}, [%4];"
        : "=r"(r[0]), "=r"(r[1]), "=r"(r[2]), "=r"(r[3]) : "r"(a));
}
__device__ __forceinline__ void ldsm4t(u32 a, u32* r) {
    asm volatile("ldmatrix.sync.aligned.m8n8.x4.trans.shared.b16 {%0,%1,%2,%3}, [%4];"
        : "=r"(r[0]), "=r"(r[1]), "=r"(r[2]), "=r"(r[3]) : "r"(a));
}
__device__ __forceinline__ void mmabf(float* d, const u32* a, u32 b0, u32 b1) {
    asm volatile("mma.sync.aligned.m16n8k16.row.col.f32.bf16.bf16.f32 "
        "{%0,%1,%2,%3},{%4,%5,%6,%7},{%8,%9},{%0,%1,%2,%3};"
        : "+f"(d[0]), "+f"(d[1]), "+f"(d[2]), "+f"(d[3])
        : "r"(a[0]), "r"(a[1]), "r"(a[2]), "r"(a[3]), "r"(b0), "r"(b1));
}

// split 8 fp32 -> bf16 hi/lo, 16B store into 64-col tile (row stride 128B)
__device__ __forceinline__ void split8_64(char* hi, char* lo, int r, int slot,
                                          const float* f)
{
    u32 H[4], L[4];
#pragma unroll
    for (int j = 0; j < 4; j++) {
        float a = f[2 * j], b = f[2 * j + 1];
        __nv_bfloat16 ha = __float2bfloat16(a), hb = __float2bfloat16(b);
        float fa = __bfloat162float(ha), fb = __bfloat162float(hb);
        __nv_bfloat162 hp; hp.x = ha; hp.y = hb;
        H[j] = *(u32*)&hp;
        __nv_bfloat162 lp = __floats2bfloat162_rn(a - fa, b - fb);
        L[j] = *(u32*)&lp;
    }
    u32 off = (u32)r * 128 + (u32)((slot ^ (r & 7)) << 4);
    *(uint4*)(hi + off) = make_uint4(H[0], H[1], H[2], H[3]);
    *(uint4*)(lo + off) = make_uint4(L[0], L[1], L[2], L[3]);
}

// split 8 fp32 -> bf16 hi/lo, 16B store into 128-col tile (row stride 256B)
__device__ __forceinline__ void split8(char* hi, char* lo, int r, int slot,
                                       const float* f)
{
    u32 H[4], L[4];
#pragma unroll
    for (int j = 0; j < 4; j++) {
        float a = f[2 * j], b = f[2 * j + 1];
        __nv_bfloat16 ha = __float2bfloat16(a), hb = __float2bfloat16(b);
        float fa = __bfloat162float(ha), fb = __bfloat162float(hb);
        __nv_bfloat162 hp; hp.x = ha; hp.y = hb;
        H[j] = *(u32*)&hp;
        __nv_bfloat162 lp = __floats2bfloat162_rn(a - fa, b - fb);
        L[j] = *(u32*)&lp;
    }
    u32 off = (u32)r * 256 + (u32)((slot ^ (r & 7)) << 4);
    *(uint4*)(hi + off) = make_uint4(H[0], H[1], H[2], H[3]);
    *(uint4*)(lo + off) = make_uint4(L[0], L[1], L[2], L[3]);
}

// GEMM over K=64 where BOTH operands are stored [k:64 rows][mn:128 cols], trans-ldsm.
__device__ __forceinline__ void warp_gemm_tt(u32 ah, u32 al, u32 bh, u32 bl,
                                             int lane, int m0, int n0,
                                             float acc[2][4][4])
{
    int rkA = (lane & 7) + ((lane >> 4) << 3);
    int slA = (lane >> 3) & 1;
    int rkB = (lane & 7) + (((lane >> 3) & 1) << 3);
    int slB = lane >> 4;
#pragma unroll
    for (int ks = 0; ks < 4; ks++) {
        u32 AH[2][4], AL[2][4], BH[2][4], BL[2][4];
#pragma unroll
        for (int mf = 0; mf < 2; mf++) {
            int row = ks * 16 + rkA;
            int slot = (m0 >> 3) + 2 * mf + slA;
            u32 ad = (u32)row * 256 + (u32)((slot ^ (row & 7)) << 4);
            ldsm4t(ah + ad, AH[mf]);
            ldsm4t(al + ad, AL[mf]);
        }
#pragma unroll
        for (int nb = 0; nb < 2; nb++) {
            int row = ks * 16 + rkB;
            int slot = (n0 >> 3) + 2 * nb + slB;
            u32 ad = (u32)row * 256 + (u32)((slot ^ (row & 7)) << 4);
            ldsm4t(bh + ad, BH[nb]);
            ldsm4t(bl + ad, BL[nb]);
        }
#pragma unroll
        for (int mf = 0; mf < 2; mf++)
#pragma unroll
            for (int nh = 0; nh < 2; nh++)
#pragma unroll
                for (int no = 0; no < 2; no++) {
                    float* d = acc[mf][nh * 2 + no];
                    mmabf(d, AH[mf], BH[nh][2 * no], BH[nh][2 * no + 1]);
                    mmabf(d, AH[mf], BL[nh][2 * no], BL[nh][2 * no + 1]);
                    mmabf(d, AL[mf], BH[nh][2 * no], BH[nh][2 * no + 1]);
                }
    }
}

// GEMM over K=64: A non-trans [m:128][k:64], B trans [k:64][n:128].
__device__ __forceinline__ void warp_gemm_nt(u32 ah, u32 al, u32 bh, u32 bl,
                                             int lane, int m0, int n0,
                                             float acc[2][4][4])
{
    int rA = lane & 15, hi16 = lane >> 4;
    int rowA[2] = {m0 + rA, m0 + 16 + rA};
    int rkB = (lane & 7) + (((lane >> 3) & 1) << 3);
    int slB = lane >> 4;
#pragma unroll
    for (int ks = 0; ks < 4; ks++) {
        u32 AH[2][4], AL[2][4], BH[2][4], BL[2][4];
#pragma unroll
        for (int f = 0; f < 2; f++) {
            u32 sa = (u32)rowA[f] * 128 + (u32)((((ks << 1) + hi16) ^ (rowA[f] & 7)) << 4);
            ldsm4(ah + sa, AH[f]);
            ldsm4(al + sa, AL[f]);
        }
#pragma unroll
        for (int nb = 0; nb < 2; nb++) {
            int row = ks * 16 + rkB;
            int slot = (n0 >> 3) + 2 * nb + slB;
            u32 ad = (u32)row * 256 + (u32)((slot ^ (row & 7)) << 4);
            ldsm4t(bh + ad, BH[nb]);
            ldsm4t(bl + ad, BL[nb]);
        }
#pragma unroll
        for (int mf = 0; mf < 2; mf++)
#pragma unroll
            for (int nh = 0; nh < 2; nh++)
#pragma unroll
                for (int no = 0; no < 2; no++) {
                    float* d = acc[mf][nh * 2 + no];
                    mmabf(d, AH[mf], BH[nh][2 * no], BH[nh][2 * no + 1]);
                    mmabf(d, AH[mf], BL[nh][2 * no], BL[nh][2 * no + 1]);
                    mmabf(d, AL[mf], BH[nh][2 * no], BH[nh][2 * no + 1]);
                }
    }
}

// ---------------- K0: per-batch q split + s1 ----------------
__global__ __launch_bounds__(512) void k0_prep(
    const float* __restrict__ q_g, const float* __restrict__ wq)
{
    __shared__ float red[32 * 128];
    int tid = threadIdx.x, b = blockIdx.x;
    int sx = tid & 15;
    float s1p[8] = {0, 0, 0, 0, 0, 0, 0, 0};
    char* dhB = g_qhi + b * 32768;
    char* dlB = g_qlo + b * 32768;
#pragma unroll
    for (int it = 0; it < 4; it++) {
        int i = tid + it * 512;
        int h = i >> 4;
        const float* pq = &q_g[((size_t)b * Hn + h) * Qn + sx * 8];
        float4 v0 = *(const float4*)pq, v1 = *(const float4*)(pq + 4);
        float f[8] = {v0.x, v0.y, v0.z, v0.w, v1.x, v1.y, v1.z, v1.w};
        float wqv = __ldg(&wq[h]);
#pragma unroll
        for (int j = 0; j < 8; j++) s1p[j] += f[j] * wqv;
        split8(dhB + (h >> 6) * 16384, dlB + (h >> 6) * 16384, h & 63, sx, f);
    }
    int k = tid >> 4;
#pragma unroll
    for (int j = 0; j < 8; j++) red[k * 128 + sx * 8 + j] = s1p[j];
    __syncthreads();
    if (tid < 128) {
        float s = 0.f;
#pragma unroll
        for (int w = 0; w < 32; w++) s += red[w * 128 + tid];
        g_s1[b * Qn + tid] = s;
    }
}

// ---------------- K1 ----------------
#define K1_SMEM 83968

__global__ __launch_bounds__(512, 2) void k1_score(
    const float* __restrict__ c_g,
    const float* __restrict__ cmask, const float* __restrict__ qmask,
    const float* __restrict__ wc, const float* __restrict__ wcq,
    const float* __restrict__ bias)
{
    extern __shared__ __align__(256) char smem[];
    u32 sb = smem_u32(smem);
    float* s0s  = (float*)(smem + 65536);
    float* s1s  = (float*)(smem + 66048);
    float* qms  = (float*)(smem + 66560);
    float* cms  = (float*)(smem + 67072);
    float* red1 = (float*)(smem + 67584);
    float* red2 = (float*)(smem + 75776);
    int tid = threadIdx.x, lane = tid & 31, wid = tid >> 5;
    int b = blockIdx.y, ct = blockIdx.x, c0 = ct * 128;
    float biasv = bias[0];

    for (int i = tid; i < 2048; i += 512) red1[i] = 0.f;
    if (tid < 128) qms[tid] = qmask[b * Qn + tid];
    else if (tid < 256) cms[tid - 128] = cmask[b * Cn + c0 + tid - 128];
    else if (tid < 384) s1s[tid - 256] = g_s1[b * Qn + tid - 256];

    float acc[2][4][4];
#pragma unroll
    for (int i = 0; i < 2; i++)
#pragma unroll
        for (int j = 0; j < 4; j++)
#pragma unroll
            for (int k = 0; k < 4; k++) acc[i][j][k] = 0.f;

    int m0 = (wid >> 2) * 32, n0 = (wid & 3) * 32;
    int sx0 = tid & 15;

#pragma unroll
    for (int kc = 0; kc < 2; kc++) {
        __syncthreads();
        const uint4* srcH = (const uint4*)(g_qhi + b * 32768 + kc * 16384);
        const uint4* srcL = (const uint4*)(g_qlo + b * 32768 + kc * 16384);
#pragma unroll
        for (int it = 0; it < 2; it++) {
            int i = tid + it * 512;
            ((uint4*)(smem + 32768))[i] = srcH[i];
            ((uint4*)(smem + 49152))[i] = srcL[i];
        }
        float s0p[8] = {0, 0, 0, 0, 0, 0, 0, 0};
#pragma unroll
        for (int it = 0; it < 2; it++) {
            int i = tid + it * 512;
            int hl = i >> 4, sx = i & 15;
            int h = kc * 64 + hl;
            const float* pc = &c_g[((size_t)b * Hn + h) * Cn + c0 + sx * 8];
            float4 v0 = *(const float4*)pc, v1 = *(const float4*)(pc + 4);
            float f[8] = {v0.x, v0.y, v0.z, v0.w, v1.x, v1.y, v1.z, v1.w};
            float wcv = __ldg(&wc[h]), wcqv = __ldg(&wcq[h]);
#pragma unroll
            for (int j = 0; j < 8; j++) { s0p[j] += f[j] * wcv; f[j] *= wcqv; }
            split8(smem, smem + 16384, hl, sx, f);
        }
#pragma unroll
        for (int j = 0; j < 8; j++)
            s0p[j] += __shfl_xor_sync(~0u, s0p[j], 16);
        if (lane < 16) {
#pragma unroll
            for (int j = 0; j < 8; j++)
                red1[wid * 128 + sx0 * 8 + j] += s0p[j];
        }
        __syncthreads();
        warp_gemm_tt(sb, sb + 16384, sb + 32768, sb + 49152, lane, m0, n0, acc);
    }
    __syncthreads();
    if (tid < 128) {
        float a = 0.f;
#pragma unroll
        for (int w = 0; w < 16; w++) a += red1[w * 128 + tid];
        s0s[tid] = a + biasv;
    }
    __syncthreads();

    int lr = lane >> 2, lc2 = (lane & 3) * 2;

#pragma unroll
    for (int mf = 0; mf < 2; mf++) {
        int r0 = m0 + mf * 16 + lr, r1 = r0 + 8;
        float s0a = s0s[r0], s0b = s0s[r1];
#pragma unroll
        for (int nf = 0; nf < 4; nf++) {
            int col = n0 + nf * 8 + lc2;
            float s1a = s1s[col], s1b = s1s[col + 1];
            acc[mf][nf][0] += s0a + s1a;
            acc[mf][nf][1] += s0a + s1b;
            acc[mf][nf][2] += s0b + s1a;
            acc[mf][nf][3] += s0b + s1b;
        }
    }

#pragma unroll
    for (int mf = 0; mf < 2; mf++) {
        int r0 = m0 + mf * 16 + lr, r1 = r0 + 8;
#pragma unroll
        for (int nf = 0; nf < 4; nf++) {
            int col = n0 + nf * 8 + lc2;
            *(float2*)&g_S[((size_t)b * Cn + c0 + r0) * Qn + col] =
                make_float2(acc[mf][nf][0], acc[mf][nf][1]);
            *(float2*)&g_S[((size_t)b * Cn + c0 + r1) * Qn + col] =
                make_float2(acc[mf][nf][2], acc[mf][nf][3]);
        }
    }

    bool qm0[4], qm1[4];
#pragma unroll
    for (int nf = 0; nf < 4; nf++) {
        qm0[nf] = qms[n0 + nf * 8 + lc2] > 0.f;
        qm1[nf] = qms[n0 + nf * 8 + lc2 + 1] > 0.f;
    }
    bool cmv[2][2];
#pragma unroll
    for (int mf = 0; mf < 2; mf++) {
        cmv[mf][0] = cms[m0 + mf * 16 + lr] > 0.f;
        cmv[mf][1] = cms[m0 + mf * 16 + 8 + lr] > 0.f;
    }

    float rmx[2][2];
#pragma unroll
    for (int mf = 0; mf < 2; mf++) { rmx[mf][0] = -1e30f; rmx[mf][1] = -1e30f; }
#pragma unroll
    for (int mf = 0; mf < 2; mf++)
#pragma unroll
        for (int nf = 0; nf < 4; nf++) {
            if (qm0[nf]) {
                rmx[mf][0] = fmaxf(rmx[mf][0], acc[mf][nf][0]);
                rmx[mf][1] = fmaxf(rmx[mf][1], acc[mf][nf][2]);
            }
            if (qm1[nf]) {
                rmx[mf][0] = fmaxf(rmx[mf][0], acc[mf][nf][1]);
                rmx[mf][1] = fmaxf(rmx[mf][1], acc[mf][nf][3]);
            }
        }
#pragma unroll
    for (int mf = 0; mf < 2; mf++)
#pragma unroll
        for (int h = 0; h < 2; h++) {
            rmx[mf][h] = fmaxf(rmx[mf][h], __shfl_xor_sync(~0u, rmx[mf][h], 1));
            rmx[mf][h] = fmaxf(rmx[mf][h], __shfl_xor_sync(~0u, rmx[mf][h], 2));
        }
    if ((lane & 3) == 0)
#pragma unroll
        for (int mf = 0; mf < 2; mf++)
#pragma unroll
            for (int h = 0; h < 2; h++)
                red1[(wid & 3) * 128 + m0 + mf * 16 + h * 8 + lr] = rmx[mf][h];
    __syncthreads();

    float rowMv[2][2];
#pragma unroll
    for (int mf = 0; mf < 2; mf++)
#pragma unroll
        for (int h = 0; h < 2; h++) {
            int r = m0 + mf * 16 + h * 8 + lr;
            float m = red1[r];
#pragma unroll
            for (int g = 1; g < 4; g++) m = fmaxf(m, red1[g * 128 + r]);
            rowMv[mf][h] = m;
        }
    float rzz[2][2] = {{0.f, 0.f}, {0.f, 0.f}};
#pragma unroll
    for (int mf = 0; mf < 2; mf++)
#pragma unroll
        for (int nf = 0; nf < 4; nf++) {
            if (qm0[nf]) {
                rzz[mf][0] += __expf(acc[mf][nf][0] - rowMv[mf][0]);
                rzz[mf][1] += __expf(acc[mf][nf][2] - rowMv[mf][1]);
            }
            if (qm1[nf]) {
                rzz[mf][0] += __expf(acc[mf][nf][1] - rowMv[mf][0]);
                rzz[mf][1] += __expf(acc[mf][nf][3] - rowMv[mf][1]);
            }
        }
#pragma unroll
    for (int mf = 0; mf < 2; mf++)
#pragma unroll
        for (int h = 0; h < 2; h++) {
            rzz[mf][h] += __shfl_xor_sync(~0u, rzz[mf][h], 1);
            rzz[mf][h] += __shfl_xor_sync(~0u, rzz[mf][h], 2);
        }
    if ((lane & 3) == 0)
#pragma unroll
        for (int mf = 0; mf < 2; mf++)
#pragma unroll
            for (int h = 0; h < 2; h++)
                red2[(wid & 3) * 128 + m0 + mf * 16 + h * 8 + lr] = rzz[mf][h];
    __syncthreads();

    if ((wid & 3) == 0 && (lane & 3) == 0) {
#pragma unroll
        for (int mf = 0; mf < 2; mf++)
#pragma unroll
            for (int h = 0; h < 2; h++) {
                int r = m0 + mf * 16 + h * 8 + lr;
                float z = red2[r] + red2[128 + r] + red2[256 + r] + red2[384 + r];
                g_rowM[b * Cn + c0 + r] = rowMv[mf][h];
                g_rowZ[b * Cn + c0 + r] = z;
            }
    }
    __syncthreads();

    float cmx[4][2];
#pragma unroll
    for (int nf = 0; nf < 4; nf++) { cmx[nf][0] = -1e30f; cmx[nf][1] = -1e30f; }
#pragma unroll
    for (int mf = 0; mf < 2; mf++)
#pragma unroll
        for (int nf = 0; nf < 4; nf++) {
            if (cmv[mf][0]) {
                cmx[nf][0] = fmaxf(cmx[nf][0], acc[mf][nf][0]);
                cmx[nf][1] = fmaxf(cmx[nf][1], acc[mf][nf][1]);
            }
            if (cmv[mf][1]) {
                cmx[nf][0] = fmaxf(cmx[nf][0], acc[mf][nf][2]);
                cmx[nf][1] = fmaxf(cmx[nf][1], acc[mf][nf][3]);
            }
        }
#pragma unroll
    for (int nf = 0; nf < 4; nf++)
#pragma unroll
        for (int v = 0; v < 2; v++) {
            cmx[nf][v] = fmaxf(cmx[nf][v], __shfl_xor_sync(~0u, cmx[nf][v], 4));
            cmx[nf][v] = fmaxf(cmx[nf][v], __shfl_xor_sync(~0u, cmx[nf][v], 8));
            cmx[nf][v] = fmaxf(cmx[nf][v], __shfl_xor_sync(~0u, cmx[nf][v], 16));
        }
    if (lr == 0)
#pragma unroll
        for (int nf = 0; nf < 4; nf++) {
            red1[(wid >> 2) * 128 + n0 + nf * 8 + lc2]     = cmx[nf][0];
            red1[(wid >> 2) * 128 + n0 + nf * 8 + lc2 + 1] = cmx[nf][1];
        }
    __syncthreads();

    float pMv[4][2];
#pragma unroll
    for (int nf = 0; nf < 4; nf++)
#pragma unroll
        for (int v = 0; v < 2; v++) {
            int col = n0 + nf * 8 + lc2 + v;
            float m = red1[col];
#pragma unroll
            for (int g = 1; g < 4; g++) m = fmaxf(m, red1[g * 128 + col]);
            pMv[nf][v] = m;
        }
    float czz[4][2] = {{0,0},{0,0},{0,0},{0,0}};
#pragma unroll
    for (int nf = 0; nf < 4; nf++) {
        if (cmv[0][0]) { czz[nf][0] += __expf(acc[0][nf][0] - pMv[nf][0]); czz[nf][1] += __expf(acc[0][nf][1] - pMv[nf][1]); }
        if (cmv[0][1]) { czz[nf][0] += __expf(acc[0][nf][2] - pMv[nf][0]); czz[nf][1] += __expf(acc[0][nf][3] - pMv[nf][1]); }
        if (cmv[1][0]) { czz[nf][0] += __expf(acc[1][nf][0] - pMv[nf][0]); czz[nf][1] += __expf(acc[1][nf][1] - pMv[nf][1]); }
        if (cmv[1][1]) { czz[nf][0] += __expf(acc[1][nf][2] - pMv[nf][0]); czz[nf][1] += __expf(acc[1][nf][3] - pMv[nf][1]); }
    }
#pragma unroll
    for (int nf = 0; nf < 4; nf++)
#pragma unroll
        for (int v = 0; v < 2; v++) {
            czz[nf][v] += __shfl_xor_sync(~0u, czz[nf][v], 4);
            czz[nf][v] += __shfl_xor_sync(~0u, czz[nf][v], 8);
            czz[nf][v] += __shfl_xor_sync(~0u, czz[nf][v], 16);
        }
    if (lr == 0)
#pragma unroll
        for (int nf = 0; nf < 4; nf++) {
            red2[(wid >> 2) * 128 + n0 + nf * 8 + lc2]     = czz[nf][0];
            red2[(wid >> 2) * 128 + n0 + nf * 8 + lc2 + 1] = czz[nf][1];
        }
    __syncthreads();

    if ((wid >> 2) == 0 && lr == 0) {
#pragma unroll
        for (int nf = 0; nf < 4; nf++)
#pragma unroll
            for (int v = 0; v < 2; v++) {
                int col = n0 + nf * 8 + lc2 + v;
                float z = red2[col] + red2[128 + col] + red2[256 + col] + red2[384 + col];
                g_pM[(b * NT + ct) * Qn + col] = pMv[nf][v];
                g_pZ[(b * NT + ct) * Qn + col] = z;
            }
    }
}

// ---------------- K3: qb^T partials ----------------
#define K3_SMEM 66048

__global__ __launch_bounds__(512, 2) void k3_qb(
    const float* __restrict__ c_g, const float* __restrict__ cmask)
{
    extern __shared__ __align__(256) char smem[];
    u32 sb = smem_u32(smem);
    float* colMs = (float*)(smem + 65536);
    int tid = threadIdx.x, lane = tid & 31, wid = tid >> 5;
    int b = blockIdx.y, quarter = blockIdx.x;

    if (tid < 128) {
        float m = -3.4e38f;
#pragma unroll
        for (int t = 0; t < NT; t++) m = fmaxf(m, g_pM[(b * NT + t) * Qn + tid]);
        colMs[tid] = m;
    }

    float acc[2][4][4];
#pragma unroll
    for (int i = 0; i < 2; i++)
#pragma unroll
        for (int j = 0; j < 4; j++)
#pragma unroll
            for (int k = 0; k < 4; k++) acc[i][j][k] = 0.f;

    int m0 = (wid >> 2) * 32, n0 = (wid & 3) * 32;

    for (int it = 0; it < 4; it++) {
        int c0 = quarter * 256 + it * 64;
        __syncthreads();
        for (int i = tid; i < 1024; i += 512) {
            int r = i >> 3, sx = i & 7;
            const float* pa = &c_g[((size_t)b * Hn + r) * Cn + c0 + sx * 8];
            float4 v0 = *(const float4*)pa, v1 = *(const float4*)(pa + 4);
            float f[8] = {v0.x, v0.y, v0.z, v0.w, v1.x, v1.y, v1.z, v1.w};
            split8_64(smem, smem + 16384, r, sx, f);
        }
        for (int i = tid; i < 1024; i += 512) {
            int cl = i >> 4, sx = i & 15;
            const float* ps = &g_S[((size_t)b * Cn + c0 + cl) * Qn + sx * 8];
            float4 s0 = *(const float4*)ps, s1 = *(const float4*)(ps + 4);
            float f[8] = {s0.x, s0.y, s0.z, s0.w, s1.x, s1.y, s1.z, s1.w};
            bool cmv = __ldg(&cmask[b * Cn + c0 + cl]) > 0.f;
#pragma unroll
            for (int j = 0; j < 8; j++)
                f[j] = cmv ? __expf(f[j] - colMs[sx * 8 + j]) : 0.f;
            split8(smem + 32768, smem + 49152, cl, sx, f);
        }
        __syncthreads();
        warp_gemm_nt(sb, sb + 16384, sb + 32768, sb + 49152, lane, m0, n0, acc);
    }

    int lr = lane >> 2, lc2 = (lane & 3) * 2;
#pragma unroll
    for (int mf = 0; mf < 2; mf++) {
        int h0 = m0 + mf * 16 + lr, h1 = h0 + 8;
#pragma unroll
        for (int nf = 0; nf < 4; nf++) {
            int col = n0 + nf * 8 + lc2;
            *(float2*)&g_qbp4[((size_t)(b * 4 + quarter) * Hn + h0) * Qn + col] =
                make_float2(acc[mf][nf][0], acc[mf][nf][1]);
            *(float2*)&g_qbp4[((size_t)(b * 4 + quarter) * Hn + h1) * Qn + col] =
                make_float2(acc[mf][nf][2], acc[mf][nf][3]);
        }
    }
}

// ---------------- K3b: combine partials, normalize, split to bf16 tiles -----
__global__ __launch_bounds__(512) void k3b_comb() {
    __shared__ float rcz[128];
    int tid = threadIdx.x, b = blockIdx.x;
    if (tid < 128) {
        float m = -3.4e38f;
#pragma unroll
        for (int t = 0; t < NT; t++) m = fmaxf(m, g_pM[(b * NT + t) * Qn + tid]);
        float z = 0.f;
#pragma unroll
        for (int t = 0; t < NT; t++)
            z += g_pZ[(b * NT + t) * Qn + tid] * __expf(g_pM[(b * NT + t) * Qn + tid] - m);
        rcz[tid] = (z > 0.f) ? 1.f / z : 0.f;
    }
    __syncthreads();
    char* dhB = g_phi + b * 32768;
    char* dlB = g_plo + b * 32768;
    const size_t PS = (size_t)Hn * Qn;
    int sx = tid & 15;
#pragma unroll
    for (int it = 0; it < 4; it++) {
        int i = tid + it * 512;
        int h = i >> 4;
        const float* p0 = &g_qbp4[((size_t)(b * 4) * Hn + h) * Qn + sx * 8];
        float fp[8] = {0, 0, 0, 0, 0, 0, 0, 0};
#pragma unroll
        for (int t = 0; t < 4; t++) {
            float4 a0 = *(const float4*)(p0 + t * PS);
            float4 a1 = *(const float4*)(p0 + t * PS + 4);
            fp[0] += a0.x; fp[1] += a0.y; fp[2] += a0.z; fp[3] += a0.w;
            fp[4] += a1.x; fp[5] += a1.y; fp[6] += a1.z; fp[7] += a1.w;
        }
#pragma unroll
        for (int j = 0; j < 8; j++) fp[j] *= rcz[sx * 8 + j];
        split8(dhB + (h >> 6) * 16384, dlB + (h >> 6) * 16384, h & 63, sx, fp);
    }
}

// ---------------- K4: dual GEMM; fragment-direct output, no staging ---------
#define K4_SMEM 198656

__global__ __launch_bounds__(512) void k4_out(
    const float* __restrict__ c_g,
    const float* __restrict__ qmask, float* __restrict__ out)
{
    extern __shared__ __align__(256) char smem[];
    u32 sb = smem_u32(smem);
    float* rms = (float*)(smem + 196608);
    float* qms = (float*)(smem + 197120);
    float* rzs = (float*)(smem + 197632);
    int tid = threadIdx.x, lane = tid & 31, wid = tid >> 5;
    int b = blockIdx.y, ct = blockIdx.x, c0 = ct * 128;
    const size_t HC = (size_t)Hn * Cn;
    float* outB = out + (size_t)b * 4 * HC;

    if (tid < 128) rms[tid] = g_rowM[b * Cn + c0 + tid];
    else if (tid < 256) qms[tid - 128] = qmask[b * Qn + tid - 128];
    else if (tid < 384) {
        float z = g_rowZ[b * Cn + c0 + tid - 256];
        rzs[tid - 256] = (z > 0.f) ? 1.f / z : 0.f;
    }

    // Q + P fills: straight copies of precomputed bf16 tiles
    {
        const uint4* qH = (const uint4*)(g_qhi + b * 32768);
        const uint4* qL = (const uint4*)(g_qlo + b * 32768);
        const uint4* pH = (const uint4*)(g_phi + b * 32768);
        const uint4* pL = (const uint4*)(g_plo + b * 32768);
#pragma unroll
        for (int it = 0; it < 4; it++) {
            int i = tid + it * 512;
            ((uint4*)(smem + 65536))[i]  = qH[i];
            ((uint4*)(smem + 98304))[i]  = qL[i];
            ((uint4*)(smem + 131072))[i] = pH[i];
            ((uint4*)(smem + 163840))[i] = pL[i];
        }
    }
    __syncthreads();   // rms/qms/rzs visible to all threads before E fill

    // E fill + plane-0 copy (coalesced)
    for (int i = tid; i < 2048; i += 512) {
        int r = i >> 4, sx = i & 15;
        const float* ps = &g_S[((size_t)b * Cn + c0 + r) * Qn + sx * 8];
        float4 s0 = *(const float4*)ps, s1 = *(const float4*)(ps + 4);
        float fe[8] = {s0.x, s0.y, s0.z, s0.w, s1.x, s1.y, s1.z, s1.w};
        float rm = rms[r];
#pragma unroll
        for (int j = 0; j < 8; j++)
            fe[j] = (qms[sx * 8 + j] > 0.f) ? __expf(fe[j] - rm) : 0.f;
        split8(smem, smem + 32768, r, sx, fe);
        // plane 0: out[h][cc] = c[h][cc] — r acts as h-index here
        const int h = r, ccb = sx * 8;
        float4 c0v = *(const float4*)&c_g[((size_t)b * Hn + h) * Cn + c0 + ccb];
        float4 c1v = *(const float4*)&c_g[((size_t)b * Hn + h) * Cn + c0 + ccb + 4];
        *(float4*)&outB[(size_t)h * Cn + c0 + ccb]     = c0v;
        *(float4*)&outB[(size_t)h * Cn + c0 + ccb + 4] = c1v;
    }
    __syncthreads();

    int m0 = (wid >> 2) * 32, n0 = (wid & 3) * 32;
    int lr = lane >> 2, lc = (lane & 3) * 2;

    float accA[2][4][4], accB[2][4][4];
#pragma unroll
    for (int i = 0; i < 2; i++)
#pragma unroll
        for (int j = 0; j < 4; j++)
#pragma unroll
            for (int k = 0; k < 4; k++) { accA[i][j][k] = 0.f; accB[i][j][k] = 0.f; }

    {
        u32 eh = sb, el = sb + 32768, qh = sb + 65536, ql = sb + 98304;
        u32 ph = sb + 131072, pl = sb + 163840;
        int rA = lane & 15, hi16 = lane >> 4;
        int rBl = (lane & 7) + ((lane >> 4) << 3);
        int kh = (lane >> 3) & 1;
        int rowA[2] = {m0 + rA, m0 + 16 + rA};
        int rowB[2] = {n0 + rBl, n0 + 16 + rBl};
#pragma unroll
        for (int ks = 0; ks < 8; ks++) {
            u32 AH[2][4], AL[2][4];
#pragma unroll
            for (int f = 0; f < 2; f++) {
                u32 sa = (u32)rowA[f] * 256 + (u32)((((ks << 1) + hi16) ^ (rowA[f] & 7)) << 4);
                ldsm4(eh + sa, AH[f]);
                ldsm4(el + sa, AL[f]);
            }
#pragma unroll
            for (int nh = 0; nh < 2; nh++) {
                u32 QH[4], QL[4], PH[4], PL[4];
                u32 sbo = (u32)rowB[nh] * 256 + (u32)((((ks << 1) + kh) ^ (rowB[nh] & 7)) << 4);
                ldsm4(qh + sbo, QH);
                ldsm4(ql + sbo, QL);
                ldsm4(ph + sbo, PH);
                ldsm4(pl + sbo, PL);
#pragma unroll
                for (int mf = 0; mf < 2; mf++)
#pragma unroll
                    for (int no = 0; no < 2; no++) {
                        float* dA = accA[mf][nh * 2 + no];
                        mmabf(dA, AH[mf], QH[2 * no], QH[2 * no + 1]);
                        mmabf(dA, AH[mf], QL[2 * no], QL[2 * no + 1]);
                        mmabf(dA, AL[mf], QH[2 * no], QH[2 * no + 1]);
                        float* dB = accB[mf][nh * 2 + no];
                        mmabf(dB, AH[mf], PH[2 * no], PH[2 * no + 1]);
                        mmabf(dB, AH[mf], PL[2 * no], PL[2 * no + 1]);
                        mmabf(dB, AL[mf], PH[2 * no], PH[2 * no + 1]);
                    }
            }
        }
    }

    // fragment-direct epilogue: planes 1 (a), 2 (c*a), 3 (c*b)
#pragma unroll
    for (int mf = 0; mf < 2; mf++) {
        int cl0 = m0 + mf * 16 + lr, cl1 = cl0 + 8;
        float rz0 = rzs[cl0], rz1 = rzs[cl1];
#pragma unroll
        for (int nf = 0; nf < 4; nf++) {
            int h = n0 + nf * 8 + lc, h2 = h + 1;
            float a00 = accA[mf][nf][0] * rz0, a01 = accA[mf][nf][1] * rz0;
            float a10 = accA[mf][nf][2] * rz1, a11 = accA[mf][nf][3] * rz1;
            float b00 = accB[mf][nf][0] * rz0, b01 = accB[mf][nf][1] * rz0;
            float b10 = accB[mf][nf][2] * rz1, b11 = accB[mf][nf][3] * rz1;
            float cv00 = __ldg(&c_g[((size_t)b * Hn + h)  * Cn + c0 + cl0]);
            float cv10 = __ldg(&c_g[((size_t)b * Hn + h)  * Cn + c0 + cl1]);
            float cv01 = __ldg(&c_g[((size_t)b * Hn + h2) * Cn + c0 + cl0]);
            float cv11 = __ldg(&c_g[((size_t)b * Hn + h2) * Cn + c0 + cl1]);
            size_t o00 = (size_t)h  * Cn + c0 + cl0;
            size_t o10 = (size_t)h  * Cn + c0 + cl1;
            size_t o01 = (size_t)h2 * Cn + c0 + cl0;
            size_t o11 = (size_t)h2 * Cn + c0 + cl1;
            outB[HC + o00] = a00;  outB[HC + o10] = a10;
            outB[HC + o01] = a01;  outB[HC + o11] = a11;
            outB[2 * HC + o00] = cv00 * a00;  outB[2 * HC + o10] = cv10 * a10;
            outB[2 * HC + o01] = cv01 * a01;  outB[2 * HC + o11] = cv11 * a11;
            outB[3 * HC + o00] = cv00 * b00;  outB[3 * HC + o10] = cv10 * b10;
            outB[3 * HC + o01] = cv01 * b01;  outB[3 * HC + o11] = cv11 * b11;
        }
    }
}

// ---------------- launch ----------------
extern "C" void kernel_launch(void* const* d_in, const int* in_sizes, int n_in,
                              void* d_out, int out_size)
{
    const float* c     = (const float*)d_in[0];
    const float* q     = (const float*)d_in[1];
    const float* cmask = (const float*)d_in[2];
    const float* qmask = (const float*)d_in[3];
    const float* wc    = (const float*)d_in[4];
    const float* wq    = (const float*)d_in[5];
    const float* wcq   = (const float*)d_in[6];
    const float* bias  = (const float*)d_in[7];
    float* out = (float*)d_out;

    cudaFuncSetAttribute(k1_score, cudaFuncAttributeMaxDynamicSharedMemorySize, K1_SMEM);
    cudaFuncSetAttribute(k3_qb,    cudaFuncAttributeMaxDynamicSharedMemorySize, K3_SMEM);
    cudaFuncSetAttribute(k4_out,   cudaFuncAttributeMaxDynamicSharedMemorySize, K4_SMEM);

    k0_prep<<<Bn, 512>>>(q, wq);
    k1_score<<<dim3(NT, Bn), 512, K1_SMEM>>>(c, cmask, qmask, wc, wcq, bias);
    k3_qb<<<dim3(4, Bn), 512, K3_SMEM>>>(c, cmask);
    k3b_comb<<<Bn, 512>>>();
    k4_out<<<dim3(NT, Bn), 512, K4_SMEM>>>(c, qmask, out);
}

// round 17
// speedup vs baseline: 1.4829x; 1.0507x over previous
#include <cuda_runtime.h>
#include <cuda_bf16.h>

#define Bn 64
#define Hn 128
#define Cn 1024
#define Qn 128
#define NT 8

typedef unsigned int u32;

// ---------------- scratch ----------------
__device__ float g_S  [Bn * Cn * Qn];
__device__ float g_rowM[Bn * Cn];
__device__ float g_rowZ[Bn * Cn];
__device__ float g_pM [Bn * NT * Qn];
__device__ float g_pZ [Bn * NT * Qn];
__device__ float g_qbp4[Bn * 4 * Hn * Qn];
__device__ char  g_qhi[Bn * 32768];   // q bf16-hi tiles, smem byte-layout [h][q]
__device__ char  g_qlo[Bn * 32768];
__device__ char  g_phi[Bn * 32768];   // qb^T bf16-hi tiles (normalized)
__device__ char  g_plo[Bn * 32768];
__device__ float g_s1 [Bn * Qn];

// ---------------- helpers ----------------
__device__ __forceinline__ u32 smem_u32(const void* p) {
    u32 a;
    asm("{ .reg .u64 t; cvta.to.shared.u64 t, %1; cvt.u32.u64 %0, t; }" : "=r"(a) : "l"(p));
    return a;
}
__device__ __forceinline__ void ldsm4(u32 a, u32* r) {
    asm volatile("ldmatrix.sync.aligned.m8n8.x4.shared.b16 {%0,%1,%2,%3}, [%4];"
        : "=r"(r[0]), "=r"(r[1]), "=r"(r[2]), "=r"(r[3]) : "r"(a));
}
__device__ __forceinline__ void ldsm4t(u32 a, u32* r) {
    asm volatile("ldmatrix.sync.aligned.m8n8.x4.trans.shared.b16 {%0,%1,%2,%3}, [%4];"
        : "=r"(r[0]), "=r"(r[1]), "=r"(r[2]), "=r"(r[3]) : "r"(a));
}
__device__ __forceinline__ void mmabf(float* d, const u32* a, u32 b0, u32 b1) {
    asm volatile("mma.sync.aligned.m16n8k16.row.col.f32.bf16.bf16.f32 "
        "{%0,%1,%2,%3},{%4,%5,%6,%7},{%8,%9},{%0,%1,%2,%3};"
        : "+f"(d[0]), "+f"(d[1]), "+f"(d[2]), "+f"(d[3])
        : "r"(a[0]), "r"(a[1]), "r"(a[2]), "r"(a[3]), "r"(b0), "r"(b1));
}

// split 8 fp32 -> bf16 hi/lo, 16B store into 64-col tile (row stride 128B)
__device__ __forceinline__ void split8_64(char* hi, char* lo, int r, int slot,
                                          const float* f)
{
    u32 H[4], L[4];
#pragma unroll
    for (int j = 0; j < 4; j++) {
        float a = f[2 * j], b = f[2 * j + 1];
        __nv_bfloat16 ha = __float2bfloat16(a), hb = __float2bfloat16(b);
        float fa = __bfloat162float(ha), fb = __bfloat162float(hb);
        __nv_bfloat162 hp; hp.x = ha; hp.y = hb;
        H[j] = *(u32*)&hp;
        __nv_bfloat162 lp = __floats2bfloat162_rn(a - fa, b - fb);
        L[j] = *(u32*)&lp;
    }
    u32 off = (u32)r * 128 + (u32)((slot ^ (r & 7)) << 4);
    *(uint4*)(hi + off) = make_uint4(H[0], H[1], H[2], H[3]);
    *(uint4*)(lo + off) = make_uint4(L[0], L[1], L[2], L[3]);
}

// split 8 fp32 -> bf16 hi/lo, 16B store into 128-col tile (row stride 256B)
__device__ __forceinline__ void split8(char* hi, char* lo, int r, int slot,
                                       const float* f)
{
    u32 H[4], L[4];
#pragma unroll
    for (int j = 0; j < 4; j++) {
        float a = f[2 * j], b = f[2 * j + 1];
        __nv_bfloat16 ha = __float2bfloat16(a), hb = __float2bfloat16(b);
        float fa = __bfloat162float(ha), fb = __bfloat162float(hb);
        __nv_bfloat162 hp; hp.x = ha; hp.y = hb;
        H[j] = *(u32*)&hp;
        __nv_bfloat162 lp = __floats2bfloat162_rn(a - fa, b - fb);
        L[j] = *(u32*)&lp;
    }
    u32 off = (u32)r * 256 + (u32)((slot ^ (r & 7)) << 4);
    *(uint4*)(hi + off) = make_uint4(H[0], H[1], H[2], H[3]);
    *(uint4*)(lo + off) = make_uint4(L[0], L[1], L[2], L[3]);
}

// GEMM over K=64 where BOTH operands are stored [k:64 rows][mn:128 cols], trans-ldsm.
__device__ __forceinline__ void warp_gemm_tt(u32 ah, u32 al, u32 bh, u32 bl,
                                             int lane, int m0, int n0,
                                             float acc[2][4][4])
{
    int rkA = (lane & 7) + ((lane >> 4) << 3);
    int slA = (lane >> 3) & 1;
    int rkB = (lane & 7) + (((lane >> 3) & 1) << 3);
    int slB = lane >> 4;
#pragma unroll
    for (int ks = 0; ks < 4; ks++) {
        u32 AH[2][4], AL[2][4], BH[2][4], BL[2][4];
#pragma unroll
        for (int mf = 0; mf < 2; mf++) {
            int row = ks * 16 + rkA;
            int slot = (m0 >> 3) + 2 * mf + slA;
            u32 ad = (u32)row * 256 + (u32)((slot ^ (row & 7)) << 4);
            ldsm4t(ah + ad, AH[mf]);
            ldsm4t(al + ad, AL[mf]);
        }
#pragma unroll
        for (int nb = 0; nb < 2; nb++) {
            int row = ks * 16 + rkB;
            int slot = (n0 >> 3) + 2 * nb + slB;
            u32 ad = (u32)row * 256 + (u32)((slot ^ (row & 7)) << 4);
            ldsm4t(bh + ad, BH[nb]);
            ldsm4t(bl + ad, BL[nb]);
        }
#pragma unroll
        for (int mf = 0; mf < 2; mf++)
#pragma unroll
            for (int nh = 0; nh < 2; nh++)
#pragma unroll
                for (int no = 0; no < 2; no++) {
                    float* d = acc[mf][nh * 2 + no];
                    mmabf(d, AH[mf], BH[nh][2 * no], BH[nh][2 * no + 1]);
                    mmabf(d, AH[mf], BL[nh][2 * no], BL[nh][2 * no + 1]);
                    mmabf(d, AL[mf], BH[nh][2 * no], BH[nh][2 * no + 1]);
                }
    }
}

// GEMM over K=64: A non-trans [m:128][k:64], B trans [k:64][n:128].
__device__ __forceinline__ void warp_gemm_nt(u32 ah, u32 al, u32 bh, u32 bl,
                                             int lane, int m0, int n0,
                                             float acc[2][4][4])
{
    int rA = lane & 15, hi16 = lane >> 4;
    int rowA[2] = {m0 + rA, m0 + 16 + rA};
    int rkB = (lane & 7) + (((lane >> 3) & 1) << 3);
    int slB = lane >> 4;
#pragma unroll
    for (int ks = 0; ks < 4; ks++) {
        u32 AH[2][4], AL[2][4], BH[2][4], BL[2][4];
#pragma unroll
        for (int f = 0; f < 2; f++) {
            u32 sa = (u32)rowA[f] * 128 + (u32)((((ks << 1) + hi16) ^ (rowA[f] & 7)) << 4);
            ldsm4(ah + sa, AH[f]);
            ldsm4(al + sa, AL[f]);
        }
#pragma unroll
        for (int nb = 0; nb < 2; nb++) {
            int row = ks * 16 + rkB;
            int slot = (n0 >> 3) + 2 * nb + slB;
            u32 ad = (u32)row * 256 + (u32)((slot ^ (row & 7)) << 4);
            ldsm4t(bh + ad, BH[nb]);
            ldsm4t(bl + ad, BL[nb]);
        }
#pragma unroll
        for (int mf = 0; mf < 2; mf++)
#pragma unroll
            for (int nh = 0; nh < 2; nh++)
#pragma unroll
                for (int no = 0; no < 2; no++) {
                    float* d = acc[mf][nh * 2 + no];
                    mmabf(d, AH[mf], BH[nh][2 * no], BH[nh][2 * no + 1]);
                    mmabf(d, AH[mf], BL[nh][2 * no], BL[nh][2 * no + 1]);
                    mmabf(d, AL[mf], BH[nh][2 * no], BH[nh][2 * no + 1]);
                }
    }
}

// ---------------- K0: per-batch q split + s1 ----------------
__global__ __launch_bounds__(512) void k0_prep(
    const float* __restrict__ q_g, const float* __restrict__ wq)
{
    __shared__ float red[32 * 128];
    int tid = threadIdx.x, b = blockIdx.x;
    int sx = tid & 15;
    float s1p[8] = {0, 0, 0, 0, 0, 0, 0, 0};
    char* dhB = g_qhi + b * 32768;
    char* dlB = g_qlo + b * 32768;
#pragma unroll
    for (int it = 0; it < 4; it++) {
        int i = tid + it * 512;
        int h = i >> 4;
        const float* pq = &q_g[((size_t)b * Hn + h) * Qn + sx * 8];
        float4 v0 = *(const float4*)pq, v1 = *(const float4*)(pq + 4);
        float f[8] = {v0.x, v0.y, v0.z, v0.w, v1.x, v1.y, v1.z, v1.w};
        float wqv = __ldg(&wq[h]);
#pragma unroll
        for (int j = 0; j < 8; j++) s1p[j] += f[j] * wqv;
        split8(dhB + (h >> 6) * 16384, dlB + (h >> 6) * 16384, h & 63, sx, f);
    }
    int k = tid >> 4;
#pragma unroll
    for (int j = 0; j < 8; j++) red[k * 128 + sx * 8 + j] = s1p[j];
    __syncthreads();
    if (tid < 128) {
        float s = 0.f;
#pragma unroll
        for (int w = 0; w < 32; w++) s += red[w * 128 + tid];
        g_s1[b * Qn + tid] = s;
    }
}

// ---------------- K1 ----------------
#define K1_SMEM 83968

__global__ __launch_bounds__(512, 2) void k1_score(
    const float* __restrict__ c_g,
    const float* __restrict__ cmask, const float* __restrict__ qmask,
    const float* __restrict__ wc, const float* __restrict__ wcq,
    const float* __restrict__ bias)
{
    extern __shared__ __align__(256) char smem[];
    u32 sb = smem_u32(smem);
    float* s0s  = (float*)(smem + 65536);
    float* s1s  = (float*)(smem + 66048);
    float* qms  = (float*)(smem + 66560);
    float* cms  = (float*)(smem + 67072);
    float* red1 = (float*)(smem + 67584);
    float* red2 = (float*)(smem + 75776);
    int tid = threadIdx.x, lane = tid & 31, wid = tid >> 5;
    int b = blockIdx.y, ct = blockIdx.x, c0 = ct * 128;
    float biasv = bias[0];

    for (int i = tid; i < 2048; i += 512) red1[i] = 0.f;
    if (tid < 128) qms[tid] = qmask[b * Qn + tid];
    else if (tid < 256) cms[tid - 128] = cmask[b * Cn + c0 + tid - 128];
    else if (tid < 384) s1s[tid - 256] = g_s1[b * Qn + tid - 256];

    float acc[2][4][4];
#pragma unroll
    for (int i = 0; i < 2; i++)
#pragma unroll
        for (int j = 0; j < 4; j++)
#pragma unroll
            for (int k = 0; k < 4; k++) acc[i][j][k] = 0.f;

    int m0 = (wid >> 2) * 32, n0 = (wid & 3) * 32;
    int sx0 = tid & 15;

#pragma unroll
    for (int kc = 0; kc < 2; kc++) {
        __syncthreads();
        const uint4* srcH = (const uint4*)(g_qhi + b * 32768 + kc * 16384);
        const uint4* srcL = (const uint4*)(g_qlo + b * 32768 + kc * 16384);
#pragma unroll
        for (int it = 0; it < 2; it++) {
            int i = tid + it * 512;
            ((uint4*)(smem + 32768))[i] = srcH[i];
            ((uint4*)(smem + 49152))[i] = srcL[i];
        }
        float s0p[8] = {0, 0, 0, 0, 0, 0, 0, 0};
#pragma unroll
        for (int it = 0; it < 2; it++) {
            int i = tid + it * 512;
            int hl = i >> 4, sx = i & 15;
            int h = kc * 64 + hl;
            const float* pc = &c_g[((size_t)b * Hn + h) * Cn + c0 + sx * 8];
            float4 v0 = *(const float4*)pc, v1 = *(const float4*)(pc + 4);
            float f[8] = {v0.x, v0.y, v0.z, v0.w, v1.x, v1.y, v1.z, v1.w};
            float wcv = __ldg(&wc[h]), wcqv = __ldg(&wcq[h]);
#pragma unroll
            for (int j = 0; j < 8; j++) { s0p[j] += f[j] * wcv; f[j] *= wcqv; }
            split8(smem, smem + 16384, hl, sx, f);
        }
#pragma unroll
        for (int j = 0; j < 8; j++)
            s0p[j] += __shfl_xor_sync(~0u, s0p[j], 16);
        if (lane < 16) {
#pragma unroll
            for (int j = 0; j < 8; j++)
                red1[wid * 128 + sx0 * 8 + j] += s0p[j];
        }
        __syncthreads();
        warp_gemm_tt(sb, sb + 16384, sb + 32768, sb + 49152, lane, m0, n0, acc);
    }
    __syncthreads();
    if (tid < 128) {
        float a = 0.f;
#pragma unroll
        for (int w = 0; w < 16; w++) a += red1[w * 128 + tid];
        s0s[tid] = a + biasv;
    }
    __syncthreads();

    int lr = lane >> 2, lc2 = (lane & 3) * 2;

#pragma unroll
    for (int mf = 0; mf < 2; mf++) {
        int r0 = m0 + mf * 16 + lr, r1 = r0 + 8;
        float s0a = s0s[r0], s0b = s0s[r1];
#pragma unroll
        for (int nf = 0; nf < 4; nf++) {
            int col = n0 + nf * 8 + lc2;
            float s1a = s1s[col], s1b = s1s[col + 1];
            acc[mf][nf][0] += s0a + s1a;
            acc[mf][nf][1] += s0a + s1b;
            acc[mf][nf][2] += s0b + s1a;
            acc[mf][nf][3] += s0b + s1b;
        }
    }

#pragma unroll
    for (int mf = 0; mf < 2; mf++) {
        int r0 = m0 + mf * 16 + lr, r1 = r0 + 8;
#pragma unroll
        for (int nf = 0; nf < 4; nf++) {
            int col = n0 + nf * 8 + lc2;
            *(float2*)&g_S[((size_t)b * Cn + c0 + r0) * Qn + col] =
                make_float2(acc[mf][nf][0], acc[mf][nf][1]);
            *(float2*)&g_S[((size_t)b * Cn + c0 + r1) * Qn + col] =
                make_float2(acc[mf][nf][2], acc[mf][nf][3]);
        }
    }

    bool qm0[4], qm1[4];
#pragma unroll
    for (int nf = 0; nf < 4; nf++) {
        qm0[nf] = qms[n0 + nf * 8 + lc2] > 0.f;
        qm1[nf] = qms[n0 + nf * 8 + lc2 + 1] > 0.f;
    }
    bool cmv[2][2];
#pragma unroll
    for (int mf = 0; mf < 2; mf++) {
        cmv[mf][0] = cms[m0 + mf * 16 + lr] > 0.f;
        cmv[mf][1] = cms[m0 + mf * 16 + 8 + lr] > 0.f;
    }

    float rmx[2][2];
#pragma unroll
    for (int mf = 0; mf < 2; mf++) { rmx[mf][0] = -1e30f; rmx[mf][1] = -1e30f; }
#pragma unroll
    for (int mf = 0; mf < 2; mf++)
#pragma unroll
        for (int nf = 0; nf < 4; nf++) {
            if (qm0[nf]) {
                rmx[mf][0] = fmaxf(rmx[mf][0], acc[mf][nf][0]);
                rmx[mf][1] = fmaxf(rmx[mf][1], acc[mf][nf][2]);
            }
            if (qm1[nf]) {
                rmx[mf][0] = fmaxf(rmx[mf][0], acc[mf][nf][1]);
                rmx[mf][1] = fmaxf(rmx[mf][1], acc[mf][nf][3]);
            }
        }
#pragma unroll
    for (int mf = 0; mf < 2; mf++)
#pragma unroll
        for (int h = 0; h < 2; h++) {
            rmx[mf][h] = fmaxf(rmx[mf][h], __shfl_xor_sync(~0u, rmx[mf][h], 1));
            rmx[mf][h] = fmaxf(rmx[mf][h], __shfl_xor_sync(~0u, rmx[mf][h], 2));
        }
    if ((lane & 3) == 0)
#pragma unroll
        for (int mf = 0; mf < 2; mf++)
#pragma unroll
            for (int h = 0; h < 2; h++)
                red1[(wid & 3) * 128 + m0 + mf * 16 + h * 8 + lr] = rmx[mf][h];
    __syncthreads();

    float rowMv[2][2];
#pragma unroll
    for (int mf = 0; mf < 2; mf++)
#pragma unroll
        for (int h = 0; h < 2; h++) {
            int r = m0 + mf * 16 + h * 8 + lr;
            float m = red1[r];
#pragma unroll
            for (int g = 1; g < 4; g++) m = fmaxf(m, red1[g * 128 + r]);
            rowMv[mf][h] = m;
        }
    float rzz[2][2] = {{0.f, 0.f}, {0.f, 0.f}};
#pragma unroll
    for (int mf = 0; mf < 2; mf++)
#pragma unroll
        for (int nf = 0; nf < 4; nf++) {
            if (qm0[nf]) {
                rzz[mf][0] += __expf(acc[mf][nf][0] - rowMv[mf][0]);
                rzz[mf][1] += __expf(acc[mf][nf][2] - rowMv[mf][1]);
            }
            if (qm1[nf]) {
                rzz[mf][0] += __expf(acc[mf][nf][1] - rowMv[mf][0]);
                rzz[mf][1] += __expf(acc[mf][nf][3] - rowMv[mf][1]);
            }
        }
#pragma unroll
    for (int mf = 0; mf < 2; mf++)
#pragma unroll
        for (int h = 0; h < 2; h++) {
            rzz[mf][h] += __shfl_xor_sync(~0u, rzz[mf][h], 1);
            rzz[mf][h] += __shfl_xor_sync(~0u, rzz[mf][h], 2);
        }
    if ((lane & 3) == 0)
#pragma unroll
        for (int mf = 0; mf < 2; mf++)
#pragma unroll
            for (int h = 0; h < 2; h++)
                red2[(wid & 3) * 128 + m0 + mf * 16 + h * 8 + lr] = rzz[mf][h];
    __syncthreads();

    if ((wid & 3) == 0 && (lane & 3) == 0) {
#pragma unroll
        for (int mf = 0; mf < 2; mf++)
#pragma unroll
            for (int h = 0; h < 2; h++) {
                int r = m0 + mf * 16 + h * 8 + lr;
                float z = red2[r] + red2[128 + r] + red2[256 + r] + red2[384 + r];
                g_rowM[b * Cn + c0 + r] = rowMv[mf][h];
                g_rowZ[b * Cn + c0 + r] = z;
            }
    }
    __syncthreads();

    float cmx[4][2];
#pragma unroll
    for (int nf = 0; nf < 4; nf++) { cmx[nf][0] = -1e30f; cmx[nf][1] = -1e30f; }
#pragma unroll
    for (int mf = 0; mf < 2; mf++)
#pragma unroll
        for (int nf = 0; nf < 4; nf++) {
            if (cmv[mf][0]) {
                cmx[nf][0] = fmaxf(cmx[nf][0], acc[mf][nf][0]);
                cmx[nf][1] = fmaxf(cmx[nf][1], acc[mf][nf][1]);
            }
            if (cmv[mf][1]) {
                cmx[nf][0] = fmaxf(cmx[nf][0], acc[mf][nf][2]);
                cmx[nf][1] = fmaxf(cmx[nf][1], acc[mf][nf][3]);
            }
        }
#pragma unroll
    for (int nf = 0; nf < 4; nf++)
#pragma unroll
        for (int v = 0; v < 2; v++) {
            cmx[nf][v] = fmaxf(cmx[nf][v], __shfl_xor_sync(~0u, cmx[nf][v], 4));
            cmx[nf][v] = fmaxf(cmx[nf][v], __shfl_xor_sync(~0u, cmx[nf][v], 8));
            cmx[nf][v] = fmaxf(cmx[nf][v], __shfl_xor_sync(~0u, cmx[nf][v], 16));
        }
    if (lr == 0)
#pragma unroll
        for (int nf = 0; nf < 4; nf++) {
            red1[(wid >> 2) * 128 + n0 + nf * 8 + lc2]     = cmx[nf][0];
            red1[(wid >> 2) * 128 + n0 + nf * 8 + lc2 + 1] = cmx[nf][1];
        }
    __syncthreads();

    float pMv[4][2];
#pragma unroll
    for (int nf = 0; nf < 4; nf++)
#pragma unroll
        for (int v = 0; v < 2; v++) {
            int col = n0 + nf * 8 + lc2 + v;
            float m = red1[col];
#pragma unroll
            for (int g = 1; g < 4; g++) m = fmaxf(m, red1[g * 128 + col]);
            pMv[nf][v] = m;
        }
    float czz[4][2] = {{0,0},{0,0},{0,0},{0,0}};
#pragma unroll
    for (int nf = 0; nf < 4; nf++) {
        if (cmv[0][0]) { czz[nf][0] += __expf(acc[0][nf][0] - pMv[nf][0]); czz[nf][1] += __expf(acc[0][nf][1] - pMv[nf][1]); }
        if (cmv[0][1]) { czz[nf][0] += __expf(acc[0][nf][2] - pMv[nf][0]); czz[nf][1] += __expf(acc[0][nf][3] - pMv[nf][1]); }
        if (cmv[1][0]) { czz[nf][0] += __expf(acc[1][nf][0] - pMv[nf][0]); czz[nf][1] += __expf(acc[1][nf][1] - pMv[nf][1]); }
        if (cmv[1][1]) { czz[nf][0] += __expf(acc[1][nf][2] - pMv[nf][0]); czz[nf][1] += __expf(acc[1][nf][3] - pMv[nf][1]); }
    }
#pragma unroll
    for (int nf = 0; nf < 4; nf++)
#pragma unroll
        for (int v = 0; v < 2; v++) {
            czz[nf][v] += __shfl_xor_sync(~0u, czz[nf][v], 4);
            czz[nf][v] += __shfl_xor_sync(~0u, czz[nf][v], 8);
            czz[nf][v] += __shfl_xor_sync(~0u, czz[nf][v], 16);
        }
    if (lr == 0)
#pragma unroll
        for (int nf = 0; nf < 4; nf++) {
            red2[(wid >> 2) * 128 + n0 + nf * 8 + lc2]     = czz[nf][0];
            red2[(wid >> 2) * 128 + n0 + nf * 8 + lc2 + 1] = czz[nf][1];
        }
    __syncthreads();

    if ((wid >> 2) == 0 && lr == 0) {
#pragma unroll
        for (int nf = 0; nf < 4; nf++)
#pragma unroll
            for (int v = 0; v < 2; v++) {
                int col = n0 + nf * 8 + lc2 + v;
                float z = red2[col] + red2[128 + col] + red2[256 + col] + red2[384 + col];
                g_pM[(b * NT + ct) * Qn + col] = pMv[nf][v];
                g_pZ[(b * NT + ct) * Qn + col] = z;
            }
    }
}

// ---------------- K3: qb^T partials (+ plane-0 output copy) ----------------
#define K3_SMEM 66048

__global__ __launch_bounds__(512, 2) void k3_qb(
    const float* __restrict__ c_g, const float* __restrict__ cmask,
    float* __restrict__ out)
{
    extern __shared__ __align__(256) char smem[];
    u32 sb = smem_u32(smem);
    float* colMs = (float*)(smem + 65536);
    int tid = threadIdx.x, lane = tid & 31, wid = tid >> 5;
    int b = blockIdx.y, quarter = blockIdx.x;
    const size_t HC = (size_t)Hn * Cn;
    float* out0 = out + (size_t)b * 4 * HC;   // plane 0

    if (tid < 128) {
        float m = -3.4e38f;
#pragma unroll
        for (int t = 0; t < NT; t++) m = fmaxf(m, g_pM[(b * NT + t) * Qn + tid]);
        colMs[tid] = m;
    }

    float acc[2][4][4];
#pragma unroll
    for (int i = 0; i < 2; i++)
#pragma unroll
        for (int j = 0; j < 4; j++)
#pragma unroll
            for (int k = 0; k < 4; k++) acc[i][j][k] = 0.f;

    int m0 = (wid >> 2) * 32, n0 = (wid & 3) * 32;

    for (int it = 0; it < 4; it++) {
        int c0 = quarter * 256 + it * 64;
        __syncthreads();
        for (int i = tid; i < 1024; i += 512) {
            int r = i >> 3, sx = i & 7;
            const float* pa = &c_g[((size_t)b * Hn + r) * Cn + c0 + sx * 8];
            float4 v0 = *(const float4*)pa, v1 = *(const float4*)(pa + 4);
            float f[8] = {v0.x, v0.y, v0.z, v0.w, v1.x, v1.y, v1.z, v1.w};
            split8_64(smem, smem + 16384, r, sx, f);
            // plane 0: out[h][cc] = c[h][cc] (free reuse of the load)
            *(float4*)&out0[(size_t)r * Cn + c0 + sx * 8]     = v0;
            *(float4*)&out0[(size_t)r * Cn + c0 + sx * 8 + 4] = v1;
        }
        for (int i = tid; i < 1024; i += 512) {
            int cl = i >> 4, sx = i & 15;
            const float* ps = &g_S[((size_t)b * Cn + c0 + cl) * Qn + sx * 8];
            float4 s0 = *(const float4*)ps, s1 = *(const float4*)(ps + 4);
            float f[8] = {s0.x, s0.y, s0.z, s0.w, s1.x, s1.y, s1.z, s1.w};
            bool cmv = __ldg(&cmask[b * Cn + c0 + cl]) > 0.f;
#pragma unroll
            for (int j = 0; j < 8; j++)
                f[j] = cmv ? __expf(f[j] - colMs[sx * 8 + j]) : 0.f;
            split8(smem + 32768, smem + 49152, cl, sx, f);
        }
        __syncthreads();
        warp_gemm_nt(sb, sb + 16384, sb + 32768, sb + 49152, lane, m0, n0, acc);
    }

    int lr = lane >> 2, lc2 = (lane & 3) * 2;
#pragma unroll
    for (int mf = 0; mf < 2; mf++) {
        int h0 = m0 + mf * 16 + lr, h1 = h0 + 8;
#pragma unroll
        for (int nf = 0; nf < 4; nf++) {
            int col = n0 + nf * 8 + lc2;
            *(float2*)&g_qbp4[((size_t)(b * 4 + quarter) * Hn + h0) * Qn + col] =
                make_float2(acc[mf][nf][0], acc[mf][nf][1]);
            *(float2*)&g_qbp4[((size_t)(b * 4 + quarter) * Hn + h1) * Qn + col] =
                make_float2(acc[mf][nf][2], acc[mf][nf][3]);
        }
    }
}

// ---------------- K3b: combine partials (4-way parallel over h) ------------
__global__ __launch_bounds__(512) void k3b_comb() {
    __shared__ float rcz[128];
    int tid = threadIdx.x, b = blockIdx.y, quarter = blockIdx.x;
    if (tid < 128) {
        float m = -3.4e38f;
#pragma unroll
        for (int t = 0; t < NT; t++) m = fmaxf(m, g_pM[(b * NT + t) * Qn + tid]);
        float z = 0.f;
#pragma unroll
        for (int t = 0; t < NT; t++)
            z += g_pZ[(b * NT + t) * Qn + tid] * __expf(g_pM[(b * NT + t) * Qn + tid] - m);
        rcz[tid] = (z > 0.f) ? 1.f / z : 0.f;
    }
    __syncthreads();
    char* dhB = g_phi + b * 32768;
    char* dlB = g_plo + b * 32768;
    const size_t PS = (size_t)Hn * Qn;
    int sx = tid & 15;
    int h = quarter * 32 + (tid >> 4);
    const float* p0 = &g_qbp4[((size_t)(b * 4) * Hn + h) * Qn + sx * 8];
    float fp[8] = {0, 0, 0, 0, 0, 0, 0, 0};
#pragma unroll
    for (int t = 0; t < 4; t++) {
        float4 a0 = *(const float4*)(p0 + t * PS);
        float4 a1 = *(const float4*)(p0 + t * PS + 4);
        fp[0] += a0.x; fp[1] += a0.y; fp[2] += a0.z; fp[3] += a0.w;
        fp[4] += a1.x; fp[5] += a1.y; fp[6] += a1.z; fp[7] += a1.w;
    }
#pragma unroll
    for (int j = 0; j < 8; j++) fp[j] *= rcz[sx * 8 + j];
    split8(dhB + (h >> 6) * 16384, dlB + (h >> 6) * 16384, h & 63, sx, fp);
}

// ---------------- K4: dual GEMM; fragment-direct output, no staging ---------
#define K4_SMEM 198656

__global__ __launch_bounds__(512) void k4_out(
    const float* __restrict__ c_g,
    const float* __restrict__ qmask, float* __restrict__ out)
{
    extern __shared__ __align__(256) char smem[];
    u32 sb = smem_u32(smem);
    float* rms = (float*)(smem + 196608);
    float* qms = (float*)(smem + 197120);
    float* rzs = (float*)(smem + 197632);
    int tid = threadIdx.x, lane = tid & 31, wid = tid >> 5;
    int b = blockIdx.y, ct = blockIdx.x, c0 = ct * 128;
    const size_t HC = (size_t)Hn * Cn;
    float* outB = out + (size_t)b * 4 * HC;

    if (tid < 128) rms[tid] = g_rowM[b * Cn + c0 + tid];
    else if (tid < 256) qms[tid - 128] = qmask[b * Qn + tid - 128];
    else if (tid < 384) {
        float z = g_rowZ[b * Cn + c0 + tid - 256];
        rzs[tid - 256] = (z > 0.f) ? 1.f / z : 0.f;
    }

    // Q + P fills: straight copies of precomputed bf16 tiles
    {
        const uint4* qH = (const uint4*)(g_qhi + b * 32768);
        const uint4* qL = (const uint4*)(g_qlo + b * 32768);
        const uint4* pH = (const uint4*)(g_phi + b * 32768);
        const uint4* pL = (const uint4*)(g_plo + b * 32768);
#pragma unroll
        for (int it = 0; it < 4; it++) {
            int i = tid + it * 512;
            ((uint4*)(smem + 65536))[i]  = qH[i];
            ((uint4*)(smem + 98304))[i]  = qL[i];
            ((uint4*)(smem + 131072))[i] = pH[i];
            ((uint4*)(smem + 163840))[i] = pL[i];
        }
    }
    __syncthreads();   // rms/qms/rzs visible before E fill

    // E fill
    for (int i = tid; i < 2048; i += 512) {
        int r = i >> 4, sx = i & 15;
        const float* ps = &g_S[((size_t)b * Cn + c0 + r) * Qn + sx * 8];
        float4 s0 = *(const float4*)ps, s1 = *(const float4*)(ps + 4);
        float fe[8] = {s0.x, s0.y, s0.z, s0.w, s1.x, s1.y, s1.z, s1.w};
        float rm = rms[r];
#pragma unroll
        for (int j = 0; j < 8; j++)
            fe[j] = (qms[sx * 8 + j] > 0.f) ? __expf(fe[j] - rm) : 0.f;
        split8(smem, smem + 32768, r, sx, fe);
    }
    __syncthreads();

    int m0 = (wid >> 2) * 32, n0 = (wid & 3) * 32;
    int lr = lane >> 2, lc = (lane & 3) * 2;

    float accA[2][4][4], accB[2][4][4];
#pragma unroll
    for (int i = 0; i < 2; i++)
#pragma unroll
        for (int j = 0; j < 4; j++)
#pragma unroll
            for (int k = 0; k < 4; k++) { accA[i][j][k] = 0.f; accB[i][j][k] = 0.f; }

    {
        u32 eh = sb, el = sb + 32768, qh = sb + 65536, ql = sb + 98304;
        u32 ph = sb + 131072, pl = sb + 163840;
        int rA = lane & 15, hi16 = lane >> 4;
        int rBl = (lane & 7) + ((lane >> 4) << 3);
        int kh = (lane >> 3) & 1;
        int rowA[2] = {m0 + rA, m0 + 16 + rA};
        int rowB[2] = {n0 + rBl, n0 + 16 + rBl};
#pragma unroll
        for (int ks = 0; ks < 8; ks++) {
            u32 AH[2][4], AL[2][4];
#pragma unroll
            for (int f = 0; f < 2; f++) {
                u32 sa = (u32)rowA[f] * 256 + (u32)((((ks << 1) + hi16) ^ (rowA[f] & 7)) << 4);
                ldsm4(eh + sa, AH[f]);
                ldsm4(el + sa, AL[f]);
            }
#pragma unroll
            for (int nh = 0; nh < 2; nh++) {
                u32 QH[4], QL[4], PH[4], PL[4];
                u32 sbo = (u32)rowB[nh] * 256 + (u32)((((ks << 1) + kh) ^ (rowB[nh] & 7)) << 4);
                ldsm4(qh + sbo, QH);
                ldsm4(ql + sbo, QL);
                ldsm4(ph + sbo, PH);
                ldsm4(pl + sbo, PL);
#pragma unroll
                for (int mf = 0; mf < 2; mf++)
#pragma unroll
                    for (int no = 0; no < 2; no++) {
                        float* dA = accA[mf][nh * 2 + no];
                        mmabf(dA, AH[mf], QH[2 * no], QH[2 * no + 1]);
                        mmabf(dA, AH[mf], QL[2 * no], QL[2 * no + 1]);
                        mmabf(dA, AL[mf], QH[2 * no], QH[2 * no + 1]);
                        float* dB = accB[mf][nh * 2 + no];
                        mmabf(dB, AH[mf], PH[2 * no], PH[2 * no + 1]);
                        mmabf(dB, AH[mf], PL[2 * no], PL[2 * no + 1]);
                        mmabf(dB, AL[mf], PH[2 * no], PH[2 * no + 1]);
                    }
            }
        }
    }

    // fragment-direct epilogue: planes 1 (a), 2 (c*a), 3 (c*b)
#pragma unroll
    for (int mf = 0; mf < 2; mf++) {
        int cl0 = m0 + mf * 16 + lr, cl1 = cl0 + 8;
        float rz0 = rzs[cl0], rz1 = rzs[cl1];
#pragma unroll
        for (int nf = 0; nf < 4; nf++) {
            int h = n0 + nf * 8 + lc, h2 = h + 1;
            float a00 = accA[mf][nf][0] * rz0, a01 = accA[mf][nf][1] * rz0;
            float a10 = accA[mf][nf][2] * rz1, a11 = accA[mf][nf][3] * rz1;
            float b00 = accB[mf][nf][0] * rz0, b01 = accB[mf][nf][1] * rz0;
            float b10 = accB[mf][nf][2] * rz1, b11 = accB[mf][nf][3] * rz1;
            float cv00 = __ldg(&c_g[((size_t)b * Hn + h)  * Cn + c0 + cl0]);
            float cv10 = __ldg(&c_g[((size_t)b * Hn + h)  * Cn + c0 + cl1]);
            float cv01 = __ldg(&c_g[((size_t)b * Hn + h2) * Cn + c0 + cl0]);
            float cv11 = __ldg(&c_g[((size_t)b * Hn + h2) * Cn + c0 + cl1]);
            size_t o00 = (size_t)h  * Cn + c0 + cl0;
            size_t o10 = (size_t)h  * Cn + c0 + cl1;
            size_t o01 = (size_t)h2 * Cn + c0 + cl0;
            size_t o11 = (size_t)h2 * Cn + c0 + cl1;
            outB[HC + o00] = a00;  outB[HC + o10] = a10;
            outB[HC + o01] = a01;  outB[HC + o11] = a11;
            outB[2 * HC + o00] = cv00 * a00;  outB[2 * HC + o10] = cv10 * a10;
            outB[2 * HC + o01] = cv01 * a01;  outB[2 * HC + o11] = cv11 * a11;
            outB[3 * HC + o00] = cv00 * b00;  outB[3 * HC + o10] = cv10 * b10;
            outB[3 * HC + o01] = cv01 * b01;  outB[3 * HC + o11] = cv11 * b11;
        }
    }
}

// ---------------- launch ----------------
extern "C" void kernel_launch(void* const* d_in, const int* in_sizes, int n_in,
                              void* d_out, int out_size)
{
    const float* c     = (const float*)d_in[0];
    const float* q     = (const float*)d_in[1];
    const float* cmask = (const float*)d_in[2];
    const float* qmask = (const float*)d_in[3];
    const float* wc    = (const float*)d_in[4];
    const float* wq    = (const float*)d_in[5];
    const float* wcq   = (const float*)d_in[6];
    const float* bias  = (const float*)d_in[7];
    float* out = (float*)d_out;

    cudaFuncSetAttribute(k1_score, cudaFuncAttributeMaxDynamicSharedMemorySize, K1_SMEM);
    cudaFuncSetAttribute(k3_qb,    cudaFuncAttributeMaxDynamicSharedMemorySize, K3_SMEM);
    cudaFuncSetAttribute(k4_out,   cudaFuncAttributeMaxDynamicSharedMemorySize, K4_SMEM);

    k0_prep<<<Bn, 512>>>(q, wq);
    k1_score<<<dim3(NT, Bn), 512, K1_SMEM>>>(c, cmask, qmask, wc, wcq, bias);
    k3_qb<<<dim3(4, Bn), 512, K3_SMEM>>>(c, cmask, out);
    k3b_comb<<<dim3(4, Bn), 512>>>();
    k4_out<<<dim3(NT, Bn), 512, K4_SMEM>>>(c, qmask, out);
}